// round 8
// baseline (speedup 1.0000x reference)
#include <cuda_runtime.h>
#include <math.h>
#include <stdint.h>

#define BB   4
#define SS   2048
#define DD   1024
#define HH   16
#define DHH  64
#define MTOT (BB*SS)          // 8192
#define MASKVAL (-1e30f)

// ---------------- scratch (static device arrays; no allocation) -------------
__device__ float g_q  [(size_t)MTOT*DD];
__device__ float g_k  [(size_t)MTOT*DD];
__device__ float g_v  [(size_t)MTOT*DD];
__device__ float g_ctx[(size_t)MTOT*DD];
__device__ float4 g_kf[(size_t)64*256*8*32];    // [bh][ntg 256][ks 8][lane] (hi0,hi1,lo0,lo1)
__device__ float2 g_vf[(size_t)64*32*8*8*32];   // [bh][kt][kks][nvt][lane]  (v0,v1) tf32
__device__ float2 g_wf[(size_t)4*128*128*32];   // [z][kg][ntg][lane] (w0,w1) tf32
__device__ uint32_t g_maskb[(size_t)SS*(SS/32)];
__device__ int   g_mask_kind;

__device__ __forceinline__ float to_tf32(float x) {
    float r;
    asm("cvt.rna.tf32.f32 %0, %1;" : "=f"(r) : "f"(x));
    return r;
}

// m16n8k8 tf32 warp MMA (Ampere-class; compiles at baseline sm_103 target)
__device__ __forceinline__ void mma_tf32(float4& d, const uint32_t a[4],
                                         const uint32_t b[2]) {
    asm volatile(
        "mma.sync.aligned.m16n8k8.row.col.f32.tf32.tf32.f32 "
        "{%0,%1,%2,%3}, {%4,%5,%6,%7}, {%8,%9}, {%0,%1,%2,%3};"
        : "+f"(d.x), "+f"(d.y), "+f"(d.z), "+f"(d.w)
        : "r"(a[0]), "r"(a[1]), "r"(a[2]), "r"(a[3]), "r"(b[0]), "r"(b[1]));
}

// ---------------- mask dtype detection + bitmask repack ----------------------
__global__ void detect_mask_kind(const unsigned int* __restrict__ m) {
    int lane = threadIdx.x;
    bool word_like = true;
    for (int i = lane; i < 256; i += 32) {
        unsigned int w = m[i];
        word_like = word_like && (w <= 1u || w == 0x3F800000u);
    }
    word_like = __all_sync(0xffffffffu, word_like);
    if (lane == 0) g_mask_kind = word_like ? 1 : 0;
}

__global__ void repack_mask(const void* __restrict__ mp) {
    int idx = blockIdx.x * blockDim.x + threadIdx.x;
    if (idx >= SS * (SS/32)) return;
    int row = idx >> 6, w = idx & 63;
    uint32_t bits = 0;
    if (g_mask_kind == 0) {
        const uchar4* p = (const uchar4*)mp + (size_t)row*(SS/4) + w*8;
#pragma unroll
        for (int j = 0; j < 8; ++j) {
            uchar4 c = p[j];
            bits |= (uint32_t)(c.x != 0) << (4*j + 0);
            bits |= (uint32_t)(c.y != 0) << (4*j + 1);
            bits |= (uint32_t)(c.z != 0) << (4*j + 2);
            bits |= (uint32_t)(c.w != 0) << (4*j + 3);
        }
    } else {
        const unsigned int* p = (const unsigned int*)mp + (size_t)row*SS + w*32;
#pragma unroll
        for (int j = 0; j < 32; ++j)
            bits |= (uint32_t)(p[j] != 0) << j;
    }
    g_maskb[idx] = bits;
}

// ---------------- weight fragment builder ------------------------------------
// b-frag for thread (g,tg): (W[k][n], W[k+4][n]), n = ntg*8+g, k = kg*8+tg.
__global__ void build_wf(const float* __restrict__ W0, const float* __restrict__ W1,
                         const float* __restrict__ W2, const float* __restrict__ W3) {
    int z = blockIdx.z;
    const float* W = (z == 0) ? W0 : (z == 1) ? W1 : (z == 2) ? W2 : W3;
    int lane = threadIdx.x, ntl = threadIdx.y;       // (32, 8)
    int g = lane >> 2, tg = lane & 3;
    int ntg = blockIdx.x * 8 + ntl;
    int kg  = blockIdx.y;
    int n = ntg*8 + g, k = kg*8 + tg;
    float w0 = W[(size_t)k*DD + n];
    float w1 = W[(size_t)(k+4)*DD + n];
    g_wf[(((size_t)z*128 + kg)*128 + ntg)*32 + lane] =
        make_float2(to_tf32(w0), to_tf32(w1));
}

// ---------------- K fragment builder (hi/lo packed) --------------------------
__global__ void build_kf() {
    int lane = threadIdx.x, ks = threadIdx.y;        // (32, 8)
    int g = lane >> 2, tg = lane & 3;
    int ntg = blockIdx.x;                            // 0..255
    int bh  = blockIdx.y;
    int b = bh >> 4, h = bh & 15;
    const float* kp = g_k + (size_t)(b*SS + ntg*8 + g)*DD + h*DHH + ks*8 + tg;
    float k0 = kp[0], k1 = kp[4];
    float h0 = to_tf32(k0), h1 = to_tf32(k1);
    float l0 = to_tf32(k0 - h0), l1 = to_tf32(k1 - h1);
    g_kf[(((size_t)bh*256 + ntg)*8 + ks)*32 + lane] = make_float4(h0, h1, l0, l1);
}

// ---------------- V fragment builder (tf32) -----------------------------------
// PV b-frag: (V[key0+tg][dh], V[key0+tg+4][dh]), dh = nvt*8+g, key0 = (kt*8+kks)*8
__global__ void build_vf() {
    int lane = threadIdx.x, kks = threadIdx.y;       // (32, 8)
    int g = lane >> 2, tg = lane & 3;
    int nvt = blockIdx.x;                            // 0..7
    int kt  = blockIdx.y;                            // 0..31
    int bh  = blockIdx.z;
    int b = bh >> 4, h = bh & 15;
    int key0 = (kt*8 + kks)*8;
    int dh = nvt*8 + g;
    float v0 = g_v[(size_t)(b*SS + key0 + tg    )*DD + h*DHH + dh];
    float v1 = g_v[(size_t)(b*SS + key0 + tg + 4)*DD + h*DHH + dh];
    g_vf[((((size_t)bh*32 + kt)*8 + kks)*8 + nvt)*32 + lane] =
        make_float2(to_tf32(v0), to_tf32(v1));
}

// ---------------- tf32 mma.sync GEMM: C[M,1024] = A @ W + bias ---------------
// CTA 128x128, 8 warps (4m x 2n). A in swizzled smem; B-frags direct LDG.
#define GA_SWZ(r, q) ((r)*32 + 4*((q) ^ ((r)&7)))

__device__ __forceinline__ void gemm_mma_body(const float* __restrict__ A,
                                              const float2* __restrict__ Wf,
                                              const float* __restrict__ bias,
                                              float* __restrict__ C) {
    __shared__ float As[2][128*32];
    const int t    = threadIdx.x;
    const int lane = t & 31;
    const int wid  = t >> 5;
    const int wm   = wid >> 1;
    const int wn   = wid & 1;
    const int g    = lane >> 2, tg = lane & 3;
    const int row0 = blockIdx.y * 128;
    const int col0 = blockIdx.x * 128;

    const int srow = t >> 3;        // 0..31 (+32c)
    const int skq  = t & 7;

    float4 ra[4];
    auto ldg_chunk = [&](int k0c) {
#pragma unroll
        for (int c = 0; c < 4; ++c)
            ra[c] = *reinterpret_cast<const float4*>(
                A + (size_t)(row0 + srow + 32*c)*DD + k0c + skq*4);
    };
    auto sts_chunk = [&](float* buf) {
#pragma unroll
        for (int c = 0; c < 4; ++c) {
            int r = srow + 32*c;
            float4 v = ra[c];
            v.x = to_tf32(v.x); v.y = to_tf32(v.y);
            v.z = to_tf32(v.z); v.w = to_tf32(v.w);
            *reinterpret_cast<float4*>(buf + GA_SWZ(r, skq)) = v;
        }
    };

    float4 acc[2][8];
#pragma unroll
    for (int i = 0; i < 2; ++i)
#pragma unroll
        for (int j = 0; j < 8; ++j) acc[i][j] = make_float4(0.f, 0.f, 0.f, 0.f);

    const float2* wbase = Wf + (size_t)(col0 >> 3)*32 + wn*8*32 + lane;

    ldg_chunk(0);
    sts_chunk(As[0]);

    for (int c = 0; c < 32; ++c) {
        __syncthreads();
        if (c + 1 < 32) ldg_chunk((c + 1) * 32);
        const float* buf = As[c & 1];
#pragma unroll
        for (int ks = 0; ks < 4; ++ks) {
            const int kg = c*4 + ks;
            // A fragments: conflict-free scalar LDS from swizzled layout
            uint32_t af[2][4];
#pragma unroll
            for (int mt = 0; mt < 2; ++mt) {
                int r0 = (wm*2 + mt)*16 + g;
                int o0 = r0*32 + 4*((2*ks)   ^ (r0 & 7)) + tg;
                int o1 = r0*32 + 4*((2*ks+1) ^ (r0 & 7)) + tg;
                af[mt][0] = __float_as_uint(buf[o0]);
                af[mt][1] = __float_as_uint(buf[o0 + 256]);
                af[mt][2] = __float_as_uint(buf[o1]);
                af[mt][3] = __float_as_uint(buf[o1 + 256]);
            }
            const float2* wk = wbase + (size_t)kg*128*32;
#pragma unroll
            for (int nt = 0; nt < 8; ++nt) {
                float2 b2 = wk[nt*32];
                uint32_t bf[2] = { __float_as_uint(b2.x), __float_as_uint(b2.y) };
                mma_tf32(acc[0][nt], af[0], bf);
                mma_tf32(acc[1][nt], af[1], bf);
            }
        }
        if (c + 1 < 32) sts_chunk(As[(c + 1) & 1]);
    }

    // epilogue
#pragma unroll
    for (int mt = 0; mt < 2; ++mt) {
        size_t rA = (size_t)(row0 + (wm*2 + mt)*16 + g);
        size_t rB = rA + 8;
#pragma unroll
        for (int nt = 0; nt < 8; ++nt) {
            int col = col0 + (wn*8 + nt)*8 + tg*2;
            float2 b2 = *reinterpret_cast<const float2*>(bias + col);
            float2 o0 = make_float2(acc[mt][nt].x + b2.x, acc[mt][nt].y + b2.y);
            float2 o1 = make_float2(acc[mt][nt].z + b2.x, acc[mt][nt].w + b2.y);
            *reinterpret_cast<float2*>(C + rA*DD + col) = o0;
            *reinterpret_cast<float2*>(C + rB*DD + col) = o1;
        }
    }
}

__global__ __launch_bounds__(256, 2) void gemm_qkv_mma(
    const float* __restrict__ A,
    const float* __restrict__ bq, const float* __restrict__ bk,
    const float* __restrict__ bv) {
    int z = blockIdx.z;
    const float2* Wf  = g_wf + (size_t)z*128*128*32;
    const float* bias = (z == 0) ? bq : (z == 1) ? bk : bv;
    float* C          = (z == 0) ? g_q : (z == 1) ? g_k : g_v;
    gemm_mma_body(A, Wf, bias, C);
}

__global__ __launch_bounds__(256, 2) void gemm_o_mma(
    const float* __restrict__ bo, float* __restrict__ out) {
    gemm_mma_body(g_ctx, g_wf + (size_t)3*128*128*32, bo, out);
}

// ---------------- flash attention, all fragments via direct LDG --------------
// CTA: 128 thr / 4 warps, q-tile 64, key-tile 64. No smem, no syncthreads.
__global__ __launch_bounds__(128) void attn_mma() {
    const int t = threadIdx.x, lane = t & 31, w = t >> 5;
    const int g = lane >> 2, tg = lane & 3;
    const int q0 = blockIdx.x * 64;
    const int bh = blockIdx.y, b = bh >> 4, h = bh & 15;
    const int rowA = q0 + w*16 + g, rowB = rowA + 8;

    // Q fragments hi/lo (resident)
    uint32_t qhi[8][4], qlo[8][4];
    {
        const float* Qb = g_q + (size_t)(b*SS)*DD + h*DHH;
#pragma unroll
        for (int ks = 0; ks < 8; ++ks) {
            float v[4];
            v[0] = Qb[(size_t)rowA*DD + ks*8 + tg];
            v[1] = Qb[(size_t)rowB*DD + ks*8 + tg];
            v[2] = Qb[(size_t)rowA*DD + ks*8 + tg + 4];
            v[3] = Qb[(size_t)rowB*DD + ks*8 + tg + 4];
#pragma unroll
            for (int j = 0; j < 4; ++j) {
                float hi = to_tf32(v[j]);
                qhi[ks][j] = __float_as_uint(hi);
                qlo[ks][j] = __float_as_uint(to_tf32(v[j] - hi));
            }
        }
    }

    const float4* kfb = g_kf + (size_t)bh*256*8*32 + lane;
    const float2* vfb = g_vf + (size_t)bh*32*8*8*32 + lane;

    float4 oacc[8];
#pragma unroll
    for (int nt = 0; nt < 8; ++nt) oacc[nt] = make_float4(0.f, 0.f, 0.f, 0.f);
    float mA = MASKVAL, mB = MASKVAL, lA = 0.f, lB = 0.f;

    for (int kt = 0; kt < 32; ++kt) {
        const uint32_t mA0 = g_maskb[rowA*64 + kt*2];
        const uint32_t mA1 = g_maskb[rowA*64 + kt*2 + 1];
        const uint32_t mB0 = g_maskb[rowB*64 + kt*2];
        const uint32_t mB1 = g_maskb[rowB*64 + kt*2 + 1];

        // ---- S = Q K^T (3xTF32, fragments direct from gmem) ----
        float4 sacc[8];
#pragma unroll
        for (int nt = 0; nt < 8; ++nt) sacc[nt] = make_float4(0.f, 0.f, 0.f, 0.f);

#pragma unroll
        for (int ks = 0; ks < 8; ++ks) {
#pragma unroll
            for (int nt = 0; nt < 8; ++nt) {
                float4 kf = kfb[((size_t)(kt*8 + nt)*8 + ks)*32];
                uint32_t bhf[2] = { __float_as_uint(kf.x), __float_as_uint(kf.y) };
                uint32_t blf[2] = { __float_as_uint(kf.z), __float_as_uint(kf.w) };
                mma_tf32(sacc[nt], qhi[ks], bhf);
                mma_tf32(sacc[nt], qlo[ks], bhf);
                mma_tf32(sacc[nt], qhi[ks], blf);
            }
        }

        // ---- scale + mask ----
#pragma unroll
        for (int nt = 0; nt < 8; ++nt) {
            int c0 = nt*8 + 2*tg;
            uint32_t wa = (c0 & 32) ? mA1 : mA0;
            uint32_t wb = (c0 & 32) ? mB1 : mB0;
            int sh = c0 & 31;
            float sx = sacc[nt].x * 0.125f, sy = sacc[nt].y * 0.125f;
            float sz = sacc[nt].z * 0.125f, sw = sacc[nt].w * 0.125f;
            if (!((wa >> sh) & 1))       sx = MASKVAL;
            if (!((wa >> (sh + 1)) & 1)) sy = MASKVAL;
            if (!((wb >> sh) & 1))       sz = MASKVAL;
            if (!((wb >> (sh + 1)) & 1)) sw = MASKVAL;
            sacc[nt] = make_float4(sx, sy, sz, sw);
        }

        // ---- online softmax ----
        float tmA = MASKVAL, tmB = MASKVAL;
#pragma unroll
        for (int nt = 0; nt < 8; ++nt) {
            tmA = fmaxf(tmA, fmaxf(sacc[nt].x, sacc[nt].y));
            tmB = fmaxf(tmB, fmaxf(sacc[nt].z, sacc[nt].w));
        }
        tmA = fmaxf(tmA, __shfl_xor_sync(0xffffffffu, tmA, 1));
        tmA = fmaxf(tmA, __shfl_xor_sync(0xffffffffu, tmA, 2));
        tmB = fmaxf(tmB, __shfl_xor_sync(0xffffffffu, tmB, 1));
        tmB = fmaxf(tmB, __shfl_xor_sync(0xffffffffu, tmB, 2));

        float mnA = fmaxf(mA, tmA), mnB = fmaxf(mB, tmB);
        float aA = __expf(mA - mnA), aB = __expf(mB - mnB);
        mA = mnA; mB = mnB;

        float sumA = 0.f, sumB = 0.f;
#pragma unroll
        for (int nt = 0; nt < 8; ++nt) {
            float px = __expf(sacc[nt].x - mnA);
            float py = __expf(sacc[nt].y - mnA);
            float pz = __expf(sacc[nt].z - mnB);
            float pw = __expf(sacc[nt].w - mnB);
            sumA += px + py; sumB += pz + pw;
            sacc[nt] = make_float4(px, py, pz, pw);
        }
        sumA += __shfl_xor_sync(0xffffffffu, sumA, 1);
        sumA += __shfl_xor_sync(0xffffffffu, sumA, 2);
        sumB += __shfl_xor_sync(0xffffffffu, sumB, 1);
        sumB += __shfl_xor_sync(0xffffffffu, sumB, 2);
        lA = lA*aA + sumA;
        lB = lB*aB + sumB;
#pragma unroll
        for (int nt = 0; nt < 8; ++nt) {
            oacc[nt].x *= aA; oacc[nt].y *= aA;
            oacc[nt].z *= aB; oacc[nt].w *= aB;
        }

        // ---- O += P V ----
        const int srcA = g*4 + (tg >> 1), srcB = srcA + 2;
        const bool odd = tg & 1;
#pragma unroll
        for (int kks = 0; kks < 8; ++kks) {
            float xa = __shfl_sync(0xffffffffu, sacc[kks].x, srcA);
            float ya = __shfl_sync(0xffffffffu, sacc[kks].y, srcA);
            float xb = __shfl_sync(0xffffffffu, sacc[kks].x, srcB);
            float yb = __shfl_sync(0xffffffffu, sacc[kks].y, srcB);
            float za = __shfl_sync(0xffffffffu, sacc[kks].z, srcA);
            float wa = __shfl_sync(0xffffffffu, sacc[kks].w, srcA);
            float zb = __shfl_sync(0xffffffffu, sacc[kks].z, srcB);
            float wb = __shfl_sync(0xffffffffu, sacc[kks].w, srcB);
            uint32_t af[4];
            af[0] = __float_as_uint(to_tf32(odd ? ya : xa));
            af[1] = __float_as_uint(to_tf32(odd ? wa : za));
            af[2] = __float_as_uint(to_tf32(odd ? yb : xb));
            af[3] = __float_as_uint(to_tf32(odd ? wb : zb));
#pragma unroll
            for (int nvt = 0; nvt < 8; ++nvt) {
                float2 v2 = vfb[(((size_t)kt*8 + kks)*8 + nvt)*32];
                uint32_t bf[2] = { __float_as_uint(v2.x), __float_as_uint(v2.y) };
                mma_tf32(oacc[nvt], af, bf);
            }
        }
    }

    // ---- epilogue ----
    const float invA = 1.f / lA, invB = 1.f / lB;
#pragma unroll
    for (int nt = 0; nt < 8; ++nt) {
        int col = h*DHH + nt*8 + 2*tg;
        float2 oA = make_float2(oacc[nt].x * invA, oacc[nt].y * invA);
        float2 oB = make_float2(oacc[nt].z * invB, oacc[nt].w * invB);
        *reinterpret_cast<float2*>(g_ctx + (size_t)(b*SS + rowA)*DD + col) = oA;
        *reinterpret_cast<float2*>(g_ctx + (size_t)(b*SS + rowB)*DD + col) = oB;
    }
}

// ---------------- launch -----------------------------------------------------
extern "C" void kernel_launch(void* const* d_in, const int* in_sizes, int n_in,
                              void* d_out, int out_size) {
    const float* hs = (const float*)d_in[0];
    const void*  mk = d_in[1];
    const float* Wq = (const float*)d_in[2]; const float* bq = (const float*)d_in[3];
    const float* Wk = (const float*)d_in[4]; const float* bk = (const float*)d_in[5];
    const float* Wv = (const float*)d_in[6]; const float* bv = (const float*)d_in[7];
    const float* Wo = (const float*)d_in[8]; const float* bo = (const float*)d_in[9];
    float* out = (float*)d_out;

    detect_mask_kind<<<1, 32>>>((const unsigned int*)mk);
    repack_mask<<<(SS*(SS/32) + 255)/256, 256>>>(mk);
    build_wf<<<dim3(16, 128, 4), dim3(32, 8)>>>(Wq, Wk, Wv, Wo);

    gemm_qkv_mma<<<dim3(8, 64, 3), 256>>>(hs, bq, bk, bv);
    build_kf<<<dim3(256, 64), dim3(32, 8)>>>();
    build_vf<<<dim3(8, 32, 64), dim3(32, 8)>>>();
    attn_mma<<<dim3(SS/64, BB*HH), 128>>>();
    gemm_o_mma<<<dim3(8, 64), 256>>>(bo, out);
}

// round 9
// speedup vs baseline: 2.0009x; 2.0009x over previous
#include <cuda_runtime.h>
#include <math.h>
#include <stdint.h>

#define BB   4
#define SS   2048
#define DD   1024
#define HH   16
#define DHH  64
#define MTOT (BB*SS)          // 8192
#define MASKVAL (-1e30f)

// ---------------- scratch (static device arrays; no allocation) -------------
__device__ float g_q  [(size_t)MTOT*DD];
__device__ float g_k  [(size_t)MTOT*DD];
__device__ float g_v  [(size_t)MTOT*DD];
__device__ float g_ctx[(size_t)MTOT*DD];
__device__ float4 g_kf[(size_t)64*256*8*32];    // [bh][ntg 256][ks 8][lane] (hi0,hi1,lo0,lo1)
__device__ float2 g_vf[(size_t)64*32*8*8*32];   // [bh][kt][kks][nvt][lane]  (v0,v1) tf32
__device__ float2 g_wf[(size_t)4*128*128*32];   // [z][kg][ntg][lane] (w0,w1) tf32
__device__ uint32_t g_maskb[(size_t)SS*(SS/32)];
__device__ int   g_mask_kind;

__device__ __forceinline__ float to_tf32(float x) {
    float r;
    asm("cvt.rna.tf32.f32 %0, %1;" : "=f"(r) : "f"(x));
    return r;
}

// m16n8k8 tf32 warp MMA (Ampere-class; compiles at baseline sm_103 target)
__device__ __forceinline__ void mma_tf32(float4& d, const uint32_t a[4],
                                         const uint32_t b[2]) {
    asm volatile(
        "mma.sync.aligned.m16n8k8.row.col.f32.tf32.tf32.f32 "
        "{%0,%1,%2,%3}, {%4,%5,%6,%7}, {%8,%9}, {%0,%1,%2,%3};"
        : "+f"(d.x), "+f"(d.y), "+f"(d.z), "+f"(d.w)
        : "r"(a[0]), "r"(a[1]), "r"(a[2]), "r"(a[3]), "r"(b[0]), "r"(b[1]));
}

// ---------------- mask dtype detection + bitmask repack ----------------------
__global__ void detect_mask_kind(const unsigned int* __restrict__ m) {
    int lane = threadIdx.x;
    bool word_like = true;
    for (int i = lane; i < 256; i += 32) {
        unsigned int w = m[i];
        word_like = word_like && (w <= 1u || w == 0x3F800000u);
    }
    word_like = __all_sync(0xffffffffu, word_like);
    if (lane == 0) g_mask_kind = word_like ? 1 : 0;
}

__global__ void repack_mask(const void* __restrict__ mp) {
    int idx = blockIdx.x * blockDim.x + threadIdx.x;
    if (idx >= SS * (SS/32)) return;
    int row = idx >> 6, w = idx & 63;
    uint32_t bits = 0;
    if (g_mask_kind == 0) {
        const uchar4* p = (const uchar4*)mp + (size_t)row*(SS/4) + w*8;
#pragma unroll
        for (int j = 0; j < 8; ++j) {
            uchar4 c = p[j];
            bits |= (uint32_t)(c.x != 0) << (4*j + 0);
            bits |= (uint32_t)(c.y != 0) << (4*j + 1);
            bits |= (uint32_t)(c.z != 0) << (4*j + 2);
            bits |= (uint32_t)(c.w != 0) << (4*j + 3);
        }
    } else {
        const unsigned int* p = (const unsigned int*)mp + (size_t)row*SS + w*32;
#pragma unroll
        for (int j = 0; j < 32; ++j)
            bits |= (uint32_t)(p[j] != 0) << j;
    }
    g_maskb[idx] = bits;
}

// ---------------- weight fragment builder ------------------------------------
__global__ void build_wf(const float* __restrict__ W0, const float* __restrict__ W1,
                         const float* __restrict__ W2, const float* __restrict__ W3) {
    int z = blockIdx.z;
    const float* W = (z == 0) ? W0 : (z == 1) ? W1 : (z == 2) ? W2 : W3;
    int lane = threadIdx.x, ntl = threadIdx.y;       // (32, 8)
    int g = lane >> 2, tg = lane & 3;
    int ntg = blockIdx.x * 8 + ntl;
    int kg  = blockIdx.y;
    int n = ntg*8 + g, k = kg*8 + tg;
    float w0 = W[(size_t)k*DD + n];
    float w1 = W[(size_t)(k+4)*DD + n];
    g_wf[(((size_t)z*128 + kg)*128 + ntg)*32 + lane] =
        make_float2(to_tf32(w0), to_tf32(w1));
}

// ---------------- K fragment builder (hi/lo packed) --------------------------
__global__ void build_kf() {
    int lane = threadIdx.x, ks = threadIdx.y;        // (32, 8)
    int g = lane >> 2, tg = lane & 3;
    int ntg = blockIdx.x;                            // 0..255
    int bh  = blockIdx.y;
    int b = bh >> 4, h = bh & 15;
    const float* kp = g_k + (size_t)(b*SS + ntg*8 + g)*DD + h*DHH + ks*8 + tg;
    float k0 = kp[0], k1 = kp[4];
    float h0 = to_tf32(k0), h1 = to_tf32(k1);
    float l0 = to_tf32(k0 - h0), l1 = to_tf32(k1 - h1);
    g_kf[(((size_t)bh*256 + ntg)*8 + ks)*32 + lane] = make_float4(h0, h1, l0, l1);
}

// ---------------- V fragment builder (tf32) -----------------------------------
__global__ void build_vf() {
    int lane = threadIdx.x, kks = threadIdx.y;       // (32, 8)
    int g = lane >> 2, tg = lane & 3;
    int nvt = blockIdx.x;                            // 0..7
    int kt  = blockIdx.y;                            // 0..31
    int bh  = blockIdx.z;
    int b = bh >> 4, h = bh & 15;
    int key0 = (kt*8 + kks)*8;
    int dh = nvt*8 + g;
    float v0 = g_v[(size_t)(b*SS + key0 + tg    )*DD + h*DHH + dh];
    float v1 = g_v[(size_t)(b*SS + key0 + tg + 4)*DD + h*DHH + dh];
    g_vf[((((size_t)bh*32 + kt)*8 + kks)*8 + nvt)*32 + lane] =
        make_float2(to_tf32(v0), to_tf32(v1));
}

// ---------------- tf32 mma.sync GEMM: C[M,1024] = A @ W + bias ---------------
#define GA_SWZ(r, q) ((r)*32 + 4*((q) ^ ((r)&7)))

__device__ __forceinline__ void gemm_mma_body(const float* __restrict__ A,
                                              const float2* __restrict__ Wf,
                                              const float* __restrict__ bias,
                                              float* __restrict__ C) {
    __shared__ float As[2][128*32];
    const int t    = threadIdx.x;
    const int lane = t & 31;
    const int wid  = t >> 5;
    const int wm   = wid >> 1;
    const int wn   = wid & 1;
    const int g    = lane >> 2, tg = lane & 3;
    const int row0 = blockIdx.y * 128;
    const int col0 = blockIdx.x * 128;

    const int srow = t >> 3;
    const int skq  = t & 7;

    float4 ra[4];
    auto ldg_chunk = [&](int k0c) {
#pragma unroll
        for (int c = 0; c < 4; ++c)
            ra[c] = *reinterpret_cast<const float4*>(
                A + (size_t)(row0 + srow + 32*c)*DD + k0c + skq*4);
    };
    auto sts_chunk = [&](float* buf) {
#pragma unroll
        for (int c = 0; c < 4; ++c) {
            int r = srow + 32*c;
            float4 v = ra[c];
            v.x = to_tf32(v.x); v.y = to_tf32(v.y);
            v.z = to_tf32(v.z); v.w = to_tf32(v.w);
            *reinterpret_cast<float4*>(buf + GA_SWZ(r, skq)) = v;
        }
    };

    float4 acc[2][8];
#pragma unroll
    for (int i = 0; i < 2; ++i)
#pragma unroll
        for (int j = 0; j < 8; ++j) acc[i][j] = make_float4(0.f, 0.f, 0.f, 0.f);

    const float2* wbase = Wf + (size_t)(col0 >> 3)*32 + wn*8*32 + lane;

    ldg_chunk(0);
    sts_chunk(As[0]);

    for (int c = 0; c < 32; ++c) {
        __syncthreads();
        if (c + 1 < 32) ldg_chunk((c + 1) * 32);
        const float* buf = As[c & 1];
#pragma unroll
        for (int ks = 0; ks < 4; ++ks) {
            const int kg = c*4 + ks;
            uint32_t af[2][4];
#pragma unroll
            for (int mt = 0; mt < 2; ++mt) {
                int r0 = (wm*2 + mt)*16 + g;
                int o0 = r0*32 + 4*((2*ks)   ^ (r0 & 7)) + tg;
                int o1 = r0*32 + 4*((2*ks+1) ^ (r0 & 7)) + tg;
                af[mt][0] = __float_as_uint(buf[o0]);
                af[mt][1] = __float_as_uint(buf[o0 + 256]);
                af[mt][2] = __float_as_uint(buf[o1]);
                af[mt][3] = __float_as_uint(buf[o1 + 256]);
            }
            const float2* wk = wbase + (size_t)kg*128*32;
#pragma unroll
            for (int nt = 0; nt < 8; ++nt) {
                float2 b2 = wk[nt*32];
                uint32_t bf[2] = { __float_as_uint(b2.x), __float_as_uint(b2.y) };
                mma_tf32(acc[0][nt], af[0], bf);
                mma_tf32(acc[1][nt], af[1], bf);
            }
        }
        if (c + 1 < 32) sts_chunk(As[(c + 1) & 1]);
    }

#pragma unroll
    for (int mt = 0; mt < 2; ++mt) {
        size_t rA = (size_t)(row0 + (wm*2 + mt)*16 + g);
        size_t rB = rA + 8;
#pragma unroll
        for (int nt = 0; nt < 8; ++nt) {
            int col = col0 + (wn*8 + nt)*8 + tg*2;
            float2 b2 = *reinterpret_cast<const float2*>(bias + col);
            float2 o0 = make_float2(acc[mt][nt].x + b2.x, acc[mt][nt].y + b2.y);
            float2 o1 = make_float2(acc[mt][nt].z + b2.x, acc[mt][nt].w + b2.y);
            *reinterpret_cast<float2*>(C + rA*DD + col) = o0;
            *reinterpret_cast<float2*>(C + rB*DD + col) = o1;
        }
    }
}

__global__ __launch_bounds__(256, 2) void gemm_qkv_mma(
    const float* __restrict__ A,
    const float* __restrict__ bq, const float* __restrict__ bk,
    const float* __restrict__ bv) {
    int z = blockIdx.z;
    const float2* Wf  = g_wf + (size_t)z*128*128*32;
    const float* bias = (z == 0) ? bq : (z == 1) ? bk : bv;
    float* C          = (z == 0) ? g_q : (z == 1) ? g_k : g_v;
    gemm_mma_body(A, Wf, bias, C);
}

__global__ __launch_bounds__(256, 2) void gemm_o_mma(
    const float* __restrict__ bo, float* __restrict__ out) {
    gemm_mma_body(g_ctx, g_wf + (size_t)3*128*128*32, bo, out);
}

// ---------------- flash attention: prebuilt fragments staged via smem --------
// CTA: 128 thr / 4 warps, q-tile 64, key-tile 64.
// Per tile: stage kf (32 KB) + vf (16 KB) cooperatively, then pure LDS+MMA.
__global__ __launch_bounds__(128) void attn_mma() {
    __shared__ float4 kf_s[8*8*32];    // [nt][ks][lane]  (hi0,hi1,lo0,lo1)
    __shared__ float2 vf_s[8*8*32];    // [kks][nvt][lane] (v0,v1)

    const int t = threadIdx.x, lane = t & 31, w = t >> 5;
    const int g = lane >> 2, tg = lane & 3;
    const int q0 = blockIdx.x * 64;
    const int bh = blockIdx.y, b = bh >> 4, h = bh & 15;
    const int rowA = q0 + w*16 + g, rowB = rowA + 8;

    // Q fragments hi/lo (resident)
    uint32_t qhi[8][4], qlo[8][4];
    {
        const float* Qb = g_q + (size_t)(b*SS)*DD + h*DHH;
#pragma unroll
        for (int ks = 0; ks < 8; ++ks) {
            float v[4];
            v[0] = Qb[(size_t)rowA*DD + ks*8 + tg];
            v[1] = Qb[(size_t)rowB*DD + ks*8 + tg];
            v[2] = Qb[(size_t)rowA*DD + ks*8 + tg + 4];
            v[3] = Qb[(size_t)rowB*DD + ks*8 + tg + 4];
#pragma unroll
            for (int j = 0; j < 4; ++j) {
                float hi = to_tf32(v[j]);
                qhi[ks][j] = __float_as_uint(hi);
                qlo[ks][j] = __float_as_uint(to_tf32(v[j] - hi));
            }
        }
    }

    const float4* kf_base = g_kf + (size_t)bh*65536;                       // 256*8*32
    const float4* vf_base = reinterpret_cast<const float4*>(g_vf + (size_t)bh*65536);

    float4 oacc[8];
#pragma unroll
    for (int nt = 0; nt < 8; ++nt) oacc[nt] = make_float4(0.f, 0.f, 0.f, 0.f);
    float mA = MASKVAL, mB = MASKVAL, lA = 0.f, lB = 0.f;

    for (int kt = 0; kt < 32; ++kt) {
        __syncthreads();   // protect previous tile's smem from overwrite
        // ---- stage fragments (contiguous copies) ----
        const float4* src_k = kf_base + (size_t)kt*2048;
        const float4* src_v = vf_base + (size_t)kt*1024;
#pragma unroll
        for (int j = 0; j < 16; ++j) kf_s[t + 128*j] = src_k[t + 128*j];
        float4* vf4 = reinterpret_cast<float4*>(vf_s);
#pragma unroll
        for (int j = 0; j < 8; ++j) vf4[t + 128*j] = src_v[t + 128*j];

        const uint32_t mA0 = g_maskb[rowA*64 + kt*2];
        const uint32_t mA1 = g_maskb[rowA*64 + kt*2 + 1];
        const uint32_t mB0 = g_maskb[rowB*64 + kt*2];
        const uint32_t mB1 = g_maskb[rowB*64 + kt*2 + 1];
        __syncthreads();

        // ---- S = Q K^T (3xTF32) ----
        float4 sacc[8];
#pragma unroll
        for (int nt = 0; nt < 8; ++nt) sacc[nt] = make_float4(0.f, 0.f, 0.f, 0.f);

#pragma unroll
        for (int ks = 0; ks < 8; ++ks) {
#pragma unroll
            for (int nt = 0; nt < 8; ++nt) {
                float4 kf = kf_s[(nt*8 + ks)*32 + lane];
                uint32_t bhf[2] = { __float_as_uint(kf.x), __float_as_uint(kf.y) };
                uint32_t blf[2] = { __float_as_uint(kf.z), __float_as_uint(kf.w) };
                mma_tf32(sacc[nt], qhi[ks], bhf);
                mma_tf32(sacc[nt], qlo[ks], bhf);
                mma_tf32(sacc[nt], qhi[ks], blf);
            }
        }

        // ---- scale + mask ----
#pragma unroll
        for (int nt = 0; nt < 8; ++nt) {
            int c0 = nt*8 + 2*tg;
            uint32_t wa = (c0 & 32) ? mA1 : mA0;
            uint32_t wb = (c0 & 32) ? mB1 : mB0;
            int sh = c0 & 31;
            float sx = sacc[nt].x * 0.125f, sy = sacc[nt].y * 0.125f;
            float sz = sacc[nt].z * 0.125f, sw = sacc[nt].w * 0.125f;
            if (!((wa >> sh) & 1))       sx = MASKVAL;
            if (!((wa >> (sh + 1)) & 1)) sy = MASKVAL;
            if (!((wb >> sh) & 1))       sz = MASKVAL;
            if (!((wb >> (sh + 1)) & 1)) sw = MASKVAL;
            sacc[nt] = make_float4(sx, sy, sz, sw);
        }

        // ---- online softmax ----
        float tmA = MASKVAL, tmB = MASKVAL;
#pragma unroll
        for (int nt = 0; nt < 8; ++nt) {
            tmA = fmaxf(tmA, fmaxf(sacc[nt].x, sacc[nt].y));
            tmB = fmaxf(tmB, fmaxf(sacc[nt].z, sacc[nt].w));
        }
        tmA = fmaxf(tmA, __shfl_xor_sync(0xffffffffu, tmA, 1));
        tmA = fmaxf(tmA, __shfl_xor_sync(0xffffffffu, tmA, 2));
        tmB = fmaxf(tmB, __shfl_xor_sync(0xffffffffu, tmB, 1));
        tmB = fmaxf(tmB, __shfl_xor_sync(0xffffffffu, tmB, 2));

        float mnA = fmaxf(mA, tmA), mnB = fmaxf(mB, tmB);
        float aA = __expf(mA - mnA), aB = __expf(mB - mnB);
        mA = mnA; mB = mnB;

        float sumA = 0.f, sumB = 0.f;
#pragma unroll
        for (int nt = 0; nt < 8; ++nt) {
            float px = __expf(sacc[nt].x - mnA);
            float py = __expf(sacc[nt].y - mnA);
            float pz = __expf(sacc[nt].z - mnB);
            float pw = __expf(sacc[nt].w - mnB);
            sumA += px + py; sumB += pz + pw;
            sacc[nt] = make_float4(px, py, pz, pw);
        }
        sumA += __shfl_xor_sync(0xffffffffu, sumA, 1);
        sumA += __shfl_xor_sync(0xffffffffu, sumA, 2);
        sumB += __shfl_xor_sync(0xffffffffu, sumB, 1);
        sumB += __shfl_xor_sync(0xffffffffu, sumB, 2);
        lA = lA*aA + sumA;
        lB = lB*aB + sumB;
#pragma unroll
        for (int nt = 0; nt < 8; ++nt) {
            oacc[nt].x *= aA; oacc[nt].y *= aA;
            oacc[nt].z *= aB; oacc[nt].w *= aB;
        }

        // ---- O += P V ----
        const int srcA = g*4 + (tg >> 1), srcB = srcA + 2;
        const bool odd = tg & 1;
#pragma unroll
        for (int kks = 0; kks < 8; ++kks) {
            float xa = __shfl_sync(0xffffffffu, sacc[kks].x, srcA);
            float ya = __shfl_sync(0xffffffffu, sacc[kks].y, srcA);
            float xb = __shfl_sync(0xffffffffu, sacc[kks].x, srcB);
            float yb = __shfl_sync(0xffffffffu, sacc[kks].y, srcB);
            float za = __shfl_sync(0xffffffffu, sacc[kks].z, srcA);
            float wa = __shfl_sync(0xffffffffu, sacc[kks].w, srcA);
            float zb = __shfl_sync(0xffffffffu, sacc[kks].z, srcB);
            float wb = __shfl_sync(0xffffffffu, sacc[kks].w, srcB);
            uint32_t af[4];
            af[0] = __float_as_uint(to_tf32(odd ? ya : xa));
            af[1] = __float_as_uint(to_tf32(odd ? wa : za));
            af[2] = __float_as_uint(to_tf32(odd ? yb : xb));
            af[3] = __float_as_uint(to_tf32(odd ? wb : zb));
#pragma unroll
            for (int nvt = 0; nvt < 8; ++nvt) {
                float2 v2 = vf_s[(kks*8 + nvt)*32 + lane];
                uint32_t bf[2] = { __float_as_uint(v2.x), __float_as_uint(v2.y) };
                mma_tf32(oacc[nvt], af, bf);
            }
        }
    }

    // ---- epilogue ----
    const float invA = 1.f / lA, invB = 1.f / lB;
#pragma unroll
    for (int nt = 0; nt < 8; ++nt) {
        int col = h*DHH + nt*8 + 2*tg;
        float2 oA = make_float2(oacc[nt].x * invA, oacc[nt].y * invA);
        float2 oB = make_float2(oacc[nt].z * invB, oacc[nt].w * invB);
        *reinterpret_cast<float2*>(g_ctx + (size_t)(b*SS + rowA)*DD + col) = oA;
        *reinterpret_cast<float2*>(g_ctx + (size_t)(b*SS + rowB)*DD + col) = oB;
    }
}

// ---------------- launch -----------------------------------------------------
extern "C" void kernel_launch(void* const* d_in, const int* in_sizes, int n_in,
                              void* d_out, int out_size) {
    const float* hs = (const float*)d_in[0];
    const void*  mk = d_in[1];
    const float* Wq = (const float*)d_in[2]; const float* bq = (const float*)d_in[3];
    const float* Wk = (const float*)d_in[4]; const float* bk = (const float*)d_in[5];
    const float* Wv = (const float*)d_in[6]; const float* bv = (const float*)d_in[7];
    const float* Wo = (const float*)d_in[8]; const float* bo = (const float*)d_in[9];
    float* out = (float*)d_out;

    detect_mask_kind<<<1, 32>>>((const unsigned int*)mk);
    repack_mask<<<(SS*(SS/32) + 255)/256, 256>>>(mk);
    build_wf<<<dim3(16, 128, 4), dim3(32, 8)>>>(Wq, Wk, Wv, Wo);

    gemm_qkv_mma<<<dim3(8, 64, 3), 256>>>(hs, bq, bk, bv);
    build_kf<<<dim3(256, 64), dim3(32, 8)>>>();
    build_vf<<<dim3(8, 32, 64), dim3(32, 8)>>>();
    attn_mma<<<dim3(SS/64, BB*HH), 128>>>();
    gemm_o_mma<<<dim3(8, 64), 256>>>(bo, out);
}

// round 10
// speedup vs baseline: 2.7027x; 1.3507x over previous
#include <cuda_runtime.h>
#include <math.h>
#include <stdint.h>

#define BB   4
#define SS   2048
#define DD   1024
#define HH   16
#define DHH  64
#define MTOT (BB*SS)          // 8192
#define MASKVAL (-1e30f)

// ---------------- scratch (static device arrays; no allocation) -------------
__device__ float g_a  [(size_t)MTOT*DD];        // hs pre-rounded to tf32
__device__ float g_q  [(size_t)MTOT*DD];
__device__ float g_k  [(size_t)MTOT*DD];
__device__ float g_v  [(size_t)MTOT*DD];
__device__ float g_ctx[(size_t)MTOT*DD];        // written tf32-rounded by attn
__device__ float4 g_kf[(size_t)64*256*8*32];    // [bh][ntg 256][ks 8][lane] (hi0,hi1,lo0,lo1)
__device__ float2 g_vf[(size_t)64*32*8*8*32];   // [bh][kt][kks][nvt][lane]  (v0,v1) tf32
__device__ float2 g_wf[(size_t)4*128*128*32];   // [z][kg][ntg][lane] (w0,w1) tf32
__device__ uint32_t g_maskb[(size_t)SS*(SS/32)];
__device__ int   g_mask_kind;

__device__ __forceinline__ float to_tf32(float x) {
    float r;
    asm("cvt.rna.tf32.f32 %0, %1;" : "=f"(r) : "f"(x));
    return r;
}
__device__ __forceinline__ uint32_t smem_u32(const void* p) {
    uint32_t a;
    asm("{ .reg .u64 t; cvta.to.shared.u64 t, %1; cvt.u32.u64 %0, t; }"
        : "=r"(a) : "l"(p));
    return a;
}
#define CP16(dst, src) \
    asm volatile("cp.async.cg.shared.global [%0], [%1], 16;" :: "r"(dst), "l"(src))
#define CP_COMMIT() asm volatile("cp.async.commit_group;" ::: "memory")
#define CP_WAIT0()  asm volatile("cp.async.wait_group 0;" ::: "memory")

// m16n8k8 tf32 warp MMA
__device__ __forceinline__ void mma_tf32(float4& d, const uint32_t a[4],
                                         const uint32_t b[2]) {
    asm volatile(
        "mma.sync.aligned.m16n8k8.row.col.f32.tf32.tf32.f32 "
        "{%0,%1,%2,%3}, {%4,%5,%6,%7}, {%8,%9}, {%0,%1,%2,%3};"
        : "+f"(d.x), "+f"(d.y), "+f"(d.z), "+f"(d.w)
        : "r"(a[0]), "r"(a[1]), "r"(a[2]), "r"(a[3]), "r"(b[0]), "r"(b[1]));
}

// ---------------- mask dtype detection + bitmask repack ----------------------
__global__ void detect_mask_kind(const unsigned int* __restrict__ m) {
    int lane = threadIdx.x;
    bool word_like = true;
    for (int i = lane; i < 256; i += 32) {
        unsigned int w = m[i];
        word_like = word_like && (w <= 1u || w == 0x3F800000u);
    }
    word_like = __all_sync(0xffffffffu, word_like);
    if (lane == 0) g_mask_kind = word_like ? 1 : 0;
}

__global__ void repack_mask(const void* __restrict__ mp) {
    int idx = blockIdx.x * blockDim.x + threadIdx.x;
    if (idx >= SS * (SS/32)) return;
    int row = idx >> 6, w = idx & 63;
    uint32_t bits = 0;
    if (g_mask_kind == 0) {
        const uchar4* p = (const uchar4*)mp + (size_t)row*(SS/4) + w*8;
#pragma unroll
        for (int j = 0; j < 8; ++j) {
            uchar4 c = p[j];
            bits |= (uint32_t)(c.x != 0) << (4*j + 0);
            bits |= (uint32_t)(c.y != 0) << (4*j + 1);
            bits |= (uint32_t)(c.z != 0) << (4*j + 2);
            bits |= (uint32_t)(c.w != 0) << (4*j + 3);
        }
    } else {
        const unsigned int* p = (const unsigned int*)mp + (size_t)row*SS + w*32;
#pragma unroll
        for (int j = 0; j < 32; ++j)
            bits |= (uint32_t)(p[j] != 0) << j;
    }
    g_maskb[idx] = bits;
}

// ---------------- input pre-round: hs -> g_a (tf32) --------------------------
__global__ void round_a(const float* __restrict__ hs) {
    size_t i = (size_t)(blockIdx.x * blockDim.x + threadIdx.x) * 4;
    if (i >= (size_t)MTOT*DD) return;
    float4 v = *reinterpret_cast<const float4*>(hs + i);
    v.x = to_tf32(v.x); v.y = to_tf32(v.y); v.z = to_tf32(v.z); v.w = to_tf32(v.w);
    *reinterpret_cast<float4*>(g_a + i) = v;
}

// ---------------- weight fragment builder ------------------------------------
__global__ void build_wf(const float* __restrict__ W0, const float* __restrict__ W1,
                         const float* __restrict__ W2, const float* __restrict__ W3) {
    int z = blockIdx.z;
    const float* W = (z == 0) ? W0 : (z == 1) ? W1 : (z == 2) ? W2 : W3;
    int lane = threadIdx.x, ntl = threadIdx.y;       // (32, 8)
    int g = lane >> 2, tg = lane & 3;
    int ntg = blockIdx.x * 8 + ntl;
    int kg  = blockIdx.y;
    int n = ntg*8 + g, k = kg*8 + tg;
    float w0 = W[(size_t)k*DD + n];
    float w1 = W[(size_t)(k+4)*DD + n];
    g_wf[(((size_t)z*128 + kg)*128 + ntg)*32 + lane] =
        make_float2(to_tf32(w0), to_tf32(w1));
}

// ---------------- K fragment builder (hi/lo packed) --------------------------
__global__ void build_kf() {
    int lane = threadIdx.x, ks = threadIdx.y;        // (32, 8)
    int g = lane >> 2, tg = lane & 3;
    int ntg = blockIdx.x;                            // 0..255
    int bh  = blockIdx.y;
    int b = bh >> 4, h = bh & 15;
    const float* kp = g_k + (size_t)(b*SS + ntg*8 + g)*DD + h*DHH + ks*8 + tg;
    float k0 = kp[0], k1 = kp[4];
    float h0 = to_tf32(k0), h1 = to_tf32(k1);
    float l0 = to_tf32(k0 - h0), l1 = to_tf32(k1 - h1);
    g_kf[(((size_t)bh*256 + ntg)*8 + ks)*32 + lane] = make_float4(h0, h1, l0, l1);
}

// ---------------- V fragment builder (tf32) -----------------------------------
__global__ void build_vf() {
    int lane = threadIdx.x, kks = threadIdx.y;       // (32, 8)
    int g = lane >> 2, tg = lane & 3;
    int nvt = blockIdx.x;                            // 0..7
    int kt  = blockIdx.y;                            // 0..31
    int bh  = blockIdx.z;
    int b = bh >> 4, h = bh & 15;
    int key0 = (kt*8 + kks)*8;
    int dh = nvt*8 + g;
    float v0 = g_v[(size_t)(b*SS + key0 + tg    )*DD + h*DHH + dh];
    float v1 = g_v[(size_t)(b*SS + key0 + tg + 4)*DD + h*DHH + dh];
    g_vf[((((size_t)bh*32 + kt)*8 + kks)*8 + nvt)*32 + lane] =
        make_float2(to_tf32(v0), to_tf32(v1));
}

// ---------------- tf32 mma.sync GEMM, cp.async pipelined ---------------------
// CTA 128x128, 8 warps. Double-buffered smem: per buf A 16KB (swizzled) + W 16KB.
#define GA_SWZ(r, q) ((r)*32 + 4*((q) ^ ((r)&7)))
#define GEMM_SMEM (2*32768)

__device__ __forceinline__ void gemm_mma_body(const float* __restrict__ A,
                                              const float2* __restrict__ Wf,
                                              const float* __restrict__ bias,
                                              float* __restrict__ C,
                                              char* smem) {
    const int t    = threadIdx.x;
    const int lane = t & 31;
    const int wid  = t >> 5;
    const int wm   = wid >> 1;
    const int wn   = wid & 1;
    const int g    = lane >> 2, tg = lane & 3;
    const int row0 = blockIdx.y * 128;
    const int col0 = blockIdx.x * 128;
    const int srow = t >> 3;
    const int skq  = t & 7;
    const uint32_t sb = smem_u32(smem);

    auto cp_chunk = [&](int c, uint32_t bufoff) {
        const int k0c = c * 32;
#pragma unroll
        for (int cc = 0; cc < 4; ++cc) {                       // A tile
            int r = srow + 32*cc;
            CP16(sb + bufoff + (uint32_t)(GA_SWZ(r, skq)*4),
                 A + (size_t)(row0 + r)*DD + k0c + skq*4);
        }
#pragma unroll
        for (int j = 0; j < 4; ++j) {                          // W frags
            CP16(sb + bufoff + 16384u + (uint32_t)(j*4096 + t*16),
                 (const char*)(Wf + ((size_t)(c*4 + j)*128 + (col0 >> 3))*32) + t*16);
        }
    };

    float4 acc[2][8];
#pragma unroll
    for (int i = 0; i < 2; ++i)
#pragma unroll
        for (int j = 0; j < 8; ++j) acc[i][j] = make_float4(0.f, 0.f, 0.f, 0.f);

    cp_chunk(0, 0);
    CP_COMMIT(); CP_WAIT0();
    __syncthreads();

    for (int c = 0; c < 32; ++c) {
        const uint32_t bufoff = (c & 1) * 32768u;
        if (c + 1 < 32) { cp_chunk(c + 1, (~c & 1) * 32768u); CP_COMMIT(); }
        const float* As = (const float*)(smem + bufoff);
        const float* Ws = (const float*)(smem + bufoff + 16384);
#pragma unroll
        for (int ks = 0; ks < 4; ++ks) {
            uint32_t af[2][4];
#pragma unroll
            for (int mt = 0; mt < 2; ++mt) {
                int r0 = (wm*2 + mt)*16 + g;
                int o0 = r0*32 + 4*((2*ks)   ^ (r0 & 7)) + tg;
                int o1 = r0*32 + 4*((2*ks+1) ^ (r0 & 7)) + tg;
                af[mt][0] = __float_as_uint(As[o0]);
                af[mt][1] = __float_as_uint(As[o0 + 256]);
                af[mt][2] = __float_as_uint(As[o1]);
                af[mt][3] = __float_as_uint(As[o1 + 256]);
            }
            const float2* wk = (const float2*)(Ws + ks*1024);
#pragma unroll
            for (int nt = 0; nt < 8; ++nt) {
                float2 b2 = wk[(wn*8 + nt)*32 + lane];
                uint32_t bf[2] = { __float_as_uint(b2.x), __float_as_uint(b2.y) };
                mma_tf32(acc[0][nt], af[0], bf);
                mma_tf32(acc[1][nt], af[1], bf);
            }
        }
        if (c + 1 < 32) { CP_WAIT0(); __syncthreads(); }
    }

#pragma unroll
    for (int mt = 0; mt < 2; ++mt) {
        size_t rA = (size_t)(row0 + (wm*2 + mt)*16 + g);
        size_t rB = rA + 8;
#pragma unroll
        for (int nt = 0; nt < 8; ++nt) {
            int col = col0 + (wn*8 + nt)*8 + tg*2;
            float2 b2 = *reinterpret_cast<const float2*>(bias + col);
            float2 o0 = make_float2(acc[mt][nt].x + b2.x, acc[mt][nt].y + b2.y);
            float2 o1 = make_float2(acc[mt][nt].z + b2.x, acc[mt][nt].w + b2.y);
            *reinterpret_cast<float2*>(C + rA*DD + col) = o0;
            *reinterpret_cast<float2*>(C + rB*DD + col) = o1;
        }
    }
}

__global__ __launch_bounds__(256, 2) void gemm_qkv_mma(
    const float* __restrict__ bq, const float* __restrict__ bk,
    const float* __restrict__ bv) {
    extern __shared__ char smg[];
    int z = blockIdx.z;
    const float2* Wf  = g_wf + (size_t)z*128*128*32;
    const float* bias = (z == 0) ? bq : (z == 1) ? bk : bv;
    float* C          = (z == 0) ? g_q : (z == 1) ? g_k : g_v;
    gemm_mma_body(g_a, Wf, bias, C, smg);
}

__global__ __launch_bounds__(256, 2) void gemm_o_mma(
    const float* __restrict__ bo, float* __restrict__ out) {
    extern __shared__ char smg[];
    gemm_mma_body(g_ctx, g_wf + (size_t)3*128*128*32, bo, out, smg);
}

// ---------------- flash attention: q-tile 128, cp.async double buffer --------
// 256 thr / 8 warps. Per buf: kf 32KB + vf 16KB = 48KB; x2 = 96KB dynamic.
#define ATT_SMEM (2*49152)

__global__ __launch_bounds__(256, 2) void attn_mma() {
    extern __shared__ char sma[];
    const uint32_t sb = smem_u32(sma);

    const int t = threadIdx.x, lane = t & 31, w = t >> 5;
    const int g = lane >> 2, tg = lane & 3;
    const int q0 = blockIdx.x * 128;
    const int bh = blockIdx.y, b = bh >> 4, h = bh & 15;
    const int rowA = q0 + w*16 + g, rowB = rowA + 8;

    // Q resident in fp32 (hi/lo derived per ks in the hot loop)
    float qf[8][4];
    {
        const float* Qb = g_q + (size_t)(b*SS)*DD + h*DHH;
#pragma unroll
        for (int ks = 0; ks < 8; ++ks) {
            qf[ks][0] = Qb[(size_t)rowA*DD + ks*8 + tg];
            qf[ks][1] = Qb[(size_t)rowB*DD + ks*8 + tg];
            qf[ks][2] = Qb[(size_t)rowA*DD + ks*8 + tg + 4];
            qf[ks][3] = Qb[(size_t)rowB*DD + ks*8 + tg + 4];
        }
    }

    const float4* kf_base = g_kf + (size_t)bh*65536;
    const float4* vf_base = reinterpret_cast<const float4*>(g_vf) + (size_t)bh*32768;

    auto cp_tile = [&](int kt, uint32_t bufoff) {
        const char* srcK = (const char*)(kf_base + (size_t)kt*2048);
        const char* srcV = (const char*)(vf_base + (size_t)kt*1024);
#pragma unroll
        for (int j = 0; j < 8; ++j) {
            int idx = t + 256*j;
            CP16(sb + bufoff + (uint32_t)idx*16, srcK + (size_t)idx*16);
        }
#pragma unroll
        for (int j = 0; j < 4; ++j) {
            int idx = t + 256*j;
            CP16(sb + bufoff + 32768u + (uint32_t)idx*16, srcV + (size_t)idx*16);
        }
    };

    float4 oacc[8];
#pragma unroll
    for (int nt = 0; nt < 8; ++nt) oacc[nt] = make_float4(0.f, 0.f, 0.f, 0.f);
    float mA = MASKVAL, mB = MASKVAL, lA = 0.f, lB = 0.f;

    cp_tile(0, 0);
    CP_COMMIT(); CP_WAIT0();
    __syncthreads();

    for (int kt = 0; kt < 32; ++kt) {
        const uint32_t bufoff = (kt & 1) * 49152u;
        if (kt + 1 < 32) { cp_tile(kt + 1, (~kt & 1) * 49152u); CP_COMMIT(); }

        const uint32_t mA0 = g_maskb[rowA*64 + kt*2];
        const uint32_t mA1 = g_maskb[rowA*64 + kt*2 + 1];
        const uint32_t mB0 = g_maskb[rowB*64 + kt*2];
        const uint32_t mB1 = g_maskb[rowB*64 + kt*2 + 1];

        const float4* kf_s = (const float4*)(sma + bufoff);
        const float2* vf_s = (const float2*)(sma + bufoff + 32768);

        // ---- S = Q K^T (3xTF32) ----
        float4 sacc[8];
#pragma unroll
        for (int nt = 0; nt < 8; ++nt) sacc[nt] = make_float4(0.f, 0.f, 0.f, 0.f);

#pragma unroll
        for (int ks = 0; ks < 8; ++ks) {
            uint32_t qh[4], ql[4];
#pragma unroll
            for (int j = 0; j < 4; ++j) {
                float hi = to_tf32(qf[ks][j]);
                qh[j] = __float_as_uint(hi);
                ql[j] = __float_as_uint(to_tf32(qf[ks][j] - hi));
            }
#pragma unroll
            for (int nt = 0; nt < 8; ++nt) {
                float4 kf = kf_s[(nt*8 + ks)*32 + lane];
                uint32_t bhf[2] = { __float_as_uint(kf.x), __float_as_uint(kf.y) };
                uint32_t blf[2] = { __float_as_uint(kf.z), __float_as_uint(kf.w) };
                mma_tf32(sacc[nt], qh, bhf);
                mma_tf32(sacc[nt], ql, bhf);
                mma_tf32(sacc[nt], qh, blf);
            }
        }

        // ---- scale + mask ----
#pragma unroll
        for (int nt = 0; nt < 8; ++nt) {
            int c0 = nt*8 + 2*tg;
            uint32_t wa = (c0 & 32) ? mA1 : mA0;
            uint32_t wb = (c0 & 32) ? mB1 : mB0;
            int sh = c0 & 31;
            float sx = sacc[nt].x * 0.125f, sy = sacc[nt].y * 0.125f;
            float sz = sacc[nt].z * 0.125f, sw = sacc[nt].w * 0.125f;
            if (!((wa >> sh) & 1))       sx = MASKVAL;
            if (!((wa >> (sh + 1)) & 1)) sy = MASKVAL;
            if (!((wb >> sh) & 1))       sz = MASKVAL;
            if (!((wb >> (sh + 1)) & 1)) sw = MASKVAL;
            sacc[nt] = make_float4(sx, sy, sz, sw);
        }

        // ---- online softmax ----
        float tmA = MASKVAL, tmB = MASKVAL;
#pragma unroll
        for (int nt = 0; nt < 8; ++nt) {
            tmA = fmaxf(tmA, fmaxf(sacc[nt].x, sacc[nt].y));
            tmB = fmaxf(tmB, fmaxf(sacc[nt].z, sacc[nt].w));
        }
        tmA = fmaxf(tmA, __shfl_xor_sync(0xffffffffu, tmA, 1));
        tmA = fmaxf(tmA, __shfl_xor_sync(0xffffffffu, tmA, 2));
        tmB = fmaxf(tmB, __shfl_xor_sync(0xffffffffu, tmB, 1));
        tmB = fmaxf(tmB, __shfl_xor_sync(0xffffffffu, tmB, 2));

        float mnA = fmaxf(mA, tmA), mnB = fmaxf(mB, tmB);
        float aA = __expf(mA - mnA), aB = __expf(mB - mnB);
        mA = mnA; mB = mnB;

        float sumA = 0.f, sumB = 0.f;
#pragma unroll
        for (int nt = 0; nt < 8; ++nt) {
            float px = __expf(sacc[nt].x - mnA);
            float py = __expf(sacc[nt].y - mnA);
            float pz = __expf(sacc[nt].z - mnB);
            float pw = __expf(sacc[nt].w - mnB);
            sumA += px + py; sumB += pz + pw;
            sacc[nt] = make_float4(px, py, pz, pw);
        }
        sumA += __shfl_xor_sync(0xffffffffu, sumA, 1);
        sumA += __shfl_xor_sync(0xffffffffu, sumA, 2);
        sumB += __shfl_xor_sync(0xffffffffu, sumB, 1);
        sumB += __shfl_xor_sync(0xffffffffu, sumB, 2);
        lA = lA*aA + sumA;
        lB = lB*aB + sumB;
#pragma unroll
        for (int nt = 0; nt < 8; ++nt) {
            oacc[nt].x *= aA; oacc[nt].y *= aA;
            oacc[nt].z *= aB; oacc[nt].w *= aB;
        }

        // ---- O += P V ----
        const int srcA = g*4 + (tg >> 1), srcB = srcA + 2;
        const bool odd = tg & 1;
#pragma unroll
        for (int kks = 0; kks < 8; ++kks) {
            float xa = __shfl_sync(0xffffffffu, sacc[kks].x, srcA);
            float ya = __shfl_sync(0xffffffffu, sacc[kks].y, srcA);
            float xb = __shfl_sync(0xffffffffu, sacc[kks].x, srcB);
            float yb = __shfl_sync(0xffffffffu, sacc[kks].y, srcB);
            float za = __shfl_sync(0xffffffffu, sacc[kks].z, srcA);
            float wa = __shfl_sync(0xffffffffu, sacc[kks].w, srcA);
            float zb = __shfl_sync(0xffffffffu, sacc[kks].z, srcB);
            float wb = __shfl_sync(0xffffffffu, sacc[kks].w, srcB);
            uint32_t af[4];
            af[0] = __float_as_uint(to_tf32(odd ? ya : xa));
            af[1] = __float_as_uint(to_tf32(odd ? wa : za));
            af[2] = __float_as_uint(to_tf32(odd ? yb : xb));
            af[3] = __float_as_uint(to_tf32(odd ? wb : zb));
#pragma unroll
            for (int nvt = 0; nvt < 8; ++nvt) {
                float2 v2 = vf_s[(kks*8 + nvt)*32 + lane];
                uint32_t bf[2] = { __float_as_uint(v2.x), __float_as_uint(v2.y) };
                mma_tf32(oacc[nvt], af, bf);
            }
        }
        if (kt + 1 < 32) { CP_WAIT0(); __syncthreads(); }
    }

    // ---- epilogue: normalize + write ctx tf32-rounded (feeds O-GEMM) ----
    const float invA = 1.f / lA, invB = 1.f / lB;
#pragma unroll
    for (int nt = 0; nt < 8; ++nt) {
        int col = h*DHH + nt*8 + 2*tg;
        float2 oA = make_float2(to_tf32(oacc[nt].x * invA), to_tf32(oacc[nt].y * invA));
        float2 oB = make_float2(to_tf32(oacc[nt].z * invB), to_tf32(oacc[nt].w * invB));
        *reinterpret_cast<float2*>(g_ctx + (size_t)(b*SS + rowA)*DD + col) = oA;
        *reinterpret_cast<float2*>(g_ctx + (size_t)(b*SS + rowB)*DD + col) = oB;
    }
}

// ---------------- launch -----------------------------------------------------
extern "C" void kernel_launch(void* const* d_in, const int* in_sizes, int n_in,
                              void* d_out, int out_size) {
    const float* hs = (const float*)d_in[0];
    const void*  mk = d_in[1];
    const float* Wq = (const float*)d_in[2]; const float* bq = (const float*)d_in[3];
    const float* Wk = (const float*)d_in[4]; const float* bk = (const float*)d_in[5];
    const float* Wv = (const float*)d_in[6]; const float* bv = (const float*)d_in[7];
    const float* Wo = (const float*)d_in[8]; const float* bo = (const float*)d_in[9];
    float* out = (float*)d_out;

    static bool attr_set = false;
    if (!attr_set) {
        cudaFuncSetAttribute(gemm_qkv_mma,
                             cudaFuncAttributeMaxDynamicSharedMemorySize, GEMM_SMEM);
        cudaFuncSetAttribute(gemm_o_mma,
                             cudaFuncAttributeMaxDynamicSharedMemorySize, GEMM_SMEM);
        cudaFuncSetAttribute(attn_mma,
                             cudaFuncAttributeMaxDynamicSharedMemorySize, ATT_SMEM);
        attr_set = true;
    }

    detect_mask_kind<<<1, 32>>>((const unsigned int*)mk);
    repack_mask<<<(SS*(SS/32) + 255)/256, 256>>>(mk);
    build_wf<<<dim3(16, 128, 4), dim3(32, 8)>>>(Wq, Wk, Wv, Wo);
    round_a<<<(MTOT*DD/4 + 255)/256, 256>>>(hs);

    gemm_qkv_mma<<<dim3(8, 64, 3), 256, GEMM_SMEM>>>(bq, bk, bv);
    build_kf<<<dim3(256, 64), dim3(32, 8)>>>();
    build_vf<<<dim3(8, 32, 64), dim3(32, 8)>>>();
    attn_mma<<<dim3(SS/128, BB*HH), 256, ATT_SMEM>>>();
    gemm_o_mma<<<dim3(8, 64), 256, GEMM_SMEM>>>(bo, out);
}

// round 11
// speedup vs baseline: 2.7165x; 1.0051x over previous
#include <cuda_runtime.h>
#include <math.h>
#include <stdint.h>

#define BB   4
#define SS   2048
#define DD   1024
#define HH   16
#define DHH  64
#define MTOT (BB*SS)          // 8192
#define MASKVAL (-1e30f)

// ---------------- scratch (static device arrays; no allocation) -------------
__device__ float g_a  [(size_t)MTOT*DD];        // hs pre-rounded to tf32
__device__ float g_q  [(size_t)MTOT*DD];
__device__ float g_k  [(size_t)MTOT*DD];
__device__ float g_v  [(size_t)MTOT*DD];
__device__ float g_ctx[(size_t)MTOT*DD];        // written tf32-rounded by attn
__device__ float4 g_kf[(size_t)64*256*8*32];    // [bh][ntg 256][ks 8][lane] (hi0,hi1,lo0,lo1)
__device__ float2 g_vf[(size_t)64*32*8*8*32];   // [bh][kt][kks][nvt][lane]  (v0,v1) tf32
__device__ float2 g_wf[(size_t)4*128*128*32];   // [z][kg][ntg][lane] (w0,w1) tf32
__device__ uint32_t g_maskb[(size_t)SS*(SS/32)];
__device__ int   g_mask_kind;

__device__ __forceinline__ float to_tf32(float x) {
    float r;
    asm("cvt.rna.tf32.f32 %0, %1;" : "=f"(r) : "f"(x));
    return r;
}
__device__ __forceinline__ uint32_t smem_u32(const void* p) {
    uint32_t a;
    asm("{ .reg .u64 t; cvta.to.shared.u64 t, %1; cvt.u32.u64 %0, t; }"
        : "=r"(a) : "l"(p));
    return a;
}
#define CP16(dst, src) \
    asm volatile("cp.async.cg.shared.global [%0], [%1], 16;" :: "r"(dst), "l"(src))
#define CP_COMMIT() asm volatile("cp.async.commit_group;" ::: "memory")
#define CP_WAIT0()  asm volatile("cp.async.wait_group 0;" ::: "memory")
#define CP_WAIT1()  asm volatile("cp.async.wait_group 1;" ::: "memory")

// m16n8k8 tf32 warp MMA
__device__ __forceinline__ void mma_tf32(float4& d, const uint32_t a[4],
                                         const uint32_t b[2]) {
    asm volatile(
        "mma.sync.aligned.m16n8k8.row.col.f32.tf32.tf32.f32 "
        "{%0,%1,%2,%3}, {%4,%5,%6,%7}, {%8,%9}, {%0,%1,%2,%3};"
        : "+f"(d.x), "+f"(d.y), "+f"(d.z), "+f"(d.w)
        : "r"(a[0]), "r"(a[1]), "r"(a[2]), "r"(a[3]), "r"(b[0]), "r"(b[1]));
}

// ---------------- mask dtype detection + bitmask repack ----------------------
__global__ void detect_mask_kind(const unsigned int* __restrict__ m) {
    int lane = threadIdx.x;
    bool word_like = true;
    for (int i = lane; i < 256; i += 32) {
        unsigned int w = m[i];
        word_like = word_like && (w <= 1u || w == 0x3F800000u);
    }
    word_like = __all_sync(0xffffffffu, word_like);
    if (lane == 0) g_mask_kind = word_like ? 1 : 0;
}

__global__ void repack_mask(const void* __restrict__ mp) {
    int idx = blockIdx.x * blockDim.x + threadIdx.x;
    if (idx >= SS * (SS/32)) return;
    int row = idx >> 6, w = idx & 63;
    uint32_t bits = 0;
    if (g_mask_kind == 0) {
        const uchar4* p = (const uchar4*)mp + (size_t)row*(SS/4) + w*8;
#pragma unroll
        for (int j = 0; j < 8; ++j) {
            uchar4 c = p[j];
            bits |= (uint32_t)(c.x != 0) << (4*j + 0);
            bits |= (uint32_t)(c.y != 0) << (4*j + 1);
            bits |= (uint32_t)(c.z != 0) << (4*j + 2);
            bits |= (uint32_t)(c.w != 0) << (4*j + 3);
        }
    } else {
        const unsigned int* p = (const unsigned int*)mp + (size_t)row*SS + w*32;
#pragma unroll
        for (int j = 0; j < 32; ++j)
            bits |= (uint32_t)(p[j] != 0) << j;
    }
    g_maskb[idx] = bits;
}

// ---------------- input pre-round: hs -> g_a (tf32) --------------------------
__global__ void round_a(const float* __restrict__ hs) {
    size_t i = (size_t)(blockIdx.x * blockDim.x + threadIdx.x) * 4;
    if (i >= (size_t)MTOT*DD) return;
    float4 v = *reinterpret_cast<const float4*>(hs + i);
    v.x = to_tf32(v.x); v.y = to_tf32(v.y); v.z = to_tf32(v.z); v.w = to_tf32(v.w);
    *reinterpret_cast<float4*>(g_a + i) = v;
}

// ---------------- coalesced weight fragment builder --------------------------
// tile: 64 k x 128 n. smem stride 132 (4*tg+g conflict-free on emit reads).
__global__ void build_wf_t(const float* __restrict__ W0, const float* __restrict__ W1,
                           const float* __restrict__ W2, const float* __restrict__ W3) {
    __shared__ float sW[64*132];
    int z = blockIdx.z;
    const float* W = (z == 0) ? W0 : (z == 1) ? W1 : (z == 2) ? W2 : W3;
    const int t = threadIdx.x;
    const int ntg0 = blockIdx.x * 16;     // n-tile start (groups of 8)
    const int kg0  = blockIdx.y * 8;      // k-tile start (groups of 8)
    const int n0 = ntg0 * 8, k0 = kg0 * 8;

#pragma unroll
    for (int j = 0; j < 8; ++j) {                    // load 64x128 coalesced
        int idx = t + 256*j;
        int r = idx >> 5, c4 = idx & 31;
        float4 v = *reinterpret_cast<const float4*>(W + (size_t)(k0 + r)*DD + n0 + c4*4);
        *reinterpret_cast<float4*>(&sW[r*132 + c4*4]) = v;
    }
    __syncthreads();

#pragma unroll
    for (int j = 0; j < 16; ++j) {                   // emit 4096 float2
        int idx = t + 256*j;
        int lane = idx & 31, ntgL = (idx >> 5) & 15, kgL = idx >> 9;
        int g = lane >> 2, tg = lane & 3;
        float w0 = sW[(kgL*8 + tg    )*132 + ntgL*8 + g];
        float w1 = sW[(kgL*8 + tg + 4)*132 + ntgL*8 + g];
        g_wf[(((size_t)z*128 + kg0 + kgL)*128 + ntg0 + ntgL)*32 + lane] =
            make_float2(to_tf32(w0), to_tf32(w1));
    }
}

// ---------------- coalesced K fragment builder (hi/lo packed) ----------------
// tile: 128 seq x 64 dh. smem stride 68 (4*g+tg conflict-free on emit reads).
__global__ void build_kf_t() {
    __shared__ float sK[128*68];
    const int t = threadIdx.x;
    const int s0 = blockIdx.x * 128;
    const int bh = blockIdx.y, b = bh >> 4, h = bh & 15;

#pragma unroll
    for (int j = 0; j < 8; ++j) {                    // load 128x64 coalesced
        int idx = t + 256*j;
        int r = idx >> 4, c4 = idx & 15;
        float4 v = *reinterpret_cast<const float4*>(
            g_k + (size_t)(b*SS + s0 + r)*DD + h*DHH + c4*4);
        *reinterpret_cast<float4*>(&sK[r*68 + c4*4]) = v;
    }
    __syncthreads();

#pragma unroll
    for (int j = 0; j < 16; ++j) {                   // emit 4096 float4
        int idx = t + 256*j;
        int lane = idx & 31, ks = (idx >> 5) & 7, ntgL = idx >> 8;
        int g = lane >> 2, tg = lane & 3;
        float k0v = sK[(ntgL*8 + g)*68 + ks*8 + tg];
        float k1v = sK[(ntgL*8 + g)*68 + ks*8 + tg + 4];
        float h0 = to_tf32(k0v), h1 = to_tf32(k1v);
        g_kf[(((size_t)bh*256 + (s0 >> 3) + ntgL)*8 + ks)*32 + lane] =
            make_float4(h0, h1, to_tf32(k0v - h0), to_tf32(k1v - h1));
    }
}

// ---------------- coalesced V fragment builder (tf32) ------------------------
// tile: 128 keys x 64 dh (covers 2 kt).
__global__ void build_vf_t() {
    __shared__ float sV[128*68];
    const int t = threadIdx.x;
    const int s0 = blockIdx.x * 128;
    const int kt0 = blockIdx.x * 2;
    const int bh = blockIdx.y, b = bh >> 4, h = bh & 15;

#pragma unroll
    for (int j = 0; j < 8; ++j) {
        int idx = t + 256*j;
        int r = idx >> 4, c4 = idx & 15;
        float4 v = *reinterpret_cast<const float4*>(
            g_v + (size_t)(b*SS + s0 + r)*DD + h*DHH + c4*4);
        *reinterpret_cast<float4*>(&sV[r*68 + c4*4]) = v;
    }
    __syncthreads();

#pragma unroll
    for (int j = 0; j < 16; ++j) {                   // emit 4096 float2
        int idx = t + 256*j;
        int lane = idx & 31, nvt = (idx >> 5) & 7, kks = (idx >> 8) & 7, ktL = idx >> 11;
        int g = lane >> 2, tg = lane & 3;
        int keyL = (ktL*8 + kks)*8;
        float v0 = sV[(keyL + tg    )*68 + nvt*8 + g];
        float v1 = sV[(keyL + tg + 4)*68 + nvt*8 + g];
        g_vf[((((size_t)bh*32 + kt0 + ktL)*8 + kks)*8 + nvt)*32 + lane] =
            make_float2(to_tf32(v0), to_tf32(v1));
    }
}

// ---------------- tf32 mma.sync GEMM, 3-stage cp.async pipeline --------------
#define GA_SWZ(r, q) ((r)*32 + 4*((q) ^ ((r)&7)))
#define GEMM_SMEM (3*32768)

__device__ __forceinline__ void gemm_mma_body(const float* __restrict__ A,
                                              const float2* __restrict__ Wf,
                                              const float* __restrict__ bias,
                                              float* __restrict__ C,
                                              char* smem) {
    const int t    = threadIdx.x;
    const int lane = t & 31;
    const int wid  = t >> 5;
    const int wm   = wid >> 1;
    const int wn   = wid & 1;
    const int g    = lane >> 2, tg = lane & 3;
    const int row0 = blockIdx.y * 128;
    const int col0 = blockIdx.x * 128;
    const int srow = t >> 3;
    const int skq  = t & 7;
    const uint32_t sb = smem_u32(smem);

    auto cp_chunk = [&](int c, uint32_t bufoff) {
        const int k0c = c * 32;
#pragma unroll
        for (int cc = 0; cc < 4; ++cc) {
            int r = srow + 32*cc;
            CP16(sb + bufoff + (uint32_t)(GA_SWZ(r, skq)*4),
                 A + (size_t)(row0 + r)*DD + k0c + skq*4);
        }
#pragma unroll
        for (int j = 0; j < 4; ++j) {
            CP16(sb + bufoff + 16384u + (uint32_t)(j*4096 + t*16),
                 (const char*)(Wf + ((size_t)(c*4 + j)*128 + (col0 >> 3))*32) + t*16);
        }
    };

    float4 acc[2][8];
#pragma unroll
    for (int i = 0; i < 2; ++i)
#pragma unroll
        for (int j = 0; j < 8; ++j) acc[i][j] = make_float4(0.f, 0.f, 0.f, 0.f);

    cp_chunk(0, 0);       CP_COMMIT();
    cp_chunk(1, 32768u);  CP_COMMIT();
    CP_WAIT1();
    __syncthreads();

    for (int c = 0; c < 32; ++c) {
        const uint32_t bufoff = (uint32_t)(c % 3) * 32768u;
        if (c + 2 < 32) { cp_chunk(c + 2, (uint32_t)((c + 2) % 3) * 32768u); CP_COMMIT(); }
        const float* As = (const float*)(smem + bufoff);
        const float* Ws = (const float*)(smem + bufoff + 16384);
#pragma unroll
        for (int ks = 0; ks < 4; ++ks) {
            uint32_t af[2][4];
#pragma unroll
            for (int mt = 0; mt < 2; ++mt) {
                int r0 = (wm*2 + mt)*16 + g;
                int o0 = r0*32 + 4*((2*ks)   ^ (r0 & 7)) + tg;
                int o1 = r0*32 + 4*((2*ks+1) ^ (r0 & 7)) + tg;
                af[mt][0] = __float_as_uint(As[o0]);
                af[mt][1] = __float_as_uint(As[o0 + 256]);
                af[mt][2] = __float_as_uint(As[o1]);
                af[mt][3] = __float_as_uint(As[o1 + 256]);
            }
            const float2* wk = (const float2*)(Ws + ks*1024);
#pragma unroll
            for (int nt = 0; nt < 8; ++nt) {
                float2 b2 = wk[(wn*8 + nt)*32 + lane];
                uint32_t bf[2] = { __float_as_uint(b2.x), __float_as_uint(b2.y) };
                mma_tf32(acc[0][nt], af[0], bf);
                mma_tf32(acc[1][nt], af[1], bf);
            }
        }
        if (c + 1 < 32) {
            if (c + 2 < 32) CP_WAIT1(); else CP_WAIT0();
            __syncthreads();
        }
    }

#pragma unroll
    for (int mt = 0; mt < 2; ++mt) {
        size_t rA = (size_t)(row0 + (wm*2 + mt)*16 + g);
        size_t rB = rA + 8;
#pragma unroll
        for (int nt = 0; nt < 8; ++nt) {
            int col = col0 + (wn*8 + nt)*8 + tg*2;
            float2 b2 = *reinterpret_cast<const float2*>(bias + col);
            float2 o0 = make_float2(acc[mt][nt].x + b2.x, acc[mt][nt].y + b2.y);
            float2 o1 = make_float2(acc[mt][nt].z + b2.x, acc[mt][nt].w + b2.y);
            *reinterpret_cast<float2*>(C + rA*DD + col) = o0;
            *reinterpret_cast<float2*>(C + rB*DD + col) = o1;
        }
    }
}

__global__ __launch_bounds__(256, 2) void gemm_qkv_mma(
    const float* __restrict__ bq, const float* __restrict__ bk,
    const float* __restrict__ bv) {
    extern __shared__ char smg[];
    int z = blockIdx.z;
    const float2* Wf  = g_wf + (size_t)z*128*128*32;
    const float* bias = (z == 0) ? bq : (z == 1) ? bk : bv;
    float* C          = (z == 0) ? g_q : (z == 1) ? g_k : g_v;
    gemm_mma_body(g_a, Wf, bias, C, smg);
}

__global__ __launch_bounds__(256, 2) void gemm_o_mma(
    const float* __restrict__ bo, float* __restrict__ out) {
    extern __shared__ char smg[];
    gemm_mma_body(g_ctx, g_wf + (size_t)3*128*128*32, bo, out, smg);
}

// ---------------- flash attention: q-tile 128, cp.async double buffer --------
#define ATT_SMEM (2*49152)

__global__ __launch_bounds__(256, 2) void attn_mma() {
    extern __shared__ char sma[];
    const uint32_t sb = smem_u32(sma);

    const int t = threadIdx.x, lane = t & 31, w = t >> 5;
    const int g = lane >> 2, tg = lane & 3;
    const int q0 = blockIdx.x * 128;
    const int bh = blockIdx.y, b = bh >> 4, h = bh & 15;
    const int rowA = q0 + w*16 + g, rowB = rowA + 8;

    // Q resident in fp32, pre-scaled by 1/8 (exact; commutes with tf32 rounding)
    float qf[8][4];
    {
        const float* Qb = g_q + (size_t)(b*SS)*DD + h*DHH;
#pragma unroll
        for (int ks = 0; ks < 8; ++ks) {
            qf[ks][0] = 0.125f * Qb[(size_t)rowA*DD + ks*8 + tg];
            qf[ks][1] = 0.125f * Qb[(size_t)rowB*DD + ks*8 + tg];
            qf[ks][2] = 0.125f * Qb[(size_t)rowA*DD + ks*8 + tg + 4];
            qf[ks][3] = 0.125f * Qb[(size_t)rowB*DD + ks*8 + tg + 4];
        }
    }

    const float4* kf_base = g_kf + (size_t)bh*65536;
    const float4* vf_base = reinterpret_cast<const float4*>(g_vf) + (size_t)bh*32768;

    auto cp_tile = [&](int kt, uint32_t bufoff) {
        const char* srcK = (const char*)(kf_base + (size_t)kt*2048);
        const char* srcV = (const char*)(vf_base + (size_t)kt*1024);
#pragma unroll
        for (int j = 0; j < 8; ++j) {
            int idx = t + 256*j;
            CP16(sb + bufoff + (uint32_t)idx*16, srcK + (size_t)idx*16);
        }
#pragma unroll
        for (int j = 0; j < 4; ++j) {
            int idx = t + 256*j;
            CP16(sb + bufoff + 32768u + (uint32_t)idx*16, srcV + (size_t)idx*16);
        }
    };

    float4 oacc[8];
#pragma unroll
    for (int nt = 0; nt < 8; ++nt) oacc[nt] = make_float4(0.f, 0.f, 0.f, 0.f);
    float mA = MASKVAL, mB = MASKVAL, lA = 0.f, lB = 0.f;

    cp_tile(0, 0);
    CP_COMMIT(); CP_WAIT0();
    __syncthreads();

    for (int kt = 0; kt < 32; ++kt) {
        const uint32_t bufoff = (kt & 1) * 49152u;
        if (kt + 1 < 32) { cp_tile(kt + 1, (~kt & 1) * 49152u); CP_COMMIT(); }

        const uint32_t mA0 = g_maskb[rowA*64 + kt*2];
        const uint32_t mA1 = g_maskb[rowA*64 + kt*2 + 1];
        const uint32_t mB0 = g_maskb[rowB*64 + kt*2];
        const uint32_t mB1 = g_maskb[rowB*64 + kt*2 + 1];

        const float4* kf_s = (const float4*)(sma + bufoff);
        const float2* vf_s = (const float2*)(sma + bufoff + 32768);

        // ---- S = Q K^T (3xTF32, pre-scaled) ----
        float4 sacc[8];
#pragma unroll
        for (int nt = 0; nt < 8; ++nt) sacc[nt] = make_float4(0.f, 0.f, 0.f, 0.f);

#pragma unroll
        for (int ks = 0; ks < 8; ++ks) {
            uint32_t qh[4], ql[4];
#pragma unroll
            for (int j = 0; j < 4; ++j) {
                float hi = to_tf32(qf[ks][j]);
                qh[j] = __float_as_uint(hi);
                ql[j] = __float_as_uint(to_tf32(qf[ks][j] - hi));
            }
#pragma unroll
            for (int nt = 0; nt < 8; ++nt) {
                float4 kf = kf_s[(nt*8 + ks)*32 + lane];
                uint32_t bhf[2] = { __float_as_uint(kf.x), __float_as_uint(kf.y) };
                uint32_t blf[2] = { __float_as_uint(kf.z), __float_as_uint(kf.w) };
                mma_tf32(sacc[nt], qh, bhf);
                mma_tf32(sacc[nt], ql, bhf);
                mma_tf32(sacc[nt], qh, blf);
            }
        }

        // ---- mask ----
#pragma unroll
        for (int nt = 0; nt < 8; ++nt) {
            int c0 = nt*8 + 2*tg;
            uint32_t wa = (c0 & 32) ? mA1 : mA0;
            uint32_t wb = (c0 & 32) ? mB1 : mB0;
            int sh = c0 & 31;
            float sx = sacc[nt].x, sy = sacc[nt].y;
            float sz = sacc[nt].z, sw = sacc[nt].w;
            if (!((wa >> sh) & 1))       sx = MASKVAL;
            if (!((wa >> (sh + 1)) & 1)) sy = MASKVAL;
            if (!((wb >> sh) & 1))       sz = MASKVAL;
            if (!((wb >> (sh + 1)) & 1)) sw = MASKVAL;
            sacc[nt] = make_float4(sx, sy, sz, sw);
        }

        // ---- online softmax ----
        float tmA = MASKVAL, tmB = MASKVAL;
#pragma unroll
        for (int nt = 0; nt < 8; ++nt) {
            tmA = fmaxf(tmA, fmaxf(sacc[nt].x, sacc[nt].y));
            tmB = fmaxf(tmB, fmaxf(sacc[nt].z, sacc[nt].w));
        }
        tmA = fmaxf(tmA, __shfl_xor_sync(0xffffffffu, tmA, 1));
        tmA = fmaxf(tmA, __shfl_xor_sync(0xffffffffu, tmA, 2));
        tmB = fmaxf(tmB, __shfl_xor_sync(0xffffffffu, tmB, 1));
        tmB = fmaxf(tmB, __shfl_xor_sync(0xffffffffu, tmB, 2));

        float mnA = fmaxf(mA, tmA), mnB = fmaxf(mB, tmB);
        float aA = __expf(mA - mnA), aB = __expf(mB - mnB);
        mA = mnA; mB = mnB;

        float sumA = 0.f, sumB = 0.f;
#pragma unroll
        for (int nt = 0; nt < 8; ++nt) {
            float px = __expf(sacc[nt].x - mnA);
            float py = __expf(sacc[nt].y - mnA);
            float pz = __expf(sacc[nt].z - mnB);
            float pw = __expf(sacc[nt].w - mnB);
            sumA += px + py; sumB += pz + pw;
            sacc[nt] = make_float4(px, py, pz, pw);
        }
        sumA += __shfl_xor_sync(0xffffffffu, sumA, 1);
        sumA += __shfl_xor_sync(0xffffffffu, sumA, 2);
        sumB += __shfl_xor_sync(0xffffffffu, sumB, 1);
        sumB += __shfl_xor_sync(0xffffffffu, sumB, 2);
        lA = lA*aA + sumA;
        lB = lB*aB + sumB;
#pragma unroll
        for (int nt = 0; nt < 8; ++nt) {
            oacc[nt].x *= aA; oacc[nt].y *= aA;
            oacc[nt].z *= aB; oacc[nt].w *= aB;
        }

        // ---- O += P V ----
        const int srcA = g*4 + (tg >> 1), srcB = srcA + 2;
        const bool odd = tg & 1;
#pragma unroll
        for (int kks = 0; kks < 8; ++kks) {
            float xa = __shfl_sync(0xffffffffu, sacc[kks].x, srcA);
            float ya = __shfl_sync(0xffffffffu, sacc[kks].y, srcA);
            float xb = __shfl_sync(0xffffffffu, sacc[kks].x, srcB);
            float yb = __shfl_sync(0xffffffffu, sacc[kks].y, srcB);
            float za = __shfl_sync(0xffffffffu, sacc[kks].z, srcA);
            float wa = __shfl_sync(0xffffffffu, sacc[kks].w, srcA);
            float zb = __shfl_sync(0xffffffffu, sacc[kks].z, srcB);
            float wb = __shfl_sync(0xffffffffu, sacc[kks].w, srcB);
            uint32_t af[4];
            af[0] = __float_as_uint(to_tf32(odd ? ya : xa));
            af[1] = __float_as_uint(to_tf32(odd ? wa : za));
            af[2] = __float_as_uint(to_tf32(odd ? yb : xb));
            af[3] = __float_as_uint(to_tf32(odd ? wb : zb));
#pragma unroll
            for (int nvt = 0; nvt < 8; ++nvt) {
                float2 v2 = vf_s[(kks*8 + nvt)*32 + lane];
                uint32_t bf[2] = { __float_as_uint(v2.x), __float_as_uint(v2.y) };
                mma_tf32(oacc[nvt], af, bf);
            }
        }
        if (kt + 1 < 32) { CP_WAIT0(); __syncthreads(); }
    }

    // ---- epilogue: normalize + write ctx tf32-rounded (feeds O-GEMM) ----
    const float invA = 1.f / lA, invB = 1.f / lB;
#pragma unroll
    for (int nt = 0; nt < 8; ++nt) {
        int col = h*DHH + nt*8 + 2*tg;
        float2 oA = make_float2(to_tf32(oacc[nt].x * invA), to_tf32(oacc[nt].y * invA));
        float2 oB = make_float2(to_tf32(oacc[nt].z * invB), to_tf32(oacc[nt].w * invB));
        *reinterpret_cast<float2*>(g_ctx + (size_t)(b*SS + rowA)*DD + col) = oA;
        *reinterpret_cast<float2*>(g_ctx + (size_t)(b*SS + rowB)*DD + col) = oB;
    }
}

// ---------------- launch -----------------------------------------------------
extern "C" void kernel_launch(void* const* d_in, const int* in_sizes, int n_in,
                              void* d_out, int out_size) {
    const float* hs = (const float*)d_in[0];
    const void*  mk = d_in[1];
    const float* Wq = (const float*)d_in[2]; const float* bq = (const float*)d_in[3];
    const float* Wk = (const float*)d_in[4]; const float* bk = (const float*)d_in[5];
    const float* Wv = (const float*)d_in[6]; const float* bv = (const float*)d_in[7];
    const float* Wo = (const float*)d_in[8]; const float* bo = (const float*)d_in[9];
    float* out = (float*)d_out;

    static bool attr_set = false;
    if (!attr_set) {
        cudaFuncSetAttribute(gemm_qkv_mma,
                             cudaFuncAttributeMaxDynamicSharedMemorySize, GEMM_SMEM);
        cudaFuncSetAttribute(gemm_o_mma,
                             cudaFuncAttributeMaxDynamicSharedMemorySize, GEMM_SMEM);
        cudaFuncSetAttribute(attn_mma,
                             cudaFuncAttributeMaxDynamicSharedMemorySize, ATT_SMEM);
        attr_set = true;
    }

    detect_mask_kind<<<1, 32>>>((const unsigned int*)mk);
    repack_mask<<<(SS*(SS/32) + 255)/256, 256>>>(mk);
    build_wf_t<<<dim3(8, 16, 4), 256>>>(Wq, Wk, Wv, Wo);
    round_a<<<(MTOT*DD/4 + 255)/256, 256>>>(hs);

    gemm_qkv_mma<<<dim3(8, 64, 3), 256, GEMM_SMEM>>>(bq, bk, bv);
    build_kf_t<<<dim3(16, 64), 256>>>();
    build_vf_t<<<dim3(16, 64), 256>>>();
    attn_mma<<<dim3(SS/128, BB*HH), 256, ATT_SMEM>>>();
    gemm_o_mma<<<dim3(8, 64), 256, GEMM_SMEM>>>(bo, out);
}

// round 12
// speedup vs baseline: 2.7935x; 1.0284x over previous
#include <cuda_runtime.h>
#include <math.h>
#include <stdint.h>

#define BB   4
#define SS   2048
#define DD   1024
#define HH   16
#define DHH  64
#define MTOT (BB*SS)          // 8192
#define MASKVAL (-1e30f)

// ---------------- scratch (static device arrays; no allocation) -------------
__device__ float g_a  [(size_t)MTOT*DD];        // hs pre-rounded to tf32
__device__ float g_q  [(size_t)MTOT*DD];
__device__ float g_ctx[(size_t)MTOT*DD];        // written tf32-rounded by attn
__device__ float4 g_kf[(size_t)64*256*8*32];    // [bh][ntg 256][ks 8][lane] (hi0,hi1,lo0,lo1)
__device__ float2 g_vf[(size_t)64*32*8*8*32];   // [bh][kt][kks][nvt][lane]  (v0,v1) tf32
__device__ float2 g_wf[(size_t)4*128*128*32];   // [z][kg][ntg][lane] (w0,w1) tf32
__device__ uint32_t g_maskb[(size_t)SS*(SS/32)];

__device__ __forceinline__ float to_tf32(float x) {
    float r;
    asm("cvt.rna.tf32.f32 %0, %1;" : "=f"(r) : "f"(x));
    return r;
}
__device__ __forceinline__ uint32_t smem_u32(const void* p) {
    uint32_t a;
    asm("{ .reg .u64 t; cvta.to.shared.u64 t, %1; cvt.u32.u64 %0, t; }"
        : "=r"(a) : "l"(p));
    return a;
}
#define CP16(dst, src) \
    asm volatile("cp.async.cg.shared.global [%0], [%1], 16;" :: "r"(dst), "l"(src))
#define CP_COMMIT() asm volatile("cp.async.commit_group;" ::: "memory")
#define CP_WAIT0()  asm volatile("cp.async.wait_group 0;" ::: "memory")
#define CP_WAIT1()  asm volatile("cp.async.wait_group 1;" ::: "memory")

// m16n8k8 tf32 warp MMA
__device__ __forceinline__ void mma_tf32(float4& d, const uint32_t a[4],
                                         const uint32_t b[2]) {
    asm volatile(
        "mma.sync.aligned.m16n8k8.row.col.f32.tf32.tf32.f32 "
        "{%0,%1,%2,%3}, {%4,%5,%6,%7}, {%8,%9}, {%0,%1,%2,%3};"
        : "+f"(d.x), "+f"(d.y), "+f"(d.z), "+f"(d.w)
        : "r"(a[0]), "r"(a[1]), "r"(a[2]), "r"(a[3]), "r"(b[0]), "r"(b[1]));
}

// ---------------- mask repack with per-block dtype self-detect ---------------
__global__ void repack_mask2(const void* __restrict__ mp) {
    const unsigned int* mw = (const unsigned int*)mp;
    unsigned int probe = mw[threadIdx.x];
    int ok = (probe <= 1u) || (probe == 0x3F800000u);
    int wordlike = __syncthreads_and(ok);

    int idx = blockIdx.x * blockDim.x + threadIdx.x;
    if (idx >= SS * (SS/32)) return;
    int row = idx >> 6, w = idx & 63;
    uint32_t bits = 0;
    if (!wordlike) {
        const uchar4* p = (const uchar4*)mp + (size_t)row*(SS/4) + w*8;
#pragma unroll
        for (int j = 0; j < 8; ++j) {
            uchar4 c = p[j];
            bits |= (uint32_t)(c.x != 0) << (4*j + 0);
            bits |= (uint32_t)(c.y != 0) << (4*j + 1);
            bits |= (uint32_t)(c.z != 0) << (4*j + 2);
            bits |= (uint32_t)(c.w != 0) << (4*j + 3);
        }
    } else {
        const unsigned int* p = mw + (size_t)row*SS + w*32;
#pragma unroll
        for (int j = 0; j < 32; ++j)
            bits |= (uint32_t)(p[j] != 0) << j;
    }
    g_maskb[idx] = bits;
}

// ---------------- prep: weight fragments (blocks 0..511) + round_a (rest) ----
__global__ void prep_kernel(const float* __restrict__ hs,
                            const float* __restrict__ W0, const float* __restrict__ W1,
                            const float* __restrict__ W2, const float* __restrict__ W3) {
    __shared__ float sW[64*132];
    const int t = threadIdx.x;
    if (blockIdx.x < 512) {
        int i = blockIdx.x;
        int bx = i & 7, by = (i >> 3) & 15, z = i >> 7;
        const float* W = (z == 0) ? W0 : (z == 1) ? W1 : (z == 2) ? W2 : W3;
        const int ntg0 = bx * 16, kg0 = by * 8;
        const int n0 = ntg0 * 8, k0 = kg0 * 8;
#pragma unroll
        for (int j = 0; j < 8; ++j) {
            int idx = t + 256*j;
            int r = idx >> 5, c4 = idx & 31;
            float4 v = *reinterpret_cast<const float4*>(W + (size_t)(k0 + r)*DD + n0 + c4*4);
            *reinterpret_cast<float4*>(&sW[r*132 + c4*4]) = v;
        }
        __syncthreads();
#pragma unroll
        for (int j = 0; j < 16; ++j) {
            int idx = t + 256*j;
            int lane = idx & 31, ntgL = (idx >> 5) & 15, kgL = idx >> 9;
            int g = lane >> 2, tg = lane & 3;
            float w0 = sW[(kgL*8 + tg    )*132 + ntgL*8 + g];
            float w1 = sW[(kgL*8 + tg + 4)*132 + ntgL*8 + g];
            g_wf[(((size_t)z*128 + kg0 + kgL)*128 + ntg0 + ntgL)*32 + lane] =
                make_float2(to_tf32(w0), to_tf32(w1));
        }
    } else {
        size_t i = (size_t)(blockIdx.x - 512) * 256 + t;
        i *= 4;
        if (i < (size_t)MTOT*DD) {
            float4 v = *reinterpret_cast<const float4*>(hs + i);
            v.x = to_tf32(v.x); v.y = to_tf32(v.y);
            v.z = to_tf32(v.z); v.w = to_tf32(v.w);
            *reinterpret_cast<float4*>(g_a + i) = v;
        }
    }
}

// ---------------- tf32 mma.sync GEMM, 3-stage cp.async pipeline --------------
// emit: 0 = plain C write, 1 = K-fragment emit, 2 = V-fragment emit
#define GA_SWZ(r, q) ((r)*32 + 4*((q) ^ ((r)&7)))
#define GEMM_SMEM (3*32768)

__device__ __forceinline__ void gemm_mma_body(const float* __restrict__ A,
                                              const float2* __restrict__ Wf,
                                              const float* __restrict__ bias,
                                              float* __restrict__ C,
                                              char* smem, int emit) {
    const int t    = threadIdx.x;
    const int lane = t & 31;
    const int wid  = t >> 5;
    const int wm   = wid >> 1;
    const int wn   = wid & 1;
    const int g    = lane >> 2, tg = lane & 3;
    const int row0 = blockIdx.y * 128;
    const int col0 = blockIdx.x * 128;
    const int srow = t >> 3;
    const int skq  = t & 7;
    const uint32_t sb = smem_u32(smem);

    auto cp_chunk = [&](int c, uint32_t bufoff) {
        const int k0c = c * 32;
#pragma unroll
        for (int cc = 0; cc < 4; ++cc) {
            int r = srow + 32*cc;
            CP16(sb + bufoff + (uint32_t)(GA_SWZ(r, skq)*4),
                 A + (size_t)(row0 + r)*DD + k0c + skq*4);
        }
#pragma unroll
        for (int j = 0; j < 4; ++j) {
            CP16(sb + bufoff + 16384u + (uint32_t)(j*4096 + t*16),
                 (const char*)(Wf + ((size_t)(c*4 + j)*128 + (col0 >> 3))*32) + t*16);
        }
    };

    float4 acc[2][8];
#pragma unroll
    for (int i = 0; i < 2; ++i)
#pragma unroll
        for (int j = 0; j < 8; ++j) acc[i][j] = make_float4(0.f, 0.f, 0.f, 0.f);

    cp_chunk(0, 0);       CP_COMMIT();
    cp_chunk(1, 32768u);  CP_COMMIT();
    CP_WAIT1();
    __syncthreads();

    for (int c = 0; c < 32; ++c) {
        const uint32_t bufoff = (uint32_t)(c % 3) * 32768u;
        if (c + 2 < 32) { cp_chunk(c + 2, (uint32_t)((c + 2) % 3) * 32768u); CP_COMMIT(); }
        const float* As = (const float*)(smem + bufoff);
        const float* Ws = (const float*)(smem + bufoff + 16384);
#pragma unroll
        for (int ks = 0; ks < 4; ++ks) {
            uint32_t af[2][4];
#pragma unroll
            for (int mt = 0; mt < 2; ++mt) {
                int r0 = (wm*2 + mt)*16 + g;
                int o0 = r0*32 + 4*((2*ks)   ^ (r0 & 7)) + tg;
                int o1 = r0*32 + 4*((2*ks+1) ^ (r0 & 7)) + tg;
                af[mt][0] = __float_as_uint(As[o0]);
                af[mt][1] = __float_as_uint(As[o0 + 256]);
                af[mt][2] = __float_as_uint(As[o1]);
                af[mt][3] = __float_as_uint(As[o1 + 256]);
            }
            const float2* wk = (const float2*)(Ws + ks*1024);
#pragma unroll
            for (int nt = 0; nt < 8; ++nt) {
                float2 b2 = wk[(wn*8 + nt)*32 + lane];
                uint32_t bf[2] = { __float_as_uint(b2.x), __float_as_uint(b2.y) };
                mma_tf32(acc[0][nt], af[0], bf);
                mma_tf32(acc[1][nt], af[1], bf);
            }
        }
        if (c + 1 < 32) {
            if (c + 2 < 32) CP_WAIT1(); else CP_WAIT0();
            __syncthreads();
        }
    }

    if (emit == 0) {
#pragma unroll
        for (int mt = 0; mt < 2; ++mt) {
            size_t rA = (size_t)(row0 + (wm*2 + mt)*16 + g);
            size_t rB = rA + 8;
#pragma unroll
            for (int nt = 0; nt < 8; ++nt) {
                int col = col0 + (wn*8 + nt)*8 + tg*2;
                float2 b2 = *reinterpret_cast<const float2*>(bias + col);
                float2 o0 = make_float2(acc[mt][nt].x + b2.x, acc[mt][nt].y + b2.y);
                float2 o1 = make_float2(acc[mt][nt].z + b2.x, acc[mt][nt].w + b2.y);
                *reinterpret_cast<float2*>(C + rA*DD + col) = o0;
                *reinterpret_cast<float2*>(C + rB*DD + col) = o1;
            }
        }
        return;
    }

    // ---- fragment-emit epilogue: stage tile in smem then emit g_kf / g_vf ----
    const int STR = (emit == 1) ? 132 : 136;
    float* sC = (float*)smem;
    __syncthreads();                       // mainloop smem reads done
#pragma unroll
    for (int mt = 0; mt < 2; ++mt) {
        int rAl = (wm*2 + mt)*16 + g;
        int rBl = rAl + 8;
#pragma unroll
        for (int nt = 0; nt < 8; ++nt) {
            int col = (wn*8 + nt)*8 + tg*2;
            float2 b2 = *reinterpret_cast<const float2*>(bias + col0 + col);
            sC[rAl*STR + col]     = acc[mt][nt].x + b2.x;
            sC[rAl*STR + col + 1] = acc[mt][nt].y + b2.y;
            sC[rBl*STR + col]     = acc[mt][nt].z + b2.x;
            sC[rBl*STR + col + 1] = acc[mt][nt].w + b2.y;
        }
    }
    __syncthreads();

    const int b   = row0 >> 11;            // batch
    const int s0l = row0 & 2047;           // seq offset within batch
    const int h0  = col0 >> 6;             // first head in this tile

    if (emit == 1) {                       // K fragments (hi/lo packed)
#pragma unroll
        for (int j = 0; j < 32; ++j) {
            int idx = t + 256*j;
            int ln = idx & 31, ks = (idx >> 5) & 7, sg = (idx >> 8) & 15, hh = idx >> 12;
            int gg = ln >> 2, tgg = ln & 3;
            float k0v = sC[(sg*8 + gg)*132 + hh*64 + ks*8 + tgg];
            float k1v = sC[(sg*8 + gg)*132 + hh*64 + ks*8 + tgg + 4];
            float h0v = to_tf32(k0v), h1v = to_tf32(k1v);
            int bh = b*16 + h0 + hh;
            g_kf[(((size_t)bh*256 + (s0l >> 3) + sg)*8 + ks)*32 + ln] =
                make_float4(h0v, h1v, to_tf32(k0v - h0v), to_tf32(k1v - h1v));
        }
    } else {                               // V fragments (tf32)
#pragma unroll
        for (int j = 0; j < 32; ++j) {
            int idx = t + 256*j;
            int ln = idx & 31, nvt = (idx >> 5) & 7, kks = (idx >> 8) & 7;
            int ktL = (idx >> 11) & 1, hh = idx >> 12;
            int gg = ln >> 2, tgg = ln & 3;
            int keyL = ktL*64 + kks*8;
            float v0 = sC[(keyL + tgg    )*136 + hh*64 + nvt*8 + gg];
            float v1 = sC[(keyL + tgg + 4)*136 + hh*64 + nvt*8 + gg];
            int bh = b*16 + h0 + hh;
            g_vf[((((size_t)bh*32 + (s0l >> 6) + ktL)*8 + kks)*8 + nvt)*32 + ln] =
                make_float2(to_tf32(v0), to_tf32(v1));
        }
    }
}

__global__ __launch_bounds__(256, 2) void gemm_qkv_mma(
    const float* __restrict__ bq, const float* __restrict__ bk,
    const float* __restrict__ bv) {
    extern __shared__ char smg[];
    int z = blockIdx.z;
    const float2* Wf  = g_wf + (size_t)z*128*128*32;
    const float* bias = (z == 0) ? bq : (z == 1) ? bk : bv;
    float* C          = (z == 0) ? g_q : nullptr;
    gemm_mma_body(g_a, Wf, bias, C, smg, z);   // z==0 plain, z==1 K-frag, z==2 V-frag
}

__global__ __launch_bounds__(256, 2) void gemm_o_mma(
    const float* __restrict__ bo, float* __restrict__ out) {
    extern __shared__ char smg[];
    gemm_mma_body(g_ctx, g_wf + (size_t)3*128*128*32, bo, out, smg, 0);
}

// ---------------- flash attention: q-tile 128, cp.async double buffer --------
#define ATT_SMEM (2*49152)

__global__ __launch_bounds__(256, 2) void attn_mma() {
    extern __shared__ char sma[];
    const uint32_t sb = smem_u32(sma);

    const int t = threadIdx.x, lane = t & 31, w = t >> 5;
    const int g = lane >> 2, tg = lane & 3;
    const int q0 = blockIdx.x * 128;
    const int bh = blockIdx.y, b = bh >> 4, h = bh & 15;
    const int rowA = q0 + w*16 + g, rowB = rowA + 8;

    // Q resident in fp32, pre-scaled by 1/8 (exact; commutes with tf32 rounding)
    float qf[8][4];
    {
        const float* Qb = g_q + (size_t)(b*SS)*DD + h*DHH;
#pragma unroll
        for (int ks = 0; ks < 8; ++ks) {
            qf[ks][0] = 0.125f * Qb[(size_t)rowA*DD + ks*8 + tg];
            qf[ks][1] = 0.125f * Qb[(size_t)rowB*DD + ks*8 + tg];
            qf[ks][2] = 0.125f * Qb[(size_t)rowA*DD + ks*8 + tg + 4];
            qf[ks][3] = 0.125f * Qb[(size_t)rowB*DD + ks*8 + tg + 4];
        }
    }

    const float4* kf_base = g_kf + (size_t)bh*65536;
    const float4* vf_base = reinterpret_cast<const float4*>(g_vf) + (size_t)bh*32768;

    auto cp_tile = [&](int kt, uint32_t bufoff) {
        const char* srcK = (const char*)(kf_base + (size_t)kt*2048);
        const char* srcV = (const char*)(vf_base + (size_t)kt*1024);
#pragma unroll
        for (int j = 0; j < 8; ++j) {
            int idx = t + 256*j;
            CP16(sb + bufoff + (uint32_t)idx*16, srcK + (size_t)idx*16);
        }
#pragma unroll
        for (int j = 0; j < 4; ++j) {
            int idx = t + 256*j;
            CP16(sb + bufoff + 32768u + (uint32_t)idx*16, srcV + (size_t)idx*16);
        }
    };

    float4 oacc[8];
#pragma unroll
    for (int nt = 0; nt < 8; ++nt) oacc[nt] = make_float4(0.f, 0.f, 0.f, 0.f);
    float mA = MASKVAL, mB = MASKVAL, lA = 0.f, lB = 0.f;

    cp_tile(0, 0);
    CP_COMMIT(); CP_WAIT0();
    __syncthreads();

    for (int kt = 0; kt < 32; ++kt) {
        const uint32_t bufoff = (kt & 1) * 49152u;
        if (kt + 1 < 32) { cp_tile(kt + 1, (~kt & 1) * 49152u); CP_COMMIT(); }

        const uint32_t mA0 = g_maskb[rowA*64 + kt*2];
        const uint32_t mA1 = g_maskb[rowA*64 + kt*2 + 1];
        const uint32_t mB0 = g_maskb[rowB*64 + kt*2];
        const uint32_t mB1 = g_maskb[rowB*64 + kt*2 + 1];

        const float4* kf_s = (const float4*)(sma + bufoff);
        const float2* vf_s = (const float2*)(sma + bufoff + 32768);

        // ---- S = Q K^T (3xTF32, pre-scaled) ----
        float4 sacc[8];
#pragma unroll
        for (int nt = 0; nt < 8; ++nt) sacc[nt] = make_float4(0.f, 0.f, 0.f, 0.f);

#pragma unroll
        for (int ks = 0; ks < 8; ++ks) {
            uint32_t qh[4], ql[4];
#pragma unroll
            for (int j = 0; j < 4; ++j) {
                float hi = to_tf32(qf[ks][j]);
                qh[j] = __float_as_uint(hi);
                ql[j] = __float_as_uint(to_tf32(qf[ks][j] - hi));
            }
#pragma unroll
            for (int nt = 0; nt < 8; ++nt) {
                float4 kf = kf_s[(nt*8 + ks)*32 + lane];
                uint32_t bhf[2] = { __float_as_uint(kf.x), __float_as_uint(kf.y) };
                uint32_t blf[2] = { __float_as_uint(kf.z), __float_as_uint(kf.w) };
                mma_tf32(sacc[nt], qh, bhf);
                mma_tf32(sacc[nt], ql, bhf);
                mma_tf32(sacc[nt], qh, blf);
            }
        }

        // ---- mask ----
#pragma unroll
        for (int nt = 0; nt < 8; ++nt) {
            int c0 = nt*8 + 2*tg;
            uint32_t wa = (c0 & 32) ? mA1 : mA0;
            uint32_t wb = (c0 & 32) ? mB1 : mB0;
            int sh = c0 & 31;
            float sx = sacc[nt].x, sy = sacc[nt].y;
            float sz = sacc[nt].z, sw = sacc[nt].w;
            if (!((wa >> sh) & 1))       sx = MASKVAL;
            if (!((wa >> (sh + 1)) & 1)) sy = MASKVAL;
            if (!((wb >> sh) & 1))       sz = MASKVAL;
            if (!((wb >> (sh + 1)) & 1)) sw = MASKVAL;
            sacc[nt] = make_float4(sx, sy, sz, sw);
        }

        // ---- online softmax ----
        float tmA = MASKVAL, tmB = MASKVAL;
#pragma unroll
        for (int nt = 0; nt < 8; ++nt) {
            tmA = fmaxf(tmA, fmaxf(sacc[nt].x, sacc[nt].y));
            tmB = fmaxf(tmB, fmaxf(sacc[nt].z, sacc[nt].w));
        }
        tmA = fmaxf(tmA, __shfl_xor_sync(0xffffffffu, tmA, 1));
        tmA = fmaxf(tmA, __shfl_xor_sync(0xffffffffu, tmA, 2));
        tmB = fmaxf(tmB, __shfl_xor_sync(0xffffffffu, tmB, 1));
        tmB = fmaxf(tmB, __shfl_xor_sync(0xffffffffu, tmB, 2));

        float mnA = fmaxf(mA, tmA), mnB = fmaxf(mB, tmB);
        float aA = __expf(mA - mnA), aB = __expf(mB - mnB);
        mA = mnA; mB = mnB;

        float sumA = 0.f, sumB = 0.f;
#pragma unroll
        for (int nt = 0; nt < 8; ++nt) {
            float px = __expf(sacc[nt].x - mnA);
            float py = __expf(sacc[nt].y - mnA);
            float pz = __expf(sacc[nt].z - mnB);
            float pw = __expf(sacc[nt].w - mnB);
            sumA += px + py; sumB += pz + pw;
            sacc[nt] = make_float4(px, py, pz, pw);
        }
        sumA += __shfl_xor_sync(0xffffffffu, sumA, 1);
        sumA += __shfl_xor_sync(0xffffffffu, sumA, 2);
        sumB += __shfl_xor_sync(0xffffffffu, sumB, 1);
        sumB += __shfl_xor_sync(0xffffffffu, sumB, 2);
        lA = lA*aA + sumA;
        lB = lB*aB + sumB;
#pragma unroll
        for (int nt = 0; nt < 8; ++nt) {
            oacc[nt].x *= aA; oacc[nt].y *= aA;
            oacc[nt].z *= aB; oacc[nt].w *= aB;
        }

        // ---- O += P V ----
        const int srcA = g*4 + (tg >> 1), srcB = srcA + 2;
        const bool odd = tg & 1;
#pragma unroll
        for (int kks = 0; kks < 8; ++kks) {
            float xa = __shfl_sync(0xffffffffu, sacc[kks].x, srcA);
            float ya = __shfl_sync(0xffffffffu, sacc[kks].y, srcA);
            float xb = __shfl_sync(0xffffffffu, sacc[kks].x, srcB);
            float yb = __shfl_sync(0xffffffffu, sacc[kks].y, srcB);
            float za = __shfl_sync(0xffffffffu, sacc[kks].z, srcA);
            float wa = __shfl_sync(0xffffffffu, sacc[kks].w, srcA);
            float zb = __shfl_sync(0xffffffffu, sacc[kks].z, srcB);
            float wb = __shfl_sync(0xffffffffu, sacc[kks].w, srcB);
            uint32_t af[4];
            af[0] = __float_as_uint(to_tf32(odd ? ya : xa));
            af[1] = __float_as_uint(to_tf32(odd ? wa : za));
            af[2] = __float_as_uint(to_tf32(odd ? yb : xb));
            af[3] = __float_as_uint(to_tf32(odd ? wb : zb));
#pragma unroll
            for (int nvt = 0; nvt < 8; ++nvt) {
                float2 v2 = vf_s[(kks*8 + nvt)*32 + lane];
                uint32_t bf[2] = { __float_as_uint(v2.x), __float_as_uint(v2.y) };
                mma_tf32(oacc[nvt], af, bf);
            }
        }
        if (kt + 1 < 32) { CP_WAIT0(); __syncthreads(); }
    }

    // ---- epilogue: normalize + write ctx tf32-rounded (feeds O-GEMM) ----
    const float invA = 1.f / lA, invB = 1.f / lB;
#pragma unroll
    for (int nt = 0; nt < 8; ++nt) {
        int col = h*DHH + nt*8 + 2*tg;
        float2 oA = make_float2(to_tf32(oacc[nt].x * invA), to_tf32(oacc[nt].y * invA));
        float2 oB = make_float2(to_tf32(oacc[nt].z * invB), to_tf32(oacc[nt].w * invB));
        *reinterpret_cast<float2*>(g_ctx + (size_t)(b*SS + rowA)*DD + col) = oA;
        *reinterpret_cast<float2*>(g_ctx + (size_t)(b*SS + rowB)*DD + col) = oB;
    }
}

// ---------------- launch -----------------------------------------------------
extern "C" void kernel_launch(void* const* d_in, const int* in_sizes, int n_in,
                              void* d_out, int out_size) {
    const float* hs = (const float*)d_in[0];
    const void*  mk = d_in[1];
    const float* Wq = (const float*)d_in[2]; const float* bq = (const float*)d_in[3];
    const float* Wk = (const float*)d_in[4]; const float* bk = (const float*)d_in[5];
    const float* Wv = (const float*)d_in[6]; const float* bv = (const float*)d_in[7];
    const float* Wo = (const float*)d_in[8]; const float* bo = (const float*)d_in[9];
    float* out = (float*)d_out;

    static bool attr_set = false;
    if (!attr_set) {
        cudaFuncSetAttribute(gemm_qkv_mma,
                             cudaFuncAttributeMaxDynamicSharedMemorySize, GEMM_SMEM);
        cudaFuncSetAttribute(gemm_o_mma,
                             cudaFuncAttributeMaxDynamicSharedMemorySize, GEMM_SMEM);
        cudaFuncSetAttribute(attn_mma,
                             cudaFuncAttributeMaxDynamicSharedMemorySize, ATT_SMEM);
        attr_set = true;
    }

    repack_mask2<<<(SS*(SS/32) + 255)/256, 256>>>(mk);                       // #1
    prep_kernel<<<512 + MTOT*DD/4/256, 256>>>(hs, Wq, Wk, Wv, Wo);           // #2
    gemm_qkv_mma<<<dim3(8, 64, 3), 256, GEMM_SMEM>>>(bq, bk, bv);            // #3
    attn_mma<<<dim3(SS/128, BB*HH), 256, ATT_SMEM>>>();                      // #4 (profiled)
    gemm_o_mma<<<dim3(8, 64), 256, GEMM_SMEM>>>(bo, out);                    // #5
}

// round 13
// speedup vs baseline: 4.8467x; 1.7350x over previous
#include <cuda_runtime.h>
#include <cuda_fp16.h>
#include <math.h>
#include <stdint.h>

#define BB   4
#define SS   2048
#define DD   1024
#define HH   16
#define DHH  64
#define MTOT (BB*SS)          // 8192
#define MASKVAL (-1e30f)

// ---------------- scratch (static device arrays; no allocation) -------------
__device__ __half g_ah [(size_t)MTOT*DD];        // hs as fp16
__device__ float  g_q  [(size_t)MTOT*DD];        // Q fp32 (needed for hi/lo split)
__device__ __half g_ctxh[(size_t)MTOT*DD];       // attn output fp16 (feeds O-GEMM)
__device__ uint4  g_kfh[(size_t)64*256*4*32];    // [bh][ntg][dhc][lane] {khi0,khi1,klo0,klo1}
__device__ uint2  g_vfh[(size_t)64*32*4*8*32];   // [bh][kt][kc][nvt][lane] {b0,b1}
__device__ uint2  g_wfh[(size_t)4*64*128*32];    // [z][kg][ntg][lane] b-frags fp16
__device__ uint32_t g_maskb[(size_t)SS*(SS/32)];

__device__ __forceinline__ uint32_t smem_u32(const void* p) {
    uint32_t a;
    asm("{ .reg .u64 t; cvta.to.shared.u64 t, %1; cvt.u32.u64 %0, t; }"
        : "=r"(a) : "l"(p));
    return a;
}
// pack two fp32 -> fp16x2 {lo, hi}
__device__ __forceinline__ uint32_t pack_f16x2(float lo, float hi) {
    uint32_t r;
    asm("cvt.rn.f16x2.f32 %0, %1, %2;" : "=r"(r) : "f"(hi), "f"(lo));
    return r;
}
__device__ __forceinline__ float f16_res(float x) {
    return x - __half2float(__float2half_rn(x));
}
#define CP16(dst, src) \
    asm volatile("cp.async.cg.shared.global [%0], [%1], 16;" :: "r"(dst), "l"(src))
#define CP_COMMIT() asm volatile("cp.async.commit_group;" ::: "memory")
#define CP_WAIT0()  asm volatile("cp.async.wait_group 0;" ::: "memory")
#define CP_WAIT1()  asm volatile("cp.async.wait_group 1;" ::: "memory")

// m16n8k16 fp16 warp MMA, fp32 accum
__device__ __forceinline__ void mma_f16(float4& d, const uint32_t a[4],
                                        const uint32_t b0, const uint32_t b1) {
    asm volatile(
        "mma.sync.aligned.m16n8k16.row.col.f32.f16.f16.f32 "
        "{%0,%1,%2,%3}, {%4,%5,%6,%7}, {%8,%9}, {%0,%1,%2,%3};"
        : "+f"(d.x), "+f"(d.y), "+f"(d.z), "+f"(d.w)
        : "r"(a[0]), "r"(a[1]), "r"(a[2]), "r"(a[3]), "r"(b0), "r"(b1));
}

// ---------------- mask repack with per-block dtype self-detect ---------------
__global__ void repack_mask2(const void* __restrict__ mp) {
    const unsigned int* mw = (const unsigned int*)mp;
    unsigned int probe = mw[threadIdx.x];
    int ok = (probe <= 1u) || (probe == 0x3F800000u);
    int wordlike = __syncthreads_and(ok);

    int idx = blockIdx.x * blockDim.x + threadIdx.x;
    if (idx >= SS * (SS/32)) return;
    int row = idx >> 6, w = idx & 63;
    uint32_t bits = 0;
    if (!wordlike) {
        const uchar4* p = (const uchar4*)mp + (size_t)row*(SS/4) + w*8;
#pragma unroll
        for (int j = 0; j < 8; ++j) {
            uchar4 c = p[j];
            bits |= (uint32_t)(c.x != 0) << (4*j + 0);
            bits |= (uint32_t)(c.y != 0) << (4*j + 1);
            bits |= (uint32_t)(c.z != 0) << (4*j + 2);
            bits |= (uint32_t)(c.w != 0) << (4*j + 3);
        }
    } else {
        const unsigned int* p = mw + (size_t)row*SS + w*32;
#pragma unroll
        for (int j = 0; j < 32; ++j)
            bits |= (uint32_t)(p[j] != 0) << j;
    }
    g_maskb[idx] = bits;
}

// ---------------- prep: W b-frags (blocks 0..511) + hs->fp16 (rest) ----------
__global__ void prep_kernel(const float* __restrict__ hs,
                            const float* __restrict__ W0, const float* __restrict__ W1,
                            const float* __restrict__ W2, const float* __restrict__ W3) {
    __shared__ float sW[64*132];
    const int t = threadIdx.x;
    if (blockIdx.x < 512) {
        int i = blockIdx.x;
        int bx = i & 7, by = (i >> 3) & 15, z = i >> 7;
        const float* W = (z == 0) ? W0 : (z == 1) ? W1 : (z == 2) ? W2 : W3;
        const int ntg0 = bx * 16, kg0 = by * 4;
        const int n0 = ntg0 * 8, k0 = by * 64;
#pragma unroll
        for (int j = 0; j < 8; ++j) {
            int idx = t + 256*j;
            int r = idx >> 5, c4 = idx & 31;
            float4 v = *reinterpret_cast<const float4*>(W + (size_t)(k0 + r)*DD + n0 + c4*4);
            *reinterpret_cast<float4*>(&sW[r*132 + c4*4]) = v;
        }
        __syncthreads();
#pragma unroll
        for (int j = 0; j < 8; ++j) {
            int idx = t + 256*j;
            int ln = idx & 31, ntgL = (idx >> 5) & 15, kgL = idx >> 9;   // kgL 0..3
            int gg = ln >> 2, tgg = ln & 3;
            float w00 = sW[(kgL*16 + 2*tgg    )*132 + ntgL*8 + gg];
            float w01 = sW[(kgL*16 + 2*tgg + 1)*132 + ntgL*8 + gg];
            float w08 = sW[(kgL*16 + 2*tgg + 8)*132 + ntgL*8 + gg];
            float w09 = sW[(kgL*16 + 2*tgg + 9)*132 + ntgL*8 + gg];
            uint2 o;
            o.x = pack_f16x2(w00, w01);
            o.y = pack_f16x2(w08, w09);
            g_wfh[(((size_t)z*64 + kg0 + kgL)*128 + ntg0 + ntgL)*32 + ln] = o;
        }
    } else {
        size_t i = ((size_t)(blockIdx.x - 512) * 256 + t) * 4;
        if (i < (size_t)MTOT*DD) {
            float4 v = *reinterpret_cast<const float4*>(hs + i);
            uint2 o;
            o.x = pack_f16x2(v.x, v.y);
            o.y = pack_f16x2(v.z, v.w);
            *reinterpret_cast<uint2*>(g_ah + i) = o;
        }
    }
}

// ---------------- fp16 mma.sync GEMM, 3-stage cp.async pipeline --------------
// CTA 128x128, 8 warps (4m x 2n). Chunk = 32 K (two k16 steps).
// Stage: A fp16 128x32 (stride 80B) = 10240 B, W frags 8192 B -> 18432 B/stage.
#define GSTG_A 10240u
#define GSTG   18432u
#define GEMM_SMEM 69632      // >= 3*GSTG and >= 128*136*4 for emit staging

__device__ __forceinline__ void gemm_mma_body(const __half* __restrict__ Ah,
                                              const uint2* __restrict__ Wfh,
                                              const float* __restrict__ bias,
                                              float* __restrict__ C,
                                              char* smem, int emit) {
    const int t    = threadIdx.x;
    const int lane = t & 31;
    const int wid  = t >> 5;
    const int wm   = wid >> 1;
    const int wn   = wid & 1;
    const int g    = lane >> 2, tg = lane & 3;
    const int row0 = blockIdx.y * 128;
    const int col0 = blockIdx.x * 128;
    const uint32_t sb = smem_u32(smem);

    auto cp_chunk = [&](int c, uint32_t off) {
#pragma unroll
        for (int j = 0; j < 2; ++j) {              // A tile: 512 x 16B
            int idx = t + 256*j;
            int r = idx >> 2, s = idx & 3;
            CP16(sb + off + (uint32_t)(r*80 + s*16),
                 (const char*)(Ah + (size_t)(row0 + r)*DD + c*32) + s*16);
        }
#pragma unroll
        for (int j = 0; j < 2; ++j) {              // W frags: 2 x 4KB
            CP16(sb + off + GSTG_A + (uint32_t)(j*4096 + t*16),
                 (const char*)(Wfh + ((size_t)(c*2 + j)*128 + (col0 >> 3))*32) + t*16);
        }
    };

    float4 acc[2][8];
#pragma unroll
    for (int i = 0; i < 2; ++i)
#pragma unroll
        for (int j = 0; j < 8; ++j) acc[i][j] = make_float4(0.f, 0.f, 0.f, 0.f);

    cp_chunk(0, 0);     CP_COMMIT();
    cp_chunk(1, GSTG);  CP_COMMIT();
    CP_WAIT1();
    __syncthreads();

    for (int c = 0; c < 32; ++c) {
        const uint32_t off = (uint32_t)(c % 3) * GSTG;
        if (c + 2 < 32) { cp_chunk(c + 2, (uint32_t)((c + 2) % 3) * GSTG); CP_COMMIT(); }
        const char* Asb = smem + off;
        const char* Wsb = smem + off + GSTG_A;
#pragma unroll
        for (int kk = 0; kk < 2; ++kk) {
            uint32_t af[2][4];
#pragma unroll
            for (int mt = 0; mt < 2; ++mt) {
                int r = (wm*2 + mt)*16 + g;
                const char* base = Asb + r*80 + kk*32 + 4*tg;
                af[mt][0] = *(const uint32_t*)(base);
                af[mt][1] = *(const uint32_t*)(base + 8*80);
                af[mt][2] = *(const uint32_t*)(base + 16);
                af[mt][3] = *(const uint32_t*)(base + 8*80 + 16);
            }
#pragma unroll
            for (int nt = 0; nt < 8; ++nt) {
                uint2 b2 = *(const uint2*)(Wsb + ((kk*16 + wn*8 + nt)*32 + lane)*8);
                mma_f16(acc[0][nt], af[0], b2.x, b2.y);
                mma_f16(acc[1][nt], af[1], b2.x, b2.y);
            }
        }
        if (c + 1 < 32) {
            if (c + 2 < 32) CP_WAIT1(); else CP_WAIT0();
            __syncthreads();
        }
    }

    if (emit == 0) {
#pragma unroll
        for (int mt = 0; mt < 2; ++mt) {
            size_t rA = (size_t)(row0 + (wm*2 + mt)*16 + g);
            size_t rB = rA + 8;
#pragma unroll
            for (int nt = 0; nt < 8; ++nt) {
                int col = col0 + (wn*8 + nt)*8 + tg*2;
                float2 b2 = *reinterpret_cast<const float2*>(bias + col);
                float2 o0 = make_float2(acc[mt][nt].x + b2.x, acc[mt][nt].y + b2.y);
                float2 o1 = make_float2(acc[mt][nt].z + b2.x, acc[mt][nt].w + b2.y);
                *reinterpret_cast<float2*>(C + rA*DD + col) = o0;
                *reinterpret_cast<float2*>(C + rB*DD + col) = o1;
            }
        }
        return;
    }

    // ---- fragment-emit epilogue: stage fp32 tile, emit fp16 fragments ----
    const int STR = (emit == 1) ? 132 : 136;
    float* sC = (float*)smem;
    __syncthreads();
#pragma unroll
    for (int mt = 0; mt < 2; ++mt) {
        int rAl = (wm*2 + mt)*16 + g;
        int rBl = rAl + 8;
#pragma unroll
        for (int nt = 0; nt < 8; ++nt) {
            int col = (wn*8 + nt)*8 + tg*2;
            float2 b2 = *reinterpret_cast<const float2*>(bias + col0 + col);
            sC[rAl*STR + col]     = acc[mt][nt].x + b2.x;
            sC[rAl*STR + col + 1] = acc[mt][nt].y + b2.y;
            sC[rBl*STR + col]     = acc[mt][nt].z + b2.x;
            sC[rBl*STR + col + 1] = acc[mt][nt].w + b2.y;
        }
    }
    __syncthreads();

    const int b   = row0 >> 11;
    const int s0l = row0 & 2047;
    const int h0  = col0 >> 6;

    if (emit == 1) {                 // K fragments: {khi0,khi1,klo0,klo1}
#pragma unroll
        for (int j = 0; j < 16; ++j) {
            int idx = t + 256*j;
            int ln = idx & 31, dhc = (idx >> 5) & 3, ntgL = (idx >> 7) & 15, hh = (idx >> 11) & 1;
            int gg = ln >> 2, tgg = ln & 3;
            const float* base = sC + (ntgL*8 + gg)*132 + hh*64 + dhc*16 + 2*tgg;
            float k00 = base[0], k01 = base[1], k08 = base[8], k09 = base[9];
            uint4 o;
            o.x = pack_f16x2(k00, k01);
            o.y = pack_f16x2(k08, k09);
            o.z = pack_f16x2(f16_res(k00), f16_res(k01));
            o.w = pack_f16x2(f16_res(k08), f16_res(k09));
            int bh = b*16 + h0 + hh;
            g_kfh[(((size_t)bh*256 + (s0l >> 3) + ntgL)*4 + dhc)*32 + ln] = o;
        }
    } else {                         // V fragments: {b0,b1}
#pragma unroll
        for (int j = 0; j < 16; ++j) {
            int idx = t + 256*j;
            int ln = idx & 31, nvt = (idx >> 5) & 7, kc = (idx >> 8) & 3;
            int ktL = (idx >> 10) & 1, hh = (idx >> 11) & 1;
            int gg = ln >> 2, tgg = ln & 3;
            int kb = ktL*64 + kc*16 + 2*tgg;
            const float* bcol = sC + hh*64 + nvt*8 + gg;
            float v0 = bcol[(size_t)(kb+0)*136], v1 = bcol[(size_t)(kb+1)*136];
            float v8 = bcol[(size_t)(kb+8)*136], v9 = bcol[(size_t)(kb+9)*136];
            uint2 o;
            o.x = pack_f16x2(v0, v1);
            o.y = pack_f16x2(v8, v9);
            int bh = b*16 + h0 + hh;
            g_vfh[((((size_t)bh*32 + (s0l >> 6) + ktL)*4 + kc)*8 + nvt)*32 + ln] = o;
        }
    }
}

__global__ __launch_bounds__(256, 2) void gemm_qkv_mma(
    const float* __restrict__ bq, const float* __restrict__ bk,
    const float* __restrict__ bv) {
    extern __shared__ char smg[];
    int z = blockIdx.z;
    const uint2* Wf   = g_wfh + (size_t)z*64*128*32;
    const float* bias = (z == 0) ? bq : (z == 1) ? bk : bv;
    float* C          = (z == 0) ? g_q : nullptr;
    gemm_mma_body(g_ah, Wf, bias, C, smg, z);
}

__global__ __launch_bounds__(256, 2) void gemm_o_mma(
    const float* __restrict__ bo, float* __restrict__ out) {
    extern __shared__ char smg[];
    gemm_mma_body(g_ctxh, g_wfh + (size_t)3*64*128*32, bo, out, smg, 0);
}

// ---------------- flash attention fp16: q-tile 128, cp.async double buffer ---
// Per tile: kf 16KB + vf 8KB = 24KB; x2 buffers = 48KB.
#define ATT_STAGE 24576
#define ATT_SMEM (2*24576)

__global__ __launch_bounds__(256, 2) void attn_mma() {
    extern __shared__ char sma[];
    const uint32_t sb = smem_u32(sma);

    const int t = threadIdx.x, lane = t & 31, w = t >> 5;
    const int g = lane >> 2, tg = lane & 3;
    const int q0 = blockIdx.x * 128;
    const int bh = blockIdx.y, b = bh >> 4, h = bh & 15;
    const int rowA = q0 + w*16 + g, rowB = rowA + 8;

    // Q fragments hi/lo fp16 (resident, pre-scaled by 1/8)
    uint32_t qh[4][4], ql[4][4];
    {
        const float* Qb = g_q + (size_t)(b*SS)*DD + h*DHH;
#pragma unroll
        for (int dhc = 0; dhc < 4; ++dhc) {
            float2 a0 = *reinterpret_cast<const float2*>(Qb + (size_t)rowA*DD + dhc*16 + 2*tg);
            float2 a8 = *reinterpret_cast<const float2*>(Qb + (size_t)rowA*DD + dhc*16 + 2*tg + 8);
            float2 b0 = *reinterpret_cast<const float2*>(Qb + (size_t)rowB*DD + dhc*16 + 2*tg);
            float2 b8 = *reinterpret_cast<const float2*>(Qb + (size_t)rowB*DD + dhc*16 + 2*tg + 8);
            a0.x *= 0.125f; a0.y *= 0.125f; a8.x *= 0.125f; a8.y *= 0.125f;
            b0.x *= 0.125f; b0.y *= 0.125f; b8.x *= 0.125f; b8.y *= 0.125f;
            qh[dhc][0] = pack_f16x2(a0.x, a0.y);
            qh[dhc][1] = pack_f16x2(b0.x, b0.y);
            qh[dhc][2] = pack_f16x2(a8.x, a8.y);
            qh[dhc][3] = pack_f16x2(b8.x, b8.y);
            ql[dhc][0] = pack_f16x2(f16_res(a0.x), f16_res(a0.y));
            ql[dhc][1] = pack_f16x2(f16_res(b0.x), f16_res(b0.y));
            ql[dhc][2] = pack_f16x2(f16_res(a8.x), f16_res(a8.y));
            ql[dhc][3] = pack_f16x2(f16_res(b8.x), f16_res(b8.y));
        }
    }

    const uint4* kf_base = g_kfh + (size_t)bh*256*4*32;
    const uint2* vf_base = g_vfh + (size_t)bh*32*4*8*32;

    auto cp_tile = [&](int kt, uint32_t off) {
        const char* srcK = (const char*)(kf_base + (size_t)kt*8*4*32);
        const char* srcV = (const char*)(vf_base + (size_t)kt*4*8*32);
#pragma unroll
        for (int j = 0; j < 4; ++j) {
            int idx = t + 256*j;
            CP16(sb + off + (uint32_t)idx*16, srcK + (size_t)idx*16);
        }
#pragma unroll
        for (int j = 0; j < 2; ++j) {
            int idx = t + 256*j;
            CP16(sb + off + 16384u + (uint32_t)idx*16, srcV + (size_t)idx*16);
        }
    };

    float4 oacc[8];
#pragma unroll
    for (int nt = 0; nt < 8; ++nt) oacc[nt] = make_float4(0.f, 0.f, 0.f, 0.f);
    float mA = MASKVAL, mB = MASKVAL, lA = 0.f, lB = 0.f;

    cp_tile(0, 0);
    CP_COMMIT(); CP_WAIT0();
    __syncthreads();

    for (int kt = 0; kt < 32; ++kt) {
        const uint32_t off = (kt & 1) * (uint32_t)ATT_STAGE;
        if (kt + 1 < 32) { cp_tile(kt + 1, (~kt & 1) * (uint32_t)ATT_STAGE); CP_COMMIT(); }

        const uint32_t mA0 = g_maskb[rowA*64 + kt*2];
        const uint32_t mA1 = g_maskb[rowA*64 + kt*2 + 1];
        const uint32_t mB0 = g_maskb[rowB*64 + kt*2];
        const uint32_t mB1 = g_maskb[rowB*64 + kt*2 + 1];

        const uint4* kf_s = (const uint4*)(sma + off);
        const uint2* vf_s = (const uint2*)(sma + off + 16384);

        // ---- S = Q K^T (3-term fp16) ----
        float4 sacc[8];
#pragma unroll
        for (int nt = 0; nt < 8; ++nt) sacc[nt] = make_float4(0.f, 0.f, 0.f, 0.f);

#pragma unroll
        for (int nt = 0; nt < 8; ++nt) {
#pragma unroll
            for (int dhc = 0; dhc < 4; ++dhc) {
                uint4 kf = kf_s[(nt*4 + dhc)*32 + lane];
                mma_f16(sacc[nt], qh[dhc], kf.x, kf.y);   // qh*kh
                mma_f16(sacc[nt], ql[dhc], kf.x, kf.y);   // ql*kh
                mma_f16(sacc[nt], qh[dhc], kf.z, kf.w);   // qh*kl
            }
        }

        // ---- mask ----
#pragma unroll
        for (int nt = 0; nt < 8; ++nt) {
            int c0 = nt*8 + 2*tg;
            uint32_t wa = (c0 & 32) ? mA1 : mA0;
            uint32_t wb = (c0 & 32) ? mB1 : mB0;
            int sh = c0 & 31;
            float sx = sacc[nt].x, sy = sacc[nt].y;
            float sz = sacc[nt].z, sw = sacc[nt].w;
            if (!((wa >> sh) & 1))       sx = MASKVAL;
            if (!((wa >> (sh + 1)) & 1)) sy = MASKVAL;
            if (!((wb >> sh) & 1))       sz = MASKVAL;
            if (!((wb >> (sh + 1)) & 1)) sw = MASKVAL;
            sacc[nt] = make_float4(sx, sy, sz, sw);
        }

        // ---- online softmax ----
        float tmA = MASKVAL, tmB = MASKVAL;
#pragma unroll
        for (int nt = 0; nt < 8; ++nt) {
            tmA = fmaxf(tmA, fmaxf(sacc[nt].x, sacc[nt].y));
            tmB = fmaxf(tmB, fmaxf(sacc[nt].z, sacc[nt].w));
        }
        tmA = fmaxf(tmA, __shfl_xor_sync(0xffffffffu, tmA, 1));
        tmA = fmaxf(tmA, __shfl_xor_sync(0xffffffffu, tmA, 2));
        tmB = fmaxf(tmB, __shfl_xor_sync(0xffffffffu, tmB, 1));
        tmB = fmaxf(tmB, __shfl_xor_sync(0xffffffffu, tmB, 2));

        float mnA = fmaxf(mA, tmA), mnB = fmaxf(mB, tmB);
        float aA = __expf(mA - mnA), aB = __expf(mB - mnB);
        mA = mnA; mB = mnB;

        float sumA = 0.f, sumB = 0.f;
#pragma unroll
        for (int nt = 0; nt < 8; ++nt) {
            float px = __expf(sacc[nt].x - mnA);
            float py = __expf(sacc[nt].y - mnA);
            float pz = __expf(sacc[nt].z - mnB);
            float pw = __expf(sacc[nt].w - mnB);
            sumA += px + py; sumB += pz + pw;
            sacc[nt] = make_float4(px, py, pz, pw);
        }
        sumA += __shfl_xor_sync(0xffffffffu, sumA, 1);
        sumA += __shfl_xor_sync(0xffffffffu, sumA, 2);
        sumB += __shfl_xor_sync(0xffffffffu, sumB, 1);
        sumB += __shfl_xor_sync(0xffffffffu, sumB, 2);
        lA = lA*aA + sumA;
        lB = lB*aB + sumB;
#pragma unroll
        for (int nt = 0; nt < 8; ++nt) {
            oacc[nt].x *= aA; oacc[nt].y *= aA;
            oacc[nt].z *= aB; oacc[nt].w *= aB;
        }

        // ---- O += P V  (A-frags == C-layout: no shuffles, just f16 packs) ----
#pragma unroll
        for (int kc = 0; kc < 4; ++kc) {
            uint32_t af[4];
            af[0] = pack_f16x2(sacc[2*kc].x,   sacc[2*kc].y);
            af[1] = pack_f16x2(sacc[2*kc].z,   sacc[2*kc].w);
            af[2] = pack_f16x2(sacc[2*kc+1].x, sacc[2*kc+1].y);
            af[3] = pack_f16x2(sacc[2*kc+1].z, sacc[2*kc+1].w);
#pragma unroll
            for (int nvt = 0; nvt < 8; ++nvt) {
                uint2 v2 = vf_s[(kc*8 + nvt)*32 + lane];
                mma_f16(oacc[nvt], af, v2.x, v2.y);
            }
        }
        if (kt + 1 < 32) { CP_WAIT0(); __syncthreads(); }
    }

    // ---- epilogue: normalize + write ctx fp16 (feeds O-GEMM) ----
    const float invA = 1.f / lA, invB = 1.f / lB;
#pragma unroll
    for (int nt = 0; nt < 8; ++nt) {
        int col = h*DHH + nt*8 + 2*tg;
        *reinterpret_cast<uint32_t*>(g_ctxh + (size_t)(b*SS + rowA)*DD + col) =
            pack_f16x2(oacc[nt].x * invA, oacc[nt].y * invA);
        *reinterpret_cast<uint32_t*>(g_ctxh + (size_t)(b*SS + rowB)*DD + col) =
            pack_f16x2(oacc[nt].z * invB, oacc[nt].w * invB);
    }
}

// ---------------- launch -----------------------------------------------------
extern "C" void kernel_launch(void* const* d_in, const int* in_sizes, int n_in,
                              void* d_out, int out_size) {
    const float* hs = (const float*)d_in[0];
    const void*  mk = d_in[1];
    const float* Wq = (const float*)d_in[2]; const float* bq = (const float*)d_in[3];
    const float* Wk = (const float*)d_in[4]; const float* bk = (const float*)d_in[5];
    const float* Wv = (const float*)d_in[6]; const float* bv = (const float*)d_in[7];
    const float* Wo = (const float*)d_in[8]; const float* bo = (const float*)d_in[9];
    float* out = (float*)d_out;

    static bool attr_set = false;
    if (!attr_set) {
        cudaFuncSetAttribute(gemm_qkv_mma,
                             cudaFuncAttributeMaxDynamicSharedMemorySize, GEMM_SMEM);
        cudaFuncSetAttribute(gemm_o_mma,
                             cudaFuncAttributeMaxDynamicSharedMemorySize, GEMM_SMEM);
        cudaFuncSetAttribute(attn_mma,
                             cudaFuncAttributeMaxDynamicSharedMemorySize, ATT_SMEM);
        attr_set = true;
    }

    repack_mask2<<<(SS*(SS/32) + 255)/256, 256>>>(mk);                    // #1
    prep_kernel<<<512 + MTOT*DD/1024, 256>>>(hs, Wq, Wk, Wv, Wo);         // #2
    gemm_qkv_mma<<<dim3(8, 64, 3), 256, GEMM_SMEM>>>(bq, bk, bv);         // #3
    attn_mma<<<dim3(SS/128, BB*HH), 256, ATT_SMEM>>>();                   // #4 (profiled)
    gemm_o_mma<<<dim3(8, 64), 256, GEMM_SMEM>>>(bo, out);                 // #5
}

// round 14
// speedup vs baseline: 5.4481x; 1.1241x over previous
#include <cuda_runtime.h>
#include <cuda_fp16.h>
#include <math.h>
#include <stdint.h>

#define BB   4
#define SS   2048
#define DD   1024
#define HH   16
#define DHH  64
#define MTOT (BB*SS)          // 8192
#define MASKVAL (-1e30f)

// ---------------- scratch (static device arrays; no allocation) -------------
__device__ __half g_ah [(size_t)MTOT*DD];        // hs as fp16
__device__ float  g_q  [(size_t)MTOT*DD];        // Q fp32 (needed for hi/lo split)
__device__ __half g_ctxh[(size_t)MTOT*DD];       // attn output fp16 (feeds O-GEMM)
__device__ uint2  g_kfh[(size_t)64*256*4*32];    // [bh][ntg][dhc][lane] {k0,k1} fp16
__device__ uint2  g_vfh[(size_t)64*32*4*8*32];   // [bh][kt][kc][nvt][lane] {b0,b1}
__device__ uint2  g_wfh[(size_t)4*64*128*32];    // [z][kg][ntg][lane] b-frags fp16
__device__ uint32_t g_maskb[(size_t)SS*(SS/32)];

__device__ __forceinline__ uint32_t smem_u32(const void* p) {
    uint32_t a;
    asm("{ .reg .u64 t; cvta.to.shared.u64 t, %1; cvt.u32.u64 %0, t; }"
        : "=r"(a) : "l"(p));
    return a;
}
// pack two fp32 -> fp16x2 {lo, hi}
__device__ __forceinline__ uint32_t pack_f16x2(float lo, float hi) {
    uint32_t r;
    asm("cvt.rn.f16x2.f32 %0, %1, %2;" : "=r"(r) : "f"(hi), "f"(lo));
    return r;
}
__device__ __forceinline__ float f16_res(float x) {
    return x - __half2float(__float2half_rn(x));
}
#define CP16(dst, src) \
    asm volatile("cp.async.cg.shared.global [%0], [%1], 16;" :: "r"(dst), "l"(src))
#define CP_COMMIT() asm volatile("cp.async.commit_group;" ::: "memory")
#define CP_WAIT0()  asm volatile("cp.async.wait_group 0;" ::: "memory")
#define CP_WAIT1()  asm volatile("cp.async.wait_group 1;" ::: "memory")

// m16n8k16 fp16 warp MMA, fp32 accum
__device__ __forceinline__ void mma_f16(float4& d, const uint32_t a[4],
                                        const uint32_t b0, const uint32_t b1) {
    asm volatile(
        "mma.sync.aligned.m16n8k16.row.col.f32.f16.f16.f32 "
        "{%0,%1,%2,%3}, {%4,%5,%6,%7}, {%8,%9}, {%0,%1,%2,%3};"
        : "+f"(d.x), "+f"(d.y), "+f"(d.z), "+f"(d.w)
        : "r"(a[0]), "r"(a[1]), "r"(a[2]), "r"(a[3]), "r"(b0), "r"(b1));
}

// ---------------- mask repack with per-block dtype self-detect ---------------
__global__ void repack_mask2(const void* __restrict__ mp) {
    const unsigned int* mw = (const unsigned int*)mp;
    unsigned int probe = mw[threadIdx.x];
    int ok = (probe <= 1u) || (probe == 0x3F800000u);
    int wordlike = __syncthreads_and(ok);

    int idx = blockIdx.x * blockDim.x + threadIdx.x;
    if (idx >= SS * (SS/32)) return;
    int row = idx >> 6, w = idx & 63;
    uint32_t bits = 0;
    if (!wordlike) {
        const uchar4* p = (const uchar4*)mp + (size_t)row*(SS/4) + w*8;
#pragma unroll
        for (int j = 0; j < 8; ++j) {
            uchar4 c = p[j];
            bits |= (uint32_t)(c.x != 0) << (4*j + 0);
            bits |= (uint32_t)(c.y != 0) << (4*j + 1);
            bits |= (uint32_t)(c.z != 0) << (4*j + 2);
            bits |= (uint32_t)(c.w != 0) << (4*j + 3);
        }
    } else {
        const unsigned int* p = mw + (size_t)row*SS + w*32;
#pragma unroll
        for (int j = 0; j < 32; ++j)
            bits |= (uint32_t)(p[j] != 0) << j;
    }
    g_maskb[idx] = bits;
}

// ---------------- prep: W b-frags (blocks 0..511) + hs->fp16 (rest) ----------
__global__ void prep_kernel(const float* __restrict__ hs,
                            const float* __restrict__ W0, const float* __restrict__ W1,
                            const float* __restrict__ W2, const float* __restrict__ W3) {
    __shared__ float sW[64*132];
    const int t = threadIdx.x;
    if (blockIdx.x < 512) {
        int i = blockIdx.x;
        int bx = i & 7, by = (i >> 3) & 15, z = i >> 7;
        const float* W = (z == 0) ? W0 : (z == 1) ? W1 : (z == 2) ? W2 : W3;
        const int ntg0 = bx * 16, kg0 = by * 4;
        const int n0 = ntg0 * 8, k0 = by * 64;
#pragma unroll
        for (int j = 0; j < 8; ++j) {
            int idx = t + 256*j;
            int r = idx >> 5, c4 = idx & 31;
            float4 v = *reinterpret_cast<const float4*>(W + (size_t)(k0 + r)*DD + n0 + c4*4);
            *reinterpret_cast<float4*>(&sW[r*132 + c4*4]) = v;
        }
        __syncthreads();
#pragma unroll
        for (int j = 0; j < 8; ++j) {
            int idx = t + 256*j;
            int ln = idx & 31, ntgL = (idx >> 5) & 15, kgL = idx >> 9;   // kgL 0..3
            int gg = ln >> 2, tgg = ln & 3;
            float w00 = sW[(kgL*16 + 2*tgg    )*132 + ntgL*8 + gg];
            float w01 = sW[(kgL*16 + 2*tgg + 1)*132 + ntgL*8 + gg];
            float w08 = sW[(kgL*16 + 2*tgg + 8)*132 + ntgL*8 + gg];
            float w09 = sW[(kgL*16 + 2*tgg + 9)*132 + ntgL*8 + gg];
            uint2 o;
            o.x = pack_f16x2(w00, w01);
            o.y = pack_f16x2(w08, w09);
            g_wfh[(((size_t)z*64 + kg0 + kgL)*128 + ntg0 + ntgL)*32 + ln] = o;
        }
    } else {
        size_t i = ((size_t)(blockIdx.x - 512) * 256 + t) * 4;
        if (i < (size_t)MTOT*DD) {
            float4 v = *reinterpret_cast<const float4*>(hs + i);
            uint2 o;
            o.x = pack_f16x2(v.x, v.y);
            o.y = pack_f16x2(v.z, v.w);
            *reinterpret_cast<uint2*>(g_ah + i) = o;
        }
    }
}

// ---------------- fp16 mma.sync GEMM, 3-stage cp.async pipeline --------------
#define GSTG_A 10240u
#define GSTG   18432u
#define GEMM_SMEM 69632

__device__ __forceinline__ void gemm_mma_body(const __half* __restrict__ Ah,
                                              const uint2* __restrict__ Wfh,
                                              const float* __restrict__ bias,
                                              float* __restrict__ C,
                                              char* smem, int emit) {
    const int t    = threadIdx.x;
    const int lane = t & 31;
    const int wid  = t >> 5;
    const int wm   = wid >> 1;
    const int wn   = wid & 1;
    const int g    = lane >> 2, tg = lane & 3;
    const int row0 = blockIdx.y * 128;
    const int col0 = blockIdx.x * 128;
    const uint32_t sb = smem_u32(smem);

    auto cp_chunk = [&](int c, uint32_t off) {
#pragma unroll
        for (int j = 0; j < 2; ++j) {              // A tile: 512 x 16B
            int idx = t + 256*j;
            int r = idx >> 2, s = idx & 3;
            CP16(sb + off + (uint32_t)(r*80 + s*16),
                 (const char*)(Ah + (size_t)(row0 + r)*DD + c*32) + s*16);
        }
#pragma unroll
        for (int j = 0; j < 2; ++j) {              // W frags: 2 x 4KB
            CP16(sb + off + GSTG_A + (uint32_t)(j*4096 + t*16),
                 (const char*)(Wfh + ((size_t)(c*2 + j)*128 + (col0 >> 3))*32) + t*16);
        }
    };

    float4 acc[2][8];
#pragma unroll
    for (int i = 0; i < 2; ++i)
#pragma unroll
        for (int j = 0; j < 8; ++j) acc[i][j] = make_float4(0.f, 0.f, 0.f, 0.f);

    cp_chunk(0, 0);     CP_COMMIT();
    cp_chunk(1, GSTG);  CP_COMMIT();
    CP_WAIT1();
    __syncthreads();

    for (int c = 0; c < 32; ++c) {
        const uint32_t off = (uint32_t)(c % 3) * GSTG;
        if (c + 2 < 32) { cp_chunk(c + 2, (uint32_t)((c + 2) % 3) * GSTG); CP_COMMIT(); }
        const char* Asb = smem + off;
        const char* Wsb = smem + off + GSTG_A;
#pragma unroll
        for (int kk = 0; kk < 2; ++kk) {
            uint32_t af[2][4];
#pragma unroll
            for (int mt = 0; mt < 2; ++mt) {
                int r = (wm*2 + mt)*16 + g;
                const char* base = Asb + r*80 + kk*32 + 4*tg;
                af[mt][0] = *(const uint32_t*)(base);
                af[mt][1] = *(const uint32_t*)(base + 8*80);
                af[mt][2] = *(const uint32_t*)(base + 16);
                af[mt][3] = *(const uint32_t*)(base + 8*80 + 16);
            }
#pragma unroll
            for (int nt = 0; nt < 8; ++nt) {
                uint2 b2 = *(const uint2*)(Wsb + ((kk*16 + wn*8 + nt)*32 + lane)*8);
                mma_f16(acc[0][nt], af[0], b2.x, b2.y);
                mma_f16(acc[1][nt], af[1], b2.x, b2.y);
            }
        }
        if (c + 1 < 32) {
            if (c + 2 < 32) CP_WAIT1(); else CP_WAIT0();
            __syncthreads();
        }
    }

    if (emit == 0) {
#pragma unroll
        for (int mt = 0; mt < 2; ++mt) {
            size_t rA = (size_t)(row0 + (wm*2 + mt)*16 + g);
            size_t rB = rA + 8;
#pragma unroll
            for (int nt = 0; nt < 8; ++nt) {
                int col = col0 + (wn*8 + nt)*8 + tg*2;
                float2 b2 = *reinterpret_cast<const float2*>(bias + col);
                float2 o0 = make_float2(acc[mt][nt].x + b2.x, acc[mt][nt].y + b2.y);
                float2 o1 = make_float2(acc[mt][nt].z + b2.x, acc[mt][nt].w + b2.y);
                *reinterpret_cast<float2*>(C + rA*DD + col) = o0;
                *reinterpret_cast<float2*>(C + rB*DD + col) = o1;
            }
        }
        return;
    }

    // ---- fragment-emit epilogue: stage fp32 tile, emit fp16 fragments ----
    const int STR = (emit == 1) ? 132 : 136;
    float* sC = (float*)smem;
    __syncthreads();
#pragma unroll
    for (int mt = 0; mt < 2; ++mt) {
        int rAl = (wm*2 + mt)*16 + g;
        int rBl = rAl + 8;
#pragma unroll
        for (int nt = 0; nt < 8; ++nt) {
            int col = (wn*8 + nt)*8 + tg*2;
            float2 b2 = *reinterpret_cast<const float2*>(bias + col0 + col);
            sC[rAl*STR + col]     = acc[mt][nt].x + b2.x;
            sC[rAl*STR + col + 1] = acc[mt][nt].y + b2.y;
            sC[rBl*STR + col]     = acc[mt][nt].z + b2.x;
            sC[rBl*STR + col + 1] = acc[mt][nt].w + b2.y;
        }
    }
    __syncthreads();

    const int b   = row0 >> 11;
    const int s0l = row0 & 2047;
    const int h0  = col0 >> 6;

    if (emit == 1) {                 // K fragments: {k0,k1} fp16 (single-rounded)
#pragma unroll
        for (int j = 0; j < 16; ++j) {
            int idx = t + 256*j;
            int ln = idx & 31, dhc = (idx >> 5) & 3, ntgL = (idx >> 7) & 15, hh = (idx >> 11) & 1;
            int gg = ln >> 2, tgg = ln & 3;
            const float* base = sC + (ntgL*8 + gg)*132 + hh*64 + dhc*16 + 2*tgg;
            uint2 o;
            o.x = pack_f16x2(base[0], base[1]);
            o.y = pack_f16x2(base[8], base[9]);
            int bh = b*16 + h0 + hh;
            g_kfh[(((size_t)bh*256 + (s0l >> 3) + ntgL)*4 + dhc)*32 + ln] = o;
        }
    } else {                         // V fragments: {b0,b1}
#pragma unroll
        for (int j = 0; j < 16; ++j) {
            int idx = t + 256*j;
            int ln = idx & 31, nvt = (idx >> 5) & 7, kc = (idx >> 8) & 3;
            int ktL = (idx >> 10) & 1, hh = (idx >> 11) & 1;
            int gg = ln >> 2, tgg = ln & 3;
            int kb = ktL*64 + kc*16 + 2*tgg;
            const float* bcol = sC + hh*64 + nvt*8 + gg;
            float v0 = bcol[(size_t)(kb+0)*136], v1 = bcol[(size_t)(kb+1)*136];
            float v8 = bcol[(size_t)(kb+8)*136], v9 = bcol[(size_t)(kb+9)*136];
            uint2 o;
            o.x = pack_f16x2(v0, v1);
            o.y = pack_f16x2(v8, v9);
            int bh = b*16 + h0 + hh;
            g_vfh[((((size_t)bh*32 + (s0l >> 6) + ktL)*4 + kc)*8 + nvt)*32 + ln] = o;
        }
    }
}

__global__ __launch_bounds__(256, 2) void gemm_qkv_mma(
    const float* __restrict__ bq, const float* __restrict__ bk,
    const float* __restrict__ bv) {
    extern __shared__ char smg[];
    int z = blockIdx.z;
    const uint2* Wf   = g_wfh + (size_t)z*64*128*32;
    const float* bias = (z == 0) ? bq : (z == 1) ? bk : bv;
    float* C          = (z == 0) ? g_q : nullptr;
    gemm_mma_body(g_ah, Wf, bias, C, smg, z);
}

__global__ __launch_bounds__(256, 2) void gemm_o_mma(
    const float* __restrict__ bo, float* __restrict__ out) {
    extern __shared__ char smg[];
    gemm_mma_body(g_ctxh, g_wfh + (size_t)3*64*128*32, bo, out, smg, 0);
}

// ---------------- flash attention fp16: q-tile 128, cp.async double buffer ---
// Per tile: kf 8KB + vf 8KB = 16KB; x2 buffers = 32KB.
#define ATT_STAGE 16384
#define ATT_SMEM (2*16384)

__global__ __launch_bounds__(256, 2) void attn_mma() {
    extern __shared__ char sma[];
    const uint32_t sb = smem_u32(sma);

    const int t = threadIdx.x, lane = t & 31, w = t >> 5;
    const int g = lane >> 2, tg = lane & 3;
    const int q0 = blockIdx.x * 128;
    const int bh = blockIdx.y, b = bh >> 4, h = bh & 15;
    const int rowA = q0 + w*16 + g, rowB = rowA + 8;

    // Q fragments hi/lo fp16 (resident, pre-scaled by 1/8)
    uint32_t qh[4][4], ql[4][4];
    {
        const float* Qb = g_q + (size_t)(b*SS)*DD + h*DHH;
#pragma unroll
        for (int dhc = 0; dhc < 4; ++dhc) {
            float2 a0 = *reinterpret_cast<const float2*>(Qb + (size_t)rowA*DD + dhc*16 + 2*tg);
            float2 a8 = *reinterpret_cast<const float2*>(Qb + (size_t)rowA*DD + dhc*16 + 2*tg + 8);
            float2 b0 = *reinterpret_cast<const float2*>(Qb + (size_t)rowB*DD + dhc*16 + 2*tg);
            float2 b8 = *reinterpret_cast<const float2*>(Qb + (size_t)rowB*DD + dhc*16 + 2*tg + 8);
            a0.x *= 0.125f; a0.y *= 0.125f; a8.x *= 0.125f; a8.y *= 0.125f;
            b0.x *= 0.125f; b0.y *= 0.125f; b8.x *= 0.125f; b8.y *= 0.125f;
            qh[dhc][0] = pack_f16x2(a0.x, a0.y);
            qh[dhc][1] = pack_f16x2(b0.x, b0.y);
            qh[dhc][2] = pack_f16x2(a8.x, a8.y);
            qh[dhc][3] = pack_f16x2(b8.x, b8.y);
            ql[dhc][0] = pack_f16x2(f16_res(a0.x), f16_res(a0.y));
            ql[dhc][1] = pack_f16x2(f16_res(b0.x), f16_res(b0.y));
            ql[dhc][2] = pack_f16x2(f16_res(a8.x), f16_res(a8.y));
            ql[dhc][3] = pack_f16x2(f16_res(b8.x), f16_res(b8.y));
        }
    }

    const uint2* kf_base = g_kfh + (size_t)bh*256*4*32;
    const uint2* vf_base = g_vfh + (size_t)bh*32*4*8*32;

    auto cp_tile = [&](int kt, uint32_t off) {
        const char* srcK = (const char*)(kf_base + (size_t)kt*8*4*32);
        const char* srcV = (const char*)(vf_base + (size_t)kt*4*8*32);
#pragma unroll
        for (int j = 0; j < 2; ++j) {
            int idx = t + 256*j;
            CP16(sb + off + (uint32_t)idx*16, srcK + (size_t)idx*16);
        }
#pragma unroll
        for (int j = 0; j < 2; ++j) {
            int idx = t + 256*j;
            CP16(sb + off + 8192u + (uint32_t)idx*16, srcV + (size_t)idx*16);
        }
    };

    float4 oacc[8];
#pragma unroll
    for (int nt = 0; nt < 8; ++nt) oacc[nt] = make_float4(0.f, 0.f, 0.f, 0.f);
    float mA = MASKVAL, mB = MASKVAL, lA = 0.f, lB = 0.f;

    cp_tile(0, 0);
    CP_COMMIT(); CP_WAIT0();
    __syncthreads();

    for (int kt = 0; kt < 32; ++kt) {
        const uint32_t off = (kt & 1) * (uint32_t)ATT_STAGE;
        if (kt + 1 < 32) { cp_tile(kt + 1, (~kt & 1) * (uint32_t)ATT_STAGE); CP_COMMIT(); }

        const uint32_t mA0 = g_maskb[rowA*64 + kt*2];
        const uint32_t mA1 = g_maskb[rowA*64 + kt*2 + 1];
        const uint32_t mB0 = g_maskb[rowB*64 + kt*2];
        const uint32_t mB1 = g_maskb[rowB*64 + kt*2 + 1];

        const uint2* kf_s = (const uint2*)(sma + off);
        const uint2* vf_s = (const uint2*)(sma + off + 8192);

        // ---- S = Q K^T (2-term fp16: qh*k + ql*k) ----
        float4 sacc[8];
#pragma unroll
        for (int nt = 0; nt < 8; ++nt) sacc[nt] = make_float4(0.f, 0.f, 0.f, 0.f);

#pragma unroll
        for (int nt = 0; nt < 8; ++nt) {
#pragma unroll
            for (int dhc = 0; dhc < 4; ++dhc) {
                uint2 kf = kf_s[(nt*4 + dhc)*32 + lane];
                mma_f16(sacc[nt], qh[dhc], kf.x, kf.y);
                mma_f16(sacc[nt], ql[dhc], kf.x, kf.y);
            }
        }

        // ---- mask ----
#pragma unroll
        for (int nt = 0; nt < 8; ++nt) {
            int c0 = nt*8 + 2*tg;
            uint32_t wa = (c0 & 32) ? mA1 : mA0;
            uint32_t wb = (c0 & 32) ? mB1 : mB0;
            int sh = c0 & 31;
            float sx = sacc[nt].x, sy = sacc[nt].y;
            float sz = sacc[nt].z, sw = sacc[nt].w;
            if (!((wa >> sh) & 1))       sx = MASKVAL;
            if (!((wa >> (sh + 1)) & 1)) sy = MASKVAL;
            if (!((wb >> sh) & 1))       sz = MASKVAL;
            if (!((wb >> (sh + 1)) & 1)) sw = MASKVAL;
            sacc[nt] = make_float4(sx, sy, sz, sw);
        }

        // ---- online softmax ----
        float tmA = MASKVAL, tmB = MASKVAL;
#pragma unroll
        for (int nt = 0; nt < 8; ++nt) {
            tmA = fmaxf(tmA, fmaxf(sacc[nt].x, sacc[nt].y));
            tmB = fmaxf(tmB, fmaxf(sacc[nt].z, sacc[nt].w));
        }
        tmA = fmaxf(tmA, __shfl_xor_sync(0xffffffffu, tmA, 1));
        tmA = fmaxf(tmA, __shfl_xor_sync(0xffffffffu, tmA, 2));
        tmB = fmaxf(tmB, __shfl_xor_sync(0xffffffffu, tmB, 1));
        tmB = fmaxf(tmB, __shfl_xor_sync(0xffffffffu, tmB, 2));

        float mnA = fmaxf(mA, tmA), mnB = fmaxf(mB, tmB);
        float aA = __expf(mA - mnA), aB = __expf(mB - mnB);
        mA = mnA; mB = mnB;

        float sumA = 0.f, sumB = 0.f;
#pragma unroll
        for (int nt = 0; nt < 8; ++nt) {
            float px = __expf(sacc[nt].x - mnA);
            float py = __expf(sacc[nt].y - mnA);
            float pz = __expf(sacc[nt].z - mnB);
            float pw = __expf(sacc[nt].w - mnB);
            sumA += px + py; sumB += pz + pw;
            sacc[nt] = make_float4(px, py, pz, pw);
        }
        sumA += __shfl_xor_sync(0xffffffffu, sumA, 1);
        sumA += __shfl_xor_sync(0xffffffffu, sumA, 2);
        sumB += __shfl_xor_sync(0xffffffffu, sumB, 1);
        sumB += __shfl_xor_sync(0xffffffffu, sumB, 2);
        lA = lA*aA + sumA;
        lB = lB*aB + sumB;
#pragma unroll
        for (int nt = 0; nt < 8; ++nt) {
            oacc[nt].x *= aA; oacc[nt].y *= aA;
            oacc[nt].z *= aB; oacc[nt].w *= aB;
        }

        // ---- O += P V  (A-frags == C-layout: no shuffles, just f16 packs) ----
#pragma unroll
        for (int kc = 0; kc < 4; ++kc) {
            uint32_t af[4];
            af[0] = pack_f16x2(sacc[2*kc].x,   sacc[2*kc].y);
            af[1] = pack_f16x2(sacc[2*kc].z,   sacc[2*kc].w);
            af[2] = pack_f16x2(sacc[2*kc+1].x, sacc[2*kc+1].y);
            af[3] = pack_f16x2(sacc[2*kc+1].z, sacc[2*kc+1].w);
#pragma unroll
            for (int nvt = 0; nvt < 8; ++nvt) {
                uint2 v2 = vf_s[(kc*8 + nvt)*32 + lane];
                mma_f16(oacc[nvt], af, v2.x, v2.y);
            }
        }
        if (kt + 1 < 32) { CP_WAIT0(); __syncthreads(); }
    }

    // ---- epilogue: normalize + write ctx fp16 (feeds O-GEMM) ----
    const float invA = 1.f / lA, invB = 1.f / lB;
#pragma unroll
    for (int nt = 0; nt < 8; ++nt) {
        int col = h*DHH + nt*8 + 2*tg;
        *reinterpret_cast<uint32_t*>(g_ctxh + (size_t)(b*SS + rowA)*DD + col) =
            pack_f16x2(oacc[nt].x * invA, oacc[nt].y * invA);
        *reinterpret_cast<uint32_t*>(g_ctxh + (size_t)(b*SS + rowB)*DD + col) =
            pack_f16x2(oacc[nt].z * invB, oacc[nt].w * invB);
    }
}

// ---------------- launch -----------------------------------------------------
extern "C" void kernel_launch(void* const* d_in, const int* in_sizes, int n_in,
                              void* d_out, int out_size) {
    const float* hs = (const float*)d_in[0];
    const void*  mk = d_in[1];
    const float* Wq = (const float*)d_in[2]; const float* bq = (const float*)d_in[3];
    const float* Wk = (const float*)d_in[4]; const float* bk = (const float*)d_in[5];
    const float* Wv = (const float*)d_in[6]; const float* bv = (const float*)d_in[7];
    const float* Wo = (const float*)d_in[8]; const float* bo = (const float*)d_in[9];
    float* out = (float*)d_out;

    static bool attr_set = false;
    if (!attr_set) {
        cudaFuncSetAttribute(gemm_qkv_mma,
                             cudaFuncAttributeMaxDynamicSharedMemorySize, GEMM_SMEM);
        cudaFuncSetAttribute(gemm_o_mma,
                             cudaFuncAttributeMaxDynamicSharedMemorySize, GEMM_SMEM);
        cudaFuncSetAttribute(attn_mma,
                             cudaFuncAttributeMaxDynamicSharedMemorySize, ATT_SMEM);
        attr_set = true;
    }

    repack_mask2<<<(SS*(SS/32) + 255)/256, 256>>>(mk);                    // #1
    prep_kernel<<<512 + MTOT*DD/1024, 256>>>(hs, Wq, Wk, Wv, Wo);         // #2
    gemm_qkv_mma<<<dim3(8, 64, 3), 256, GEMM_SMEM>>>(bq, bk, bv);         // #3
    attn_mma<<<dim3(SS/128, BB*HH), 256, ATT_SMEM>>>();                   // #4 (profiled)
    gemm_o_mma<<<dim3(8, 64), 256, GEMM_SMEM>>>(bo, out);                 // #5
}

// round 15
// speedup vs baseline: 5.9585x; 1.0937x over previous
#include <cuda_runtime.h>
#include <cuda_fp16.h>
#include <math.h>
#include <stdint.h>

#define BB   4
#define SS   2048
#define DD   1024
#define HH   16
#define DHH  64
#define MTOT (BB*SS)          // 8192
#define MASKVAL (-1e30f)

// ---------------- scratch (static device arrays; no allocation) -------------
__device__ __half g_ah [(size_t)MTOT*DD];        // hs as fp16
__device__ float  g_q  [(size_t)MTOT*DD];        // Q fp32
__device__ __half g_ctxh[(size_t)MTOT*DD];       // attn output fp16 (feeds O-GEMM)
__device__ uint2  g_kfh[(size_t)64*256*4*32];    // [bh][ntg][dhc][lane] {k0,k1} fp16
__device__ uint2  g_vfh[(size_t)64*32*4*8*32];   // [bh][kt][kc][nvt][lane] {b0,b1}
__device__ uint2  g_wfh[(size_t)4*64*128*32];    // [z][kg][ntg][lane] b-frags fp16
__device__ uint32_t g_maskb[(size_t)SS*(SS/32)];

__device__ __forceinline__ uint32_t smem_u32(const void* p) {
    uint32_t a;
    asm("{ .reg .u64 t; cvta.to.shared.u64 t, %1; cvt.u32.u64 %0, t; }"
        : "=r"(a) : "l"(p));
    return a;
}
// pack two fp32 -> fp16x2 {lo, hi}
__device__ __forceinline__ uint32_t pack_f16x2(float lo, float hi) {
    uint32_t r;
    asm("cvt.rn.f16x2.f32 %0, %1, %2;" : "=r"(r) : "f"(hi), "f"(lo));
    return r;
}
#define CP16(dst, src) \
    asm volatile("cp.async.cg.shared.global [%0], [%1], 16;" :: "r"(dst), "l"(src))
#define CP_COMMIT() asm volatile("cp.async.commit_group;" ::: "memory")
#define CP_WAIT0()  asm volatile("cp.async.wait_group 0;" ::: "memory")
#define CP_WAIT1()  asm volatile("cp.async.wait_group 1;" ::: "memory")

// m16n8k16 fp16 warp MMA, fp32 accum
__device__ __forceinline__ void mma_f16(float4& d, const uint32_t a[4],
                                        const uint32_t b0, const uint32_t b1) {
    asm volatile(
        "mma.sync.aligned.m16n8k16.row.col.f32.f16.f16.f32 "
        "{%0,%1,%2,%3}, {%4,%5,%6,%7}, {%8,%9}, {%0,%1,%2,%3};"
        : "+f"(d.x), "+f"(d.y), "+f"(d.z), "+f"(d.w)
        : "r"(a[0]), "r"(a[1]), "r"(a[2]), "r"(a[3]), "r"(b0), "r"(b1));
}

// ---------------- mask repack with per-block dtype self-detect ---------------
__global__ void repack_mask2(const void* __restrict__ mp) {
    const unsigned int* mw = (const unsigned int*)mp;
    unsigned int probe = mw[threadIdx.x];
    int ok = (probe <= 1u) || (probe == 0x3F800000u);
    int wordlike = __syncthreads_and(ok);

    int idx = blockIdx.x * blockDim.x + threadIdx.x;
    if (idx >= SS * (SS/32)) return;
    int row = idx >> 6, w = idx & 63;
    uint32_t bits = 0;
    if (!wordlike) {
        const uchar4* p = (const uchar4*)mp + (size_t)row*(SS/4) + w*8;
#pragma unroll
        for (int j = 0; j < 8; ++j) {
            uchar4 c = p[j];
            bits |= (uint32_t)(c.x != 0) << (4*j + 0);
            bits |= (uint32_t)(c.y != 0) << (4*j + 1);
            bits |= (uint32_t)(c.z != 0) << (4*j + 2);
            bits |= (uint32_t)(c.w != 0) << (4*j + 3);
        }
    } else {
        const unsigned int* p = mw + (size_t)row*SS + w*32;
#pragma unroll
        for (int j = 0; j < 32; ++j)
            bits |= (uint32_t)(p[j] != 0) << j;
    }
    g_maskb[idx] = bits;
}

// ---------------- prep: W b-frags (blocks 0..511) + hs->fp16 (rest) ----------
__global__ void prep_kernel(const float* __restrict__ hs,
                            const float* __restrict__ W0, const float* __restrict__ W1,
                            const float* __restrict__ W2, const float* __restrict__ W3) {
    __shared__ float sW[64*132];
    const int t = threadIdx.x;
    if (blockIdx.x < 512) {
        int i = blockIdx.x;
        int bx = i & 7, by = (i >> 3) & 15, z = i >> 7;
        const float* W = (z == 0) ? W0 : (z == 1) ? W1 : (z == 2) ? W2 : W3;
        const int ntg0 = bx * 16, kg0 = by * 4;
        const int n0 = ntg0 * 8, k0 = by * 64;
#pragma unroll
        for (int j = 0; j < 8; ++j) {
            int idx = t + 256*j;
            int r = idx >> 5, c4 = idx & 31;
            float4 v = *reinterpret_cast<const float4*>(W + (size_t)(k0 + r)*DD + n0 + c4*4);
            *reinterpret_cast<float4*>(&sW[r*132 + c4*4]) = v;
        }
        __syncthreads();
#pragma unroll
        for (int j = 0; j < 8; ++j) {
            int idx = t + 256*j;
            int ln = idx & 31, ntgL = (idx >> 5) & 15, kgL = idx >> 9;
            int gg = ln >> 2, tgg = ln & 3;
            float w00 = sW[(kgL*16 + 2*tgg    )*132 + ntgL*8 + gg];
            float w01 = sW[(kgL*16 + 2*tgg + 1)*132 + ntgL*8 + gg];
            float w08 = sW[(kgL*16 + 2*tgg + 8)*132 + ntgL*8 + gg];
            float w09 = sW[(kgL*16 + 2*tgg + 9)*132 + ntgL*8 + gg];
            uint2 o;
            o.x = pack_f16x2(w00, w01);
            o.y = pack_f16x2(w08, w09);
            g_wfh[(((size_t)z*64 + kg0 + kgL)*128 + ntg0 + ntgL)*32 + ln] = o;
        }
    } else {
        size_t i = ((size_t)(blockIdx.x - 512) * 256 + t) * 4;
        if (i < (size_t)MTOT*DD) {
            float4 v = *reinterpret_cast<const float4*>(hs + i);
            uint2 o;
            o.x = pack_f16x2(v.x, v.y);
            o.y = pack_f16x2(v.z, v.w);
            *reinterpret_cast<uint2*>(g_ah + i) = o;
        }
    }
}

// ---------------- fp16 mma.sync GEMM, 3-stage cp.async pipeline --------------
#define GSTG_A 10240u
#define GSTG   18432u
#define GEMM_SMEM 69632

__device__ __forceinline__ void gemm_mma_body(const __half* __restrict__ Ah,
                                              const uint2* __restrict__ Wfh,
                                              const float* __restrict__ bias,
                                              float* __restrict__ C,
                                              char* smem, int emit) {
    const int t    = threadIdx.x;
    const int lane = t & 31;
    const int wid  = t >> 5;
    const int wm   = wid >> 1;
    const int wn   = wid & 1;
    const int g    = lane >> 2, tg = lane & 3;
    const int row0 = blockIdx.y * 128;
    const int col0 = blockIdx.x * 128;
    const uint32_t sb = smem_u32(smem);

    auto cp_chunk = [&](int c, uint32_t off) {
#pragma unroll
        for (int j = 0; j < 2; ++j) {
            int idx = t + 256*j;
            int r = idx >> 2, s = idx & 3;
            CP16(sb + off + (uint32_t)(r*80 + s*16),
                 (const char*)(Ah + (size_t)(row0 + r)*DD + c*32) + s*16);
        }
#pragma unroll
        for (int j = 0; j < 2; ++j) {
            CP16(sb + off + GSTG_A + (uint32_t)(j*4096 + t*16),
                 (const char*)(Wfh + ((size_t)(c*2 + j)*128 + (col0 >> 3))*32) + t*16);
        }
    };

    float4 acc[2][8];
#pragma unroll
    for (int i = 0; i < 2; ++i)
#pragma unroll
        for (int j = 0; j < 8; ++j) acc[i][j] = make_float4(0.f, 0.f, 0.f, 0.f);

    cp_chunk(0, 0);     CP_COMMIT();
    cp_chunk(1, GSTG);  CP_COMMIT();
    CP_WAIT1();
    __syncthreads();

    for (int c = 0; c < 32; ++c) {
        const uint32_t off = (uint32_t)(c % 3) * GSTG;
        if (c + 2 < 32) { cp_chunk(c + 2, (uint32_t)((c + 2) % 3) * GSTG); CP_COMMIT(); }
        const char* Asb = smem + off;
        const char* Wsb = smem + off + GSTG_A;
#pragma unroll
        for (int kk = 0; kk < 2; ++kk) {
            uint32_t af[2][4];
#pragma unroll
            for (int mt = 0; mt < 2; ++mt) {
                int r = (wm*2 + mt)*16 + g;
                const char* base = Asb + r*80 + kk*32 + 4*tg;
                af[mt][0] = *(const uint32_t*)(base);
                af[mt][1] = *(const uint32_t*)(base + 8*80);
                af[mt][2] = *(const uint32_t*)(base + 16);
                af[mt][3] = *(const uint32_t*)(base + 8*80 + 16);
            }
#pragma unroll
            for (int nt = 0; nt < 8; ++nt) {
                uint2 b2 = *(const uint2*)(Wsb + ((kk*16 + wn*8 + nt)*32 + lane)*8);
                mma_f16(acc[0][nt], af[0], b2.x, b2.y);
                mma_f16(acc[1][nt], af[1], b2.x, b2.y);
            }
        }
        if (c + 1 < 32) {
            if (c + 2 < 32) CP_WAIT1(); else CP_WAIT0();
            __syncthreads();
        }
    }

    if (emit == 0) {
#pragma unroll
        for (int mt = 0; mt < 2; ++mt) {
            size_t rA = (size_t)(row0 + (wm*2 + mt)*16 + g);
            size_t rB = rA + 8;
#pragma unroll
            for (int nt = 0; nt < 8; ++nt) {
                int col = col0 + (wn*8 + nt)*8 + tg*2;
                float2 b2 = *reinterpret_cast<const float2*>(bias + col);
                float2 o0 = make_float2(acc[mt][nt].x + b2.x, acc[mt][nt].y + b2.y);
                float2 o1 = make_float2(acc[mt][nt].z + b2.x, acc[mt][nt].w + b2.y);
                *reinterpret_cast<float2*>(C + rA*DD + col) = o0;
                *reinterpret_cast<float2*>(C + rB*DD + col) = o1;
            }
        }
        return;
    }

    // ---- fragment-emit epilogue: stage fp32 tile, emit fp16 fragments ----
    const int STR = (emit == 1) ? 132 : 136;
    float* sC = (float*)smem;
    __syncthreads();
#pragma unroll
    for (int mt = 0; mt < 2; ++mt) {
        int rAl = (wm*2 + mt)*16 + g;
        int rBl = rAl + 8;
#pragma unroll
        for (int nt = 0; nt < 8; ++nt) {
            int col = (wn*8 + nt)*8 + tg*2;
            float2 b2 = *reinterpret_cast<const float2*>(bias + col0 + col);
            sC[rAl*STR + col]     = acc[mt][nt].x + b2.x;
            sC[rAl*STR + col + 1] = acc[mt][nt].y + b2.y;
            sC[rBl*STR + col]     = acc[mt][nt].z + b2.x;
            sC[rBl*STR + col + 1] = acc[mt][nt].w + b2.y;
        }
    }
    __syncthreads();

    const int b   = row0 >> 11;
    const int s0l = row0 & 2047;
    const int h0  = col0 >> 6;

    if (emit == 1) {                 // K fragments: {k0,k1} fp16
#pragma unroll
        for (int j = 0; j < 16; ++j) {
            int idx = t + 256*j;
            int ln = idx & 31, dhc = (idx >> 5) & 3, ntgL = (idx >> 7) & 15, hh = (idx >> 11) & 1;
            int gg = ln >> 2, tgg = ln & 3;
            const float* base = sC + (ntgL*8 + gg)*132 + hh*64 + dhc*16 + 2*tgg;
            uint2 o;
            o.x = pack_f16x2(base[0], base[1]);
            o.y = pack_f16x2(base[8], base[9]);
            int bh = b*16 + h0 + hh;
            g_kfh[(((size_t)bh*256 + (s0l >> 3) + ntgL)*4 + dhc)*32 + ln] = o;
        }
    } else {                         // V fragments: {b0,b1}
#pragma unroll
        for (int j = 0; j < 16; ++j) {
            int idx = t + 256*j;
            int ln = idx & 31, nvt = (idx >> 5) & 7, kc = (idx >> 8) & 3;
            int ktL = (idx >> 10) & 1, hh = (idx >> 11) & 1;
            int gg = ln >> 2, tgg = ln & 3;
            int kb = ktL*64 + kc*16 + 2*tgg;
            const float* bcol = sC + hh*64 + nvt*8 + gg;
            float v0 = bcol[(size_t)(kb+0)*136], v1 = bcol[(size_t)(kb+1)*136];
            float v8 = bcol[(size_t)(kb+8)*136], v9 = bcol[(size_t)(kb+9)*136];
            uint2 o;
            o.x = pack_f16x2(v0, v1);
            o.y = pack_f16x2(v8, v9);
            int bh = b*16 + h0 + hh;
            g_vfh[((((size_t)bh*32 + (s0l >> 6) + ktL)*4 + kc)*8 + nvt)*32 + ln] = o;
        }
    }
}

__global__ __launch_bounds__(256, 2) void gemm_qkv_mma(
    const float* __restrict__ bq, const float* __restrict__ bk,
    const float* __restrict__ bv) {
    extern __shared__ char smg[];
    int z = blockIdx.z;
    const uint2* Wf   = g_wfh + (size_t)z*64*128*32;
    const float* bias = (z == 0) ? bq : (z == 1) ? bk : bv;
    float* C          = (z == 0) ? g_q : nullptr;
    gemm_mma_body(g_ah, Wf, bias, C, smg, z);
}

__global__ __launch_bounds__(256, 2) void gemm_o_mma(
    const float* __restrict__ bo, float* __restrict__ out) {
    extern __shared__ char smg[];
    gemm_mma_body(g_ctxh, g_wfh + (size_t)3*64*128*32, bo, out, smg, 0);
}

// ---------------- flash attention fp16: q-tile 128, cp.async double buffer ---
// Per tile: kf 8KB + vf 8KB = 16KB; x2 buffers = 32KB.
#define ATT_STAGE 16384
#define ATT_SMEM (2*16384)

__global__ __launch_bounds__(256, 2) void attn_mma() {
    extern __shared__ char sma[];
    const uint32_t sb = smem_u32(sma);

    const int t = threadIdx.x, lane = t & 31, w = t >> 5;
    const int g = lane >> 2, tg = lane & 3;
    const int q0 = blockIdx.x * 128;
    const int bh = blockIdx.y, b = bh >> 4, h = bh & 15;
    const int rowA = q0 + w*16 + g, rowB = rowA + 8;

    // Q fragments fp16 (resident, pre-scaled by 1/8, single-rounded)
    uint32_t qh[4][4];
    {
        const float* Qb = g_q + (size_t)(b*SS)*DD + h*DHH;
#pragma unroll
        for (int dhc = 0; dhc < 4; ++dhc) {
            float2 a0 = *reinterpret_cast<const float2*>(Qb + (size_t)rowA*DD + dhc*16 + 2*tg);
            float2 a8 = *reinterpret_cast<const float2*>(Qb + (size_t)rowA*DD + dhc*16 + 2*tg + 8);
            float2 b0 = *reinterpret_cast<const float2*>(Qb + (size_t)rowB*DD + dhc*16 + 2*tg);
            float2 b8 = *reinterpret_cast<const float2*>(Qb + (size_t)rowB*DD + dhc*16 + 2*tg + 8);
            qh[dhc][0] = pack_f16x2(0.125f*a0.x, 0.125f*a0.y);
            qh[dhc][1] = pack_f16x2(0.125f*b0.x, 0.125f*b0.y);
            qh[dhc][2] = pack_f16x2(0.125f*a8.x, 0.125f*a8.y);
            qh[dhc][3] = pack_f16x2(0.125f*b8.x, 0.125f*b8.y);
        }
    }

    const uint2* kf_base = g_kfh + (size_t)bh*256*4*32;
    const uint2* vf_base = g_vfh + (size_t)bh*32*4*8*32;

    auto cp_tile = [&](int kt, uint32_t off) {
        const char* srcK = (const char*)(kf_base + (size_t)kt*8*4*32);
        const char* srcV = (const char*)(vf_base + (size_t)kt*4*8*32);
#pragma unroll
        for (int j = 0; j < 2; ++j) {
            int idx = t + 256*j;
            CP16(sb + off + (uint32_t)idx*16, srcK + (size_t)idx*16);
        }
#pragma unroll
        for (int j = 0; j < 2; ++j) {
            int idx = t + 256*j;
            CP16(sb + off + 8192u + (uint32_t)idx*16, srcV + (size_t)idx*16);
        }
    };

    float4 oacc[8];
#pragma unroll
    for (int nt = 0; nt < 8; ++nt) oacc[nt] = make_float4(0.f, 0.f, 0.f, 0.f);
    float mA = MASKVAL, mB = MASKVAL, lA = 0.f, lB = 0.f;

    cp_tile(0, 0);
    CP_COMMIT(); CP_WAIT0();
    __syncthreads();

    for (int kt = 0; kt < 32; ++kt) {
        const uint32_t off = (kt & 1) * (uint32_t)ATT_STAGE;
        if (kt + 1 < 32) { cp_tile(kt + 1, (~kt & 1) * (uint32_t)ATT_STAGE); CP_COMMIT(); }

        const uint32_t mA0 = g_maskb[rowA*64 + kt*2];
        const uint32_t mA1 = g_maskb[rowA*64 + kt*2 + 1];
        const uint32_t mB0 = g_maskb[rowB*64 + kt*2];
        const uint32_t mB1 = g_maskb[rowB*64 + kt*2 + 1];

        const uint2* kf_s = (const uint2*)(sma + off);
        const uint2* vf_s = (const uint2*)(sma + off + 8192);

        // ---- S = Q K^T (single-pass fp16) ----
        float4 sacc[8];
#pragma unroll
        for (int nt = 0; nt < 8; ++nt) sacc[nt] = make_float4(0.f, 0.f, 0.f, 0.f);

#pragma unroll
        for (int nt = 0; nt < 8; ++nt) {
#pragma unroll
            for (int dhc = 0; dhc < 4; ++dhc) {
                uint2 kf = kf_s[(nt*4 + dhc)*32 + lane];
                mma_f16(sacc[nt], qh[dhc], kf.x, kf.y);
            }
        }

        // ---- mask ----
#pragma unroll
        for (int nt = 0; nt < 8; ++nt) {
            int c0 = nt*8 + 2*tg;
            uint32_t wa = (c0 & 32) ? mA1 : mA0;
            uint32_t wb = (c0 & 32) ? mB1 : mB0;
            int sh = c0 & 31;
            float sx = sacc[nt].x, sy = sacc[nt].y;
            float sz = sacc[nt].z, sw = sacc[nt].w;
            if (!((wa >> sh) & 1))       sx = MASKVAL;
            if (!((wa >> (sh + 1)) & 1)) sy = MASKVAL;
            if (!((wb >> sh) & 1))       sz = MASKVAL;
            if (!((wb >> (sh + 1)) & 1)) sw = MASKVAL;
            sacc[nt] = make_float4(sx, sy, sz, sw);
        }

        // ---- online softmax ----
        float tmA = MASKVAL, tmB = MASKVAL;
#pragma unroll
        for (int nt = 0; nt < 8; ++nt) {
            tmA = fmaxf(tmA, fmaxf(sacc[nt].x, sacc[nt].y));
            tmB = fmaxf(tmB, fmaxf(sacc[nt].z, sacc[nt].w));
        }
        tmA = fmaxf(tmA, __shfl_xor_sync(0xffffffffu, tmA, 1));
        tmA = fmaxf(tmA, __shfl_xor_sync(0xffffffffu, tmA, 2));
        tmB = fmaxf(tmB, __shfl_xor_sync(0xffffffffu, tmB, 1));
        tmB = fmaxf(tmB, __shfl_xor_sync(0xffffffffu, tmB, 2));

        float mnA = fmaxf(mA, tmA), mnB = fmaxf(mB, tmB);
        float aA = __expf(mA - mnA), aB = __expf(mB - mnB);
        mA = mnA; mB = mnB;

        float sumA = 0.f, sumB = 0.f;
#pragma unroll
        for (int nt = 0; nt < 8; ++nt) {
            float px = __expf(sacc[nt].x - mnA);
            float py = __expf(sacc[nt].y - mnA);
            float pz = __expf(sacc[nt].z - mnB);
            float pw = __expf(sacc[nt].w - mnB);
            sumA += px + py; sumB += pz + pw;
            sacc[nt] = make_float4(px, py, pz, pw);
        }
        sumA += __shfl_xor_sync(0xffffffffu, sumA, 1);
        sumA += __shfl_xor_sync(0xffffffffu, sumA, 2);
        sumB += __shfl_xor_sync(0xffffffffu, sumB, 1);
        sumB += __shfl_xor_sync(0xffffffffu, sumB, 2);
        lA = lA*aA + sumA;
        lB = lB*aB + sumB;
#pragma unroll
        for (int nt = 0; nt < 8; ++nt) {
            oacc[nt].x *= aA; oacc[nt].y *= aA;
            oacc[nt].z *= aB; oacc[nt].w *= aB;
        }

        // ---- O += P V  (A-frags == C-layout: no shuffles, just f16 packs) ----
#pragma unroll
        for (int kc = 0; kc < 4; ++kc) {
            uint32_t af[4];
            af[0] = pack_f16x2(sacc[2*kc].x,   sacc[2*kc].y);
            af[1] = pack_f16x2(sacc[2*kc].z,   sacc[2*kc].w);
            af[2] = pack_f16x2(sacc[2*kc+1].x, sacc[2*kc+1].y);
            af[3] = pack_f16x2(sacc[2*kc+1].z, sacc[2*kc+1].w);
#pragma unroll
            for (int nvt = 0; nvt < 8; ++nvt) {
                uint2 v2 = vf_s[(kc*8 + nvt)*32 + lane];
                mma_f16(oacc[nvt], af, v2.x, v2.y);
            }
        }
        if (kt + 1 < 32) { CP_WAIT0(); __syncthreads(); }
    }

    // ---- epilogue: normalize + write ctx fp16 (feeds O-GEMM) ----
    const float invA = 1.f / lA, invB = 1.f / lB;
#pragma unroll
    for (int nt = 0; nt < 8; ++nt) {
        int col = h*DHH + nt*8 + 2*tg;
        *reinterpret_cast<uint32_t*>(g_ctxh + (size_t)(b*SS + rowA)*DD + col) =
            pack_f16x2(oacc[nt].x * invA, oacc[nt].y * invA);
        *reinterpret_cast<uint32_t*>(g_ctxh + (size_t)(b*SS + rowB)*DD + col) =
            pack_f16x2(oacc[nt].z * invB, oacc[nt].w * invB);
    }
}

// ---------------- launch -----------------------------------------------------
extern "C" void kernel_launch(void* const* d_in, const int* in_sizes, int n_in,
                              void* d_out, int out_size) {
    const float* hs = (const float*)d_in[0];
    const void*  mk = d_in[1];
    const float* Wq = (const float*)d_in[2]; const float* bq = (const float*)d_in[3];
    const float* Wk = (const float*)d_in[4]; const float* bk = (const float*)d_in[5];
    const float* Wv = (const float*)d_in[6]; const float* bv = (const float*)d_in[7];
    const float* Wo = (const float*)d_in[8]; const float* bo = (const float*)d_in[9];
    float* out = (float*)d_out;

    static bool attr_set = false;
    if (!attr_set) {
        cudaFuncSetAttribute(gemm_qkv_mma,
                             cudaFuncAttributeMaxDynamicSharedMemorySize, GEMM_SMEM);
        cudaFuncSetAttribute(gemm_o_mma,
                             cudaFuncAttributeMaxDynamicSharedMemorySize, GEMM_SMEM);
        cudaFuncSetAttribute(attn_mma,
                             cudaFuncAttributeMaxDynamicSharedMemorySize, ATT_SMEM);
        attr_set = true;
    }

    repack_mask2<<<(SS*(SS/32) + 255)/256, 256>>>(mk);                    // #1
    prep_kernel<<<512 + MTOT*DD/1024, 256>>>(hs, Wq, Wk, Wv, Wo);         // #2
    gemm_qkv_mma<<<dim3(8, 64, 3), 256, GEMM_SMEM>>>(bq, bk, bv);         // #3
    attn_mma<<<dim3(SS/128, BB*HH), 256, ATT_SMEM>>>();                   // #4 (profiled)
    gemm_o_mma<<<dim3(8, 64), 256, GEMM_SMEM>>>(bo, out);                 // #5
}

// round 16
// speedup vs baseline: 6.3245x; 1.0614x over previous
#include <cuda_runtime.h>
#include <cuda_fp16.h>
#include <math.h>
#include <stdint.h>

#define BB   4
#define SS   2048
#define DD   1024
#define HH   16
#define DHH  64
#define MTOT (BB*SS)          // 8192
#define MASKVAL (-1e30f)
#define QSCALE 0.1803368866f  // 0.125 * log2(e)

// ---------------- scratch (static device arrays; no allocation) -------------
__device__ __half g_ah [(size_t)MTOT*DD];        // hs as fp16
__device__ float  g_q  [(size_t)MTOT*DD];        // Q fp32
__device__ __half g_ctxh[(size_t)MTOT*DD];       // attn output fp16 (feeds O-GEMM)
__device__ uint2  g_kfh[(size_t)64*256*4*32];    // [bh][ntg][dhc][lane] {k0,k1} fp16
__device__ uint2  g_vfh[(size_t)64*32*4*8*32];   // [bh][kt][kc][nvt][lane] {b0,b1}
__device__ uint2  g_wfh[(size_t)4*64*128*32];    // [z][kg][ntg][lane] b-frags fp16
__device__ uint32_t g_maskb[(size_t)SS*(SS/32)];

__device__ __forceinline__ uint32_t smem_u32(const void* p) {
    uint32_t a;
    asm("{ .reg .u64 t; cvta.to.shared.u64 t, %1; cvt.u32.u64 %0, t; }"
        : "=r"(a) : "l"(p));
    return a;
}
// pack two fp32 -> fp16x2 {lo, hi}
__device__ __forceinline__ uint32_t pack_f16x2(float lo, float hi) {
    uint32_t r;
    asm("cvt.rn.f16x2.f32 %0, %1, %2;" : "=r"(r) : "f"(hi), "f"(lo));
    return r;
}
#define CP16(dst, src) \
    asm volatile("cp.async.cg.shared.global [%0], [%1], 16;" :: "r"(dst), "l"(src))
#define CP_COMMIT() asm volatile("cp.async.commit_group;" ::: "memory")
#define CP_WAIT0()  asm volatile("cp.async.wait_group 0;" ::: "memory")

// m16n8k16 fp16 warp MMA, fp32 accum
__device__ __forceinline__ void mma_f16(float4& d, const uint32_t a[4],
                                        const uint32_t b0, const uint32_t b1) {
    asm volatile(
        "mma.sync.aligned.m16n8k16.row.col.f32.f16.f16.f32 "
        "{%0,%1,%2,%3}, {%4,%5,%6,%7}, {%8,%9}, {%0,%1,%2,%3};"
        : "+f"(d.x), "+f"(d.y), "+f"(d.z), "+f"(d.w)
        : "r"(a[0]), "r"(a[1]), "r"(a[2]), "r"(a[3]), "r"(b0), "r"(b1));
}

// ---------------- mask repack with per-block dtype self-detect ---------------
__global__ void repack_mask2(const void* __restrict__ mp) {
    const unsigned int* mw = (const unsigned int*)mp;
    unsigned int probe = mw[threadIdx.x];
    int ok = (probe <= 1u) || (probe == 0x3F800000u);
    int wordlike = __syncthreads_and(ok);

    int idx = blockIdx.x * blockDim.x + threadIdx.x;
    if (idx >= SS * (SS/32)) return;
    int row = idx >> 6, w = idx & 63;
    uint32_t bits = 0;
    if (!wordlike) {
        const uchar4* p = (const uchar4*)mp + (size_t)row*(SS/4) + w*8;
#pragma unroll
        for (int j = 0; j < 8; ++j) {
            uchar4 c = p[j];
            bits |= (uint32_t)(c.x != 0) << (4*j + 0);
            bits |= (uint32_t)(c.y != 0) << (4*j + 1);
            bits |= (uint32_t)(c.z != 0) << (4*j + 2);
            bits |= (uint32_t)(c.w != 0) << (4*j + 3);
        }
    } else {
        const unsigned int* p = mw + (size_t)row*SS + w*32;
#pragma unroll
        for (int j = 0; j < 32; ++j)
            bits |= (uint32_t)(p[j] != 0) << j;
    }
    g_maskb[idx] = bits;
}

// ---------------- prep: W b-frags (blocks 0..511) + hs->fp16 (rest) ----------
__global__ void prep_kernel(const float* __restrict__ hs,
                            const float* __restrict__ W0, const float* __restrict__ W1,
                            const float* __restrict__ W2, const float* __restrict__ W3) {
    __shared__ float sW[64*132];
    const int t = threadIdx.x;
    if (blockIdx.x < 512) {
        int i = blockIdx.x;
        int bx = i & 7, by = (i >> 3) & 15, z = i >> 7;
        const float* W = (z == 0) ? W0 : (z == 1) ? W1 : (z == 2) ? W2 : W3;
        const int ntg0 = bx * 16, kg0 = by * 4;
        const int n0 = ntg0 * 8, k0 = by * 64;
#pragma unroll
        for (int j = 0; j < 8; ++j) {
            int idx = t + 256*j;
            int r = idx >> 5, c4 = idx & 31;
            float4 v = *reinterpret_cast<const float4*>(W + (size_t)(k0 + r)*DD + n0 + c4*4);
            *reinterpret_cast<float4*>(&sW[r*132 + c4*4]) = v;
        }
        __syncthreads();
#pragma unroll
        for (int j = 0; j < 8; ++j) {
            int idx = t + 256*j;
            int ln = idx & 31, ntgL = (idx >> 5) & 15, kgL = idx >> 9;
            int gg = ln >> 2, tgg = ln & 3;
            float w00 = sW[(kgL*16 + 2*tgg    )*132 + ntgL*8 + gg];
            float w01 = sW[(kgL*16 + 2*tgg + 1)*132 + ntgL*8 + gg];
            float w08 = sW[(kgL*16 + 2*tgg + 8)*132 + ntgL*8 + gg];
            float w09 = sW[(kgL*16 + 2*tgg + 9)*132 + ntgL*8 + gg];
            uint2 o;
            o.x = pack_f16x2(w00, w01);
            o.y = pack_f16x2(w08, w09);
            g_wfh[(((size_t)z*64 + kg0 + kgL)*128 + ntg0 + ntgL)*32 + ln] = o;
        }
    } else {
        size_t i = ((size_t)(blockIdx.x - 512) * 256 + t) * 4;
        if (i < (size_t)MTOT*DD) {
            float4 v = *reinterpret_cast<const float4*>(hs + i);
            uint2 o;
            o.x = pack_f16x2(v.x, v.y);
            o.y = pack_f16x2(v.z, v.w);
            *reinterpret_cast<uint2*>(g_ah + i) = o;
        }
    }
}

// ---------------- fp16 mma.sync GEMM, chunk-64 double buffer -----------------
// Stage: A 128 rows x 144B (padded, conflict-free) = 18432 B + W 16 KB = 34816 B.
#define GSTG_A 18432u
#define GSTG   34816u
#define GEMM_SMEM 69632      // 2 stages; also covers 128*136*4 emit staging

__device__ __forceinline__ void gemm_mma_body(const __half* __restrict__ Ah,
                                              const uint2* __restrict__ Wfh,
                                              const float* __restrict__ bias,
                                              float* __restrict__ C,
                                              char* smem, int emit) {
    const int t    = threadIdx.x;
    const int lane = t & 31;
    const int wid  = t >> 5;
    const int wm   = wid >> 1;
    const int wn   = wid & 1;
    const int g    = lane >> 2, tg = lane & 3;
    const int row0 = blockIdx.y * 128;
    const int col0 = blockIdx.x * 128;
    const uint32_t sb = smem_u32(smem);

    auto cp_chunk = [&](int c, uint32_t off) {
#pragma unroll
        for (int j = 0; j < 4; ++j) {              // A tile: 1024 x 16B
            int idx = t + 256*j;
            int r = idx >> 3, s = idx & 7;
            CP16(sb + off + (uint32_t)(r*144 + s*16),
                 (const char*)(Ah + (size_t)(row0 + r)*DD + c*64) + s*16);
        }
#pragma unroll
        for (int j = 0; j < 4; ++j) {              // W frags: 4 x 4KB
            CP16(sb + off + GSTG_A + (uint32_t)(j*4096 + t*16),
                 (const char*)(Wfh + ((size_t)(c*4 + j)*128 + (col0 >> 3))*32) + t*16);
        }
    };

    float4 acc[2][8];
#pragma unroll
    for (int i = 0; i < 2; ++i)
#pragma unroll
        for (int j = 0; j < 8; ++j) acc[i][j] = make_float4(0.f, 0.f, 0.f, 0.f);

    cp_chunk(0, 0);
    CP_COMMIT(); CP_WAIT0();
    __syncthreads();

    for (int c = 0; c < 16; ++c) {
        const uint32_t off = (uint32_t)(c & 1) * GSTG;
        if (c + 1 < 16) { cp_chunk(c + 1, (uint32_t)(~c & 1) * GSTG); CP_COMMIT(); }
        const char* Asb = smem + off;
        const char* Wsb = smem + off + GSTG_A;
#pragma unroll
        for (int kk = 0; kk < 4; ++kk) {
            uint32_t af[2][4];
#pragma unroll
            for (int mt = 0; mt < 2; ++mt) {
                int r = (wm*2 + mt)*16 + g;
                const char* base = Asb + r*144 + kk*32 + 4*tg;
                af[mt][0] = *(const uint32_t*)(base);
                af[mt][1] = *(const uint32_t*)(base + 8*144);
                af[mt][2] = *(const uint32_t*)(base + 16);
                af[mt][3] = *(const uint32_t*)(base + 8*144 + 16);
            }
#pragma unroll
            for (int nt = 0; nt < 8; ++nt) {
                uint2 b2 = *(const uint2*)(Wsb + ((kk*16 + wn*8 + nt)*32 + lane)*8);
                mma_f16(acc[0][nt], af[0], b2.x, b2.y);
                mma_f16(acc[1][nt], af[1], b2.x, b2.y);
            }
        }
        if (c + 1 < 16) { CP_WAIT0(); __syncthreads(); }
    }

    if (emit == 0) {
#pragma unroll
        for (int mt = 0; mt < 2; ++mt) {
            size_t rA = (size_t)(row0 + (wm*2 + mt)*16 + g);
            size_t rB = rA + 8;
#pragma unroll
            for (int nt = 0; nt < 8; ++nt) {
                int col = col0 + (wn*8 + nt)*8 + tg*2;
                float2 b2 = *reinterpret_cast<const float2*>(bias + col);
                float2 o0 = make_float2(acc[mt][nt].x + b2.x, acc[mt][nt].y + b2.y);
                float2 o1 = make_float2(acc[mt][nt].z + b2.x, acc[mt][nt].w + b2.y);
                *reinterpret_cast<float2*>(C + rA*DD + col) = o0;
                *reinterpret_cast<float2*>(C + rB*DD + col) = o1;
            }
        }
        return;
    }

    // ---- fragment-emit epilogue: stage fp32 tile, emit fp16 fragments ----
    const int STR = (emit == 1) ? 132 : 136;
    float* sC = (float*)smem;
    __syncthreads();
#pragma unroll
    for (int mt = 0; mt < 2; ++mt) {
        int rAl = (wm*2 + mt)*16 + g;
        int rBl = rAl + 8;
#pragma unroll
        for (int nt = 0; nt < 8; ++nt) {
            int col = (wn*8 + nt)*8 + tg*2;
            float2 b2 = *reinterpret_cast<const float2*>(bias + col0 + col);
            sC[rAl*STR + col]     = acc[mt][nt].x + b2.x;
            sC[rAl*STR + col + 1] = acc[mt][nt].y + b2.y;
            sC[rBl*STR + col]     = acc[mt][nt].z + b2.x;
            sC[rBl*STR + col + 1] = acc[mt][nt].w + b2.y;
        }
    }
    __syncthreads();

    const int b   = row0 >> 11;
    const int s0l = row0 & 2047;
    const int h0  = col0 >> 6;

    if (emit == 1) {                 // K fragments: {k0,k1} fp16
#pragma unroll
        for (int j = 0; j < 16; ++j) {
            int idx = t + 256*j;
            int ln = idx & 31, dhc = (idx >> 5) & 3, ntgL = (idx >> 7) & 15, hh = (idx >> 11) & 1;
            int gg = ln >> 2, tgg = ln & 3;
            const float* base = sC + (ntgL*8 + gg)*132 + hh*64 + dhc*16 + 2*tgg;
            uint2 o;
            o.x = pack_f16x2(base[0], base[1]);
            o.y = pack_f16x2(base[8], base[9]);
            int bh = b*16 + h0 + hh;
            g_kfh[(((size_t)bh*256 + (s0l >> 3) + ntgL)*4 + dhc)*32 + ln] = o;
        }
    } else {                         // V fragments: {b0,b1}
#pragma unroll
        for (int j = 0; j < 16; ++j) {
            int idx = t + 256*j;
            int ln = idx & 31, nvt = (idx >> 5) & 7, kc = (idx >> 8) & 3;
            int ktL = (idx >> 10) & 1, hh = (idx >> 11) & 1;
            int gg = ln >> 2, tgg = ln & 3;
            int kb = ktL*64 + kc*16 + 2*tgg;
            const float* bcol = sC + hh*64 + nvt*8 + gg;
            float v0 = bcol[(size_t)(kb+0)*136], v1 = bcol[(size_t)(kb+1)*136];
            float v8 = bcol[(size_t)(kb+8)*136], v9 = bcol[(size_t)(kb+9)*136];
            uint2 o;
            o.x = pack_f16x2(v0, v1);
            o.y = pack_f16x2(v8, v9);
            int bh = b*16 + h0 + hh;
            g_vfh[((((size_t)bh*32 + (s0l >> 6) + ktL)*4 + kc)*8 + nvt)*32 + ln] = o;
        }
    }
}

__global__ __launch_bounds__(256, 2) void gemm_qkv_mma(
    const float* __restrict__ bq, const float* __restrict__ bk,
    const float* __restrict__ bv) {
    extern __shared__ char smg[];
    int z = blockIdx.z;
    const uint2* Wf   = g_wfh + (size_t)z*64*128*32;
    const float* bias = (z == 0) ? bq : (z == 1) ? bk : bv;
    float* C          = (z == 0) ? g_q : nullptr;
    gemm_mma_body(g_ah, Wf, bias, C, smg, z);
}

__global__ __launch_bounds__(256, 2) void gemm_o_mma(
    const float* __restrict__ bo, float* __restrict__ out) {
    extern __shared__ char smg[];
    gemm_mma_body(g_ctxh, g_wfh + (size_t)3*64*128*32, bo, out, smg, 0);
}

// ---------------- flash attention fp16: exp2 domain, deferred l-reduce -------
#define ATT_STAGE 16384
#define ATT_SMEM (2*16384)

__global__ __launch_bounds__(256, 2) void attn_mma() {
    extern __shared__ char sma[];
    const uint32_t sb = smem_u32(sma);

    const int t = threadIdx.x, lane = t & 31, w = t >> 5;
    const int g = lane >> 2, tg = lane & 3;
    const int q0 = blockIdx.x * 128;
    const int bh = blockIdx.y, b = bh >> 4, h = bh & 15;
    const int rowA = q0 + w*16 + g, rowB = rowA + 8;

    // Q fragments fp16, pre-scaled by 0.125*log2(e)  (scores in log2 domain)
    uint32_t qh[4][4];
    {
        const float* Qb = g_q + (size_t)(b*SS)*DD + h*DHH;
#pragma unroll
        for (int dhc = 0; dhc < 4; ++dhc) {
            float2 a0 = *reinterpret_cast<const float2*>(Qb + (size_t)rowA*DD + dhc*16 + 2*tg);
            float2 a8 = *reinterpret_cast<const float2*>(Qb + (size_t)rowA*DD + dhc*16 + 2*tg + 8);
            float2 b0 = *reinterpret_cast<const float2*>(Qb + (size_t)rowB*DD + dhc*16 + 2*tg);
            float2 b8 = *reinterpret_cast<const float2*>(Qb + (size_t)rowB*DD + dhc*16 + 2*tg + 8);
            qh[dhc][0] = pack_f16x2(QSCALE*a0.x, QSCALE*a0.y);
            qh[dhc][1] = pack_f16x2(QSCALE*b0.x, QSCALE*b0.y);
            qh[dhc][2] = pack_f16x2(QSCALE*a8.x, QSCALE*a8.y);
            qh[dhc][3] = pack_f16x2(QSCALE*b8.x, QSCALE*b8.y);
        }
    }

    const uint2* kf_base = g_kfh + (size_t)bh*256*4*32;
    const uint2* vf_base = g_vfh + (size_t)bh*32*4*8*32;

    auto cp_tile = [&](int kt, uint32_t off) {
        const char* srcK = (const char*)(kf_base + (size_t)kt*8*4*32);
        const char* srcV = (const char*)(vf_base + (size_t)kt*4*8*32);
#pragma unroll
        for (int j = 0; j < 2; ++j) {
            int idx = t + 256*j;
            CP16(sb + off + (uint32_t)idx*16, srcK + (size_t)idx*16);
        }
#pragma unroll
        for (int j = 0; j < 2; ++j) {
            int idx = t + 256*j;
            CP16(sb + off + 8192u + (uint32_t)idx*16, srcV + (size_t)idx*16);
        }
    };

    float4 oacc[8];
#pragma unroll
    for (int nt = 0; nt < 8; ++nt) oacc[nt] = make_float4(0.f, 0.f, 0.f, 0.f);
    float mA = MASKVAL, mB = MASKVAL;
    float lA = 0.f, lB = 0.f;             // lane-partial; reduced in epilogue

    cp_tile(0, 0);
    CP_COMMIT(); CP_WAIT0();
    __syncthreads();

    for (int kt = 0; kt < 32; ++kt) {
        const uint32_t off = (kt & 1) * (uint32_t)ATT_STAGE;
        if (kt + 1 < 32) { cp_tile(kt + 1, (~kt & 1) * (uint32_t)ATT_STAGE); CP_COMMIT(); }

        const uint32_t mA0 = g_maskb[rowA*64 + kt*2];
        const uint32_t mA1 = g_maskb[rowA*64 + kt*2 + 1];
        const uint32_t mB0 = g_maskb[rowB*64 + kt*2];
        const uint32_t mB1 = g_maskb[rowB*64 + kt*2 + 1];

        const uint2* kf_s = (const uint2*)(sma + off);
        const uint2* vf_s = (const uint2*)(sma + off + 8192);

        // ---- S = Q K^T (single-pass fp16, log2 domain) ----
        float4 sacc[8];
#pragma unroll
        for (int nt = 0; nt < 8; ++nt) sacc[nt] = make_float4(0.f, 0.f, 0.f, 0.f);

#pragma unroll
        for (int nt = 0; nt < 8; ++nt) {
#pragma unroll
            for (int dhc = 0; dhc < 4; ++dhc) {
                uint2 kf = kf_s[(nt*4 + dhc)*32 + lane];
                mma_f16(sacc[nt], qh[dhc], kf.x, kf.y);
            }
        }

        // ---- mask ----
#pragma unroll
        for (int nt = 0; nt < 8; ++nt) {
            int c0 = nt*8 + 2*tg;
            uint32_t wa = (c0 & 32) ? mA1 : mA0;
            uint32_t wb = (c0 & 32) ? mB1 : mB0;
            int sh = c0 & 31;
            float sx = sacc[nt].x, sy = sacc[nt].y;
            float sz = sacc[nt].z, sw = sacc[nt].w;
            if (!((wa >> sh) & 1))       sx = MASKVAL;
            if (!((wa >> (sh + 1)) & 1)) sy = MASKVAL;
            if (!((wb >> sh) & 1))       sz = MASKVAL;
            if (!((wb >> (sh + 1)) & 1)) sw = MASKVAL;
            sacc[nt] = make_float4(sx, sy, sz, sw);
        }

        // ---- online softmax (base-2) ----
        float tmA = MASKVAL, tmB = MASKVAL;
#pragma unroll
        for (int nt = 0; nt < 8; ++nt) {
            tmA = fmaxf(tmA, fmaxf(sacc[nt].x, sacc[nt].y));
            tmB = fmaxf(tmB, fmaxf(sacc[nt].z, sacc[nt].w));
        }
        tmA = fmaxf(tmA, __shfl_xor_sync(0xffffffffu, tmA, 1));
        tmA = fmaxf(tmA, __shfl_xor_sync(0xffffffffu, tmA, 2));
        tmB = fmaxf(tmB, __shfl_xor_sync(0xffffffffu, tmB, 1));
        tmB = fmaxf(tmB, __shfl_xor_sync(0xffffffffu, tmB, 2));

        float mnA = fmaxf(mA, tmA), mnB = fmaxf(mB, tmB);
        float aA = exp2f(mA - mnA), aB = exp2f(mB - mnB);
        mA = mnA; mB = mnB;

        float sumA = 0.f, sumB = 0.f;
#pragma unroll
        for (int nt = 0; nt < 8; ++nt) {
            float px = exp2f(sacc[nt].x - mnA);
            float py = exp2f(sacc[nt].y - mnA);
            float pz = exp2f(sacc[nt].z - mnB);
            float pw = exp2f(sacc[nt].w - mnB);
            sumA += px + py; sumB += pz + pw;
            sacc[nt] = make_float4(px, py, pz, pw);
        }
        lA = lA*aA + sumA;               // lane-partial
        lB = lB*aB + sumB;
#pragma unroll
        for (int nt = 0; nt < 8; ++nt) {
            oacc[nt].x *= aA; oacc[nt].y *= aA;
            oacc[nt].z *= aB; oacc[nt].w *= aB;
        }

        // ---- O += P V  (A-frags == C-layout: no shuffles, just f16 packs) ----
#pragma unroll
        for (int kc = 0; kc < 4; ++kc) {
            uint32_t af[4];
            af[0] = pack_f16x2(sacc[2*kc].x,   sacc[2*kc].y);
            af[1] = pack_f16x2(sacc[2*kc].z,   sacc[2*kc].w);
            af[2] = pack_f16x2(sacc[2*kc+1].x, sacc[2*kc+1].y);
            af[3] = pack_f16x2(sacc[2*kc+1].z, sacc[2*kc+1].w);
#pragma unroll
            for (int nvt = 0; nvt < 8; ++nvt) {
                uint2 v2 = vf_s[(kc*8 + nvt)*32 + lane];
                mma_f16(oacc[nvt], af, v2.x, v2.y);
            }
        }
        if (kt + 1 < 32) { CP_WAIT0(); __syncthreads(); }
    }

    // ---- epilogue: reduce l across the 4 lanes of each row, normalize ----
    lA += __shfl_xor_sync(0xffffffffu, lA, 1);
    lA += __shfl_xor_sync(0xffffffffu, lA, 2);
    lB += __shfl_xor_sync(0xffffffffu, lB, 1);
    lB += __shfl_xor_sync(0xffffffffu, lB, 2);
    const float invA = 1.f / lA, invB = 1.f / lB;
#pragma unroll
    for (int nt = 0; nt < 8; ++nt) {
        int col = h*DHH + nt*8 + 2*tg;
        *reinterpret_cast<uint32_t*>(g_ctxh + (size_t)(b*SS + rowA)*DD + col) =
            pack_f16x2(oacc[nt].x * invA, oacc[nt].y * invA);
        *reinterpret_cast<uint32_t*>(g_ctxh + (size_t)(b*SS + rowB)*DD + col) =
            pack_f16x2(oacc[nt].z * invB, oacc[nt].w * invB);
    }
}

// ---------------- launch -----------------------------------------------------
extern "C" void kernel_launch(void* const* d_in, const int* in_sizes, int n_in,
                              void* d_out, int out_size) {
    const float* hs = (const float*)d_in[0];
    const void*  mk = d_in[1];
    const float* Wq = (const float*)d_in[2]; const float* bq = (const float*)d_in[3];
    const float* Wk = (const float*)d_in[4]; const float* bk = (const float*)d_in[5];
    const float* Wv = (const float*)d_in[6]; const float* bv = (const float*)d_in[7];
    const float* Wo = (const float*)d_in[8]; const float* bo = (const float*)d_in[9];
    float* out = (float*)d_out;

    static bool attr_set = false;
    if (!attr_set) {
        cudaFuncSetAttribute(gemm_qkv_mma,
                             cudaFuncAttributeMaxDynamicSharedMemorySize, GEMM_SMEM);
        cudaFuncSetAttribute(gemm_o_mma,
                             cudaFuncAttributeMaxDynamicSharedMemorySize, GEMM_SMEM);
        cudaFuncSetAttribute(attn_mma,
                             cudaFuncAttributeMaxDynamicSharedMemorySize, ATT_SMEM);
        attr_set = true;
    }

    repack_mask2<<<(SS*(SS/32) + 255)/256, 256>>>(mk);                    // #1
    prep_kernel<<<512 + MTOT*DD/1024, 256>>>(hs, Wq, Wk, Wv, Wo);         // #2
    gemm_qkv_mma<<<dim3(8, 64, 3), 256, GEMM_SMEM>>>(bq, bk, bv);         // #3
    attn_mma<<<dim3(SS/128, BB*HH), 256, ATT_SMEM>>>();                   // #4 (profiled)
    gemm_o_mma<<<dim3(8, 64), 256, GEMM_SMEM>>>(bo, out);                 // #5
}

// round 17
// speedup vs baseline: 6.7246x; 1.0633x over previous
#include <cuda_runtime.h>
#include <cuda_fp16.h>
#include <math.h>
#include <stdint.h>

#define BB   4
#define SS   2048
#define DD   1024
#define HH   16
#define DHH  64
#define MTOT (BB*SS)          // 8192
#define MASKVAL (-1e30f)
#define QSCALE 0.1803368866f  // 0.125 * log2(e)

// ---------------- scratch (static device arrays; no allocation) -------------
__device__ __half g_ah [(size_t)MTOT*DD];        // hs as fp16
__device__ float  g_q  [(size_t)MTOT*DD];        // Q fp32
__device__ __half g_ctxh[(size_t)MTOT*DD];       // attn output fp16 (feeds O-GEMM)
__device__ uint4  g_kfh4[(size_t)64*256*2*32];   // [bh][ntg][dhc2][lane] {k(d),k(d+1)} fp16 pairs
__device__ uint4  g_vfh4[(size_t)64*32*2*8*32];  // [bh][kt][kc2][nvt][lane]
__device__ uint2  g_wfh[(size_t)4*64*128*32];    // [z][kg][ntg][lane] b-frags fp16
__device__ float4 g_bias[(size_t)16*32*8*8*32];  // [qi][kt][w][nt][lane] {0 | -1e30}

__device__ __forceinline__ uint32_t smem_u32(const void* p) {
    uint32_t a;
    asm("{ .reg .u64 t; cvta.to.shared.u64 t, %1; cvt.u32.u64 %0, t; }"
        : "=r"(a) : "l"(p));
    return a;
}
__device__ __forceinline__ uint32_t pack_f16x2(float lo, float hi) {
    uint32_t r;
    asm("cvt.rn.f16x2.f32 %0, %1, %2;" : "=r"(r) : "f"(hi), "f"(lo));
    return r;
}
#define CP16(dst, src) \
    asm volatile("cp.async.cg.shared.global [%0], [%1], 16;" :: "r"(dst), "l"(src))
#define CP_COMMIT() asm volatile("cp.async.commit_group;" ::: "memory")
#define CP_WAIT0()  asm volatile("cp.async.wait_group 0;" ::: "memory")

// m16n8k16 fp16 warp MMA, fp32 accum
__device__ __forceinline__ void mma_f16(float4& d, const uint32_t a[4],
                                        const uint32_t b0, const uint32_t b1) {
    asm volatile(
        "mma.sync.aligned.m16n8k16.row.col.f32.f16.f16.f32 "
        "{%0,%1,%2,%3}, {%4,%5,%6,%7}, {%8,%9}, {%0,%1,%2,%3};"
        : "+f"(d.x), "+f"(d.y), "+f"(d.z), "+f"(d.w)
        : "r"(a[0]), "r"(a[1]), "r"(a[2]), "r"(a[3]), "r"(b0), "r"(b1));
}

// ---------------- mask -> additive fp32 bias in sacc fragment layout ---------
__global__ void build_bias(const void* __restrict__ mp) {
    const unsigned int* mw = (const unsigned int*)mp;
    unsigned int probe = mw[threadIdx.x];
    int ok = (probe <= 1u) || (probe == 0x3F800000u);
    int wordlike = __syncthreads_and(ok);

    int idx = blockIdx.x * blockDim.x + threadIdx.x;    // 0 .. 1M-1
    int lane = idx & 31, nt = (idx >> 5) & 7, w = (idx >> 8) & 7;
    int kt = (idx >> 11) & 31, qi = idx >> 16;
    int g = lane >> 2, tg = lane & 3;
    int rowA = qi*128 + w*16 + g, rowB = rowA + 8;
    int k0 = kt*64 + nt*8 + 2*tg;

    bool a0, a1, b0, b1;
    if (!wordlike) {
        const unsigned char* p = (const unsigned char*)mp;
        a0 = p[(size_t)rowA*SS + k0]     != 0;
        a1 = p[(size_t)rowA*SS + k0 + 1] != 0;
        b0 = p[(size_t)rowB*SS + k0]     != 0;
        b1 = p[(size_t)rowB*SS + k0 + 1] != 0;
    } else {
        a0 = mw[(size_t)rowA*SS + k0]     != 0u;
        a1 = mw[(size_t)rowA*SS + k0 + 1] != 0u;
        b0 = mw[(size_t)rowB*SS + k0]     != 0u;
        b1 = mw[(size_t)rowB*SS + k0 + 1] != 0u;
    }
    g_bias[idx] = make_float4(a0 ? 0.f : MASKVAL, a1 ? 0.f : MASKVAL,
                              b0 ? 0.f : MASKVAL, b1 ? 0.f : MASKVAL);
}

// ---------------- prep: W b-frags (blocks 0..511) + hs->fp16 (rest) ----------
__global__ void prep_kernel(const float* __restrict__ hs,
                            const float* __restrict__ W0, const float* __restrict__ W1,
                            const float* __restrict__ W2, const float* __restrict__ W3) {
    __shared__ float sW[64*132];
    const int t = threadIdx.x;
    if (blockIdx.x < 512) {
        int i = blockIdx.x;
        int bx = i & 7, by = (i >> 3) & 15, z = i >> 7;
        const float* W = (z == 0) ? W0 : (z == 1) ? W1 : (z == 2) ? W2 : W3;
        const int ntg0 = bx * 16, kg0 = by * 4;
        const int n0 = ntg0 * 8, k0 = by * 64;
#pragma unroll
        for (int j = 0; j < 8; ++j) {
            int idx = t + 256*j;
            int r = idx >> 5, c4 = idx & 31;
            float4 v = *reinterpret_cast<const float4*>(W + (size_t)(k0 + r)*DD + n0 + c4*4);
            *reinterpret_cast<float4*>(&sW[r*132 + c4*4]) = v;
        }
        __syncthreads();
#pragma unroll
        for (int j = 0; j < 8; ++j) {
            int idx = t + 256*j;
            int ln = idx & 31, ntgL = (idx >> 5) & 15, kgL = idx >> 9;
            int gg = ln >> 2, tgg = ln & 3;
            float w00 = sW[(kgL*16 + 2*tgg    )*132 + ntgL*8 + gg];
            float w01 = sW[(kgL*16 + 2*tgg + 1)*132 + ntgL*8 + gg];
            float w08 = sW[(kgL*16 + 2*tgg + 8)*132 + ntgL*8 + gg];
            float w09 = sW[(kgL*16 + 2*tgg + 9)*132 + ntgL*8 + gg];
            uint2 o;
            o.x = pack_f16x2(w00, w01);
            o.y = pack_f16x2(w08, w09);
            g_wfh[(((size_t)z*64 + kg0 + kgL)*128 + ntg0 + ntgL)*32 + ln] = o;
        }
    } else {
        size_t i = ((size_t)(blockIdx.x - 512) * 256 + t) * 4;
        if (i < (size_t)MTOT*DD) {
            float4 v = *reinterpret_cast<const float4*>(hs + i);
            uint2 o;
            o.x = pack_f16x2(v.x, v.y);
            o.y = pack_f16x2(v.z, v.w);
            *reinterpret_cast<uint2*>(g_ah + i) = o;
        }
    }
}

// ---------------- fp16 mma.sync GEMM, chunk-64 double buffer -----------------
#define GSTG_A 18432u
#define GSTG   34816u
#define GEMM_SMEM 69632

__device__ __forceinline__ void gemm_mma_body(const __half* __restrict__ Ah,
                                              const uint2* __restrict__ Wfh,
                                              const float* __restrict__ bias,
                                              float* __restrict__ C,
                                              char* smem, int emit) {
    const int t    = threadIdx.x;
    const int lane = t & 31;
    const int wid  = t >> 5;
    const int wm   = wid >> 1;
    const int wn   = wid & 1;
    const int g    = lane >> 2, tg = lane & 3;
    const int row0 = blockIdx.y * 128;
    const int col0 = blockIdx.x * 128;
    const uint32_t sb = smem_u32(smem);

    auto cp_chunk = [&](int c, uint32_t off) {
#pragma unroll
        for (int j = 0; j < 4; ++j) {
            int idx = t + 256*j;
            int r = idx >> 3, s = idx & 7;
            CP16(sb + off + (uint32_t)(r*144 + s*16),
                 (const char*)(Ah + (size_t)(row0 + r)*DD + c*64) + s*16);
        }
#pragma unroll
        for (int j = 0; j < 4; ++j) {
            CP16(sb + off + GSTG_A + (uint32_t)(j*4096 + t*16),
                 (const char*)(Wfh + ((size_t)(c*4 + j)*128 + (col0 >> 3))*32) + t*16);
        }
    };

    float4 acc[2][8];
#pragma unroll
    for (int i = 0; i < 2; ++i)
#pragma unroll
        for (int j = 0; j < 8; ++j) acc[i][j] = make_float4(0.f, 0.f, 0.f, 0.f);

    cp_chunk(0, 0);
    CP_COMMIT(); CP_WAIT0();
    __syncthreads();

    for (int c = 0; c < 16; ++c) {
        const uint32_t off = (uint32_t)(c & 1) * GSTG;
        if (c + 1 < 16) { cp_chunk(c + 1, (uint32_t)(~c & 1) * GSTG); CP_COMMIT(); }
        const char* Asb = smem + off;
        const char* Wsb = smem + off + GSTG_A;
#pragma unroll
        for (int kk = 0; kk < 4; ++kk) {
            uint32_t af[2][4];
#pragma unroll
            for (int mt = 0; mt < 2; ++mt) {
                int r = (wm*2 + mt)*16 + g;
                const char* base = Asb + r*144 + kk*32 + 4*tg;
                af[mt][0] = *(const uint32_t*)(base);
                af[mt][1] = *(const uint32_t*)(base + 8*144);
                af[mt][2] = *(const uint32_t*)(base + 16);
                af[mt][3] = *(const uint32_t*)(base + 8*144 + 16);
            }
#pragma unroll
            for (int nt = 0; nt < 8; ++nt) {
                uint2 b2 = *(const uint2*)(Wsb + ((kk*16 + wn*8 + nt)*32 + lane)*8);
                mma_f16(acc[0][nt], af[0], b2.x, b2.y);
                mma_f16(acc[1][nt], af[1], b2.x, b2.y);
            }
        }
        if (c + 1 < 16) { CP_WAIT0(); __syncthreads(); }
    }

    if (emit == 0) {
#pragma unroll
        for (int mt = 0; mt < 2; ++mt) {
            size_t rA = (size_t)(row0 + (wm*2 + mt)*16 + g);
            size_t rB = rA + 8;
#pragma unroll
            for (int nt = 0; nt < 8; ++nt) {
                int col = col0 + (wn*8 + nt)*8 + tg*2;
                float2 b2 = *reinterpret_cast<const float2*>(bias + col);
                float2 o0 = make_float2(acc[mt][nt].x + b2.x, acc[mt][nt].y + b2.y);
                float2 o1 = make_float2(acc[mt][nt].z + b2.x, acc[mt][nt].w + b2.y);
                *reinterpret_cast<float2*>(C + rA*DD + col) = o0;
                *reinterpret_cast<float2*>(C + rB*DD + col) = o1;
            }
        }
        return;
    }

    // ---- fragment-emit epilogue: stage fp32 tile, emit fp16 uint4 frags ----
    const int STR = (emit == 1) ? 132 : 136;
    float* sC = (float*)smem;
    __syncthreads();
#pragma unroll
    for (int mt = 0; mt < 2; ++mt) {
        int rAl = (wm*2 + mt)*16 + g;
        int rBl = rAl + 8;
#pragma unroll
        for (int nt = 0; nt < 8; ++nt) {
            int col = (wn*8 + nt)*8 + tg*2;
            float2 b2 = *reinterpret_cast<const float2*>(bias + col0 + col);
            sC[rAl*STR + col]     = acc[mt][nt].x + b2.x;
            sC[rAl*STR + col + 1] = acc[mt][nt].y + b2.y;
            sC[rBl*STR + col]     = acc[mt][nt].z + b2.x;
            sC[rBl*STR + col + 1] = acc[mt][nt].w + b2.y;
        }
    }
    __syncthreads();

    const int b   = row0 >> 11;
    const int s0l = row0 & 2047;
    const int h0  = col0 >> 6;

    if (emit == 1) {                 // K fragments: uint4 {k(d),k(d+1)} pairs
#pragma unroll
        for (int j = 0; j < 8; ++j) {
            int idx = t + 256*j;     // 0..2047
            int ln = idx & 31, dhc2 = (idx >> 5) & 1, ntgL = (idx >> 6) & 15, hh = (idx >> 10) & 1;
            int gg = ln >> 2, tgg = ln & 3;
            const float* base0 = sC + (ntgL*8 + gg)*132 + hh*64 + dhc2*32 + 2*tgg;
            const float* base1 = base0 + 16;
            uint4 o;
            o.x = pack_f16x2(base0[0], base0[1]);
            o.y = pack_f16x2(base0[8], base0[9]);
            o.z = pack_f16x2(base1[0], base1[1]);
            o.w = pack_f16x2(base1[8], base1[9]);
            int bh = b*16 + h0 + hh;
            g_kfh4[(((size_t)bh*256 + (s0l >> 3) + ntgL)*2 + dhc2)*32 + ln] = o;
        }
    } else {                         // V fragments: uint4 {kc, kc+1} pairs
#pragma unroll
        for (int j = 0; j < 8; ++j) {
            int idx = t + 256*j;
            int ln = idx & 31, nvt = (idx >> 5) & 7, kc2 = (idx >> 8) & 1;
            int ktL = (idx >> 9) & 1, hh = (idx >> 10) & 1;
            int gg = ln >> 2, tgg = ln & 3;
            int kb0 = ktL*64 + kc2*32 + 2*tgg;
            int kb1 = kb0 + 16;
            const float* bcol = sC + hh*64 + nvt*8 + gg;
            uint4 o;
            o.x = pack_f16x2(bcol[(size_t)(kb0+0)*136], bcol[(size_t)(kb0+1)*136]);
            o.y = pack_f16x2(bcol[(size_t)(kb0+8)*136], bcol[(size_t)(kb0+9)*136]);
            o.z = pack_f16x2(bcol[(size_t)(kb1+0)*136], bcol[(size_t)(kb1+1)*136]);
            o.w = pack_f16x2(bcol[(size_t)(kb1+8)*136], bcol[(size_t)(kb1+9)*136]);
            int bh = b*16 + h0 + hh;
            g_vfh4[((((size_t)bh*32 + (s0l >> 6) + ktL)*2 + kc2)*8 + nvt)*32 + ln] = o;
        }
    }
}

__global__ __launch_bounds__(256, 2) void gemm_qkv_mma(
    const float* __restrict__ bq, const float* __restrict__ bk,
    const float* __restrict__ bv) {
    extern __shared__ char smg[];
    int z = blockIdx.z;
    const uint2* Wf   = g_wfh + (size_t)z*64*128*32;
    const float* bias = (z == 0) ? bq : (z == 1) ? bk : bv;
    float* C          = (z == 0) ? g_q : nullptr;
    gemm_mma_body(g_ah, Wf, bias, C, smg, z);
}

__global__ __launch_bounds__(256, 2) void gemm_o_mma(
    const float* __restrict__ bo, float* __restrict__ out) {
    extern __shared__ char smg[];
    gemm_mma_body(g_ctxh, g_wfh + (size_t)3*64*128*32, bo, out, smg, 0);
}

// ---------------- flash attention fp16: bias-add mask, uint4 frags -----------
// Stage: K 8KB + V 8KB + bias 32KB = 48KB; x2 = 96KB.
#define ATT_STAGE 49152
#define ATT_SMEM (2*49152)

__global__ __launch_bounds__(256, 2) void attn_mma() {
    extern __shared__ char sma[];
    const uint32_t sb = smem_u32(sma);

    const int t = threadIdx.x, lane = t & 31, w = t >> 5;
    const int g = lane >> 2, tg = lane & 3;
    const int qi = blockIdx.x;
    const int q0 = qi * 128;
    const int bh = blockIdx.y, b = bh >> 4, h = bh & 15;
    const int rowA = q0 + w*16 + g, rowB = rowA + 8;

    // Q fragments fp16, pre-scaled by 0.125*log2(e)
    uint32_t qh[4][4];
    {
        const float* Qb = g_q + (size_t)(b*SS)*DD + h*DHH;
#pragma unroll
        for (int dhc = 0; dhc < 4; ++dhc) {
            float2 a0 = *reinterpret_cast<const float2*>(Qb + (size_t)rowA*DD + dhc*16 + 2*tg);
            float2 a8 = *reinterpret_cast<const float2*>(Qb + (size_t)rowA*DD + dhc*16 + 2*tg + 8);
            float2 b0 = *reinterpret_cast<const float2*>(Qb + (size_t)rowB*DD + dhc*16 + 2*tg);
            float2 b8 = *reinterpret_cast<const float2*>(Qb + (size_t)rowB*DD + dhc*16 + 2*tg + 8);
            qh[dhc][0] = pack_f16x2(QSCALE*a0.x, QSCALE*a0.y);
            qh[dhc][1] = pack_f16x2(QSCALE*b0.x, QSCALE*b0.y);
            qh[dhc][2] = pack_f16x2(QSCALE*a8.x, QSCALE*a8.y);
            qh[dhc][3] = pack_f16x2(QSCALE*b8.x, QSCALE*b8.y);
        }
    }

    const uint4*  kf_base = g_kfh4 + (size_t)bh*256*2*32;
    const uint4*  vf_base = g_vfh4 + (size_t)bh*32*2*8*32;
    const float4* bb_base = g_bias + (size_t)qi*32*8*8*32;

    auto cp_tile = [&](int kt, uint32_t off) {
        const char* srcK = (const char*)(kf_base + (size_t)kt*512);
        const char* srcV = (const char*)(vf_base + (size_t)kt*512);
        const char* srcB = (const char*)(bb_base + (size_t)kt*2048);
#pragma unroll
        for (int j = 0; j < 2; ++j) {
            int idx = t + 256*j;
            CP16(sb + off + (uint32_t)idx*16, srcK + (size_t)idx*16);
        }
#pragma unroll
        for (int j = 0; j < 2; ++j) {
            int idx = t + 256*j;
            CP16(sb + off + 8192u + (uint32_t)idx*16, srcV + (size_t)idx*16);
        }
#pragma unroll
        for (int j = 0; j < 8; ++j) {
            int idx = t + 256*j;
            CP16(sb + off + 16384u + (uint32_t)idx*16, srcB + (size_t)idx*16);
        }
    };

    float4 oacc[8];
#pragma unroll
    for (int nt = 0; nt < 8; ++nt) oacc[nt] = make_float4(0.f, 0.f, 0.f, 0.f);
    float mA = MASKVAL, mB = MASKVAL;
    float lA = 0.f, lB = 0.f;

    cp_tile(0, 0);
    CP_COMMIT(); CP_WAIT0();
    __syncthreads();

    for (int kt = 0; kt < 32; ++kt) {
        const uint32_t off = (kt & 1) * (uint32_t)ATT_STAGE;
        if (kt + 1 < 32) { cp_tile(kt + 1, (~kt & 1) * (uint32_t)ATT_STAGE); CP_COMMIT(); }

        const uint4*  kf_s = (const uint4*)(sma + off);
        const uint4*  vf_s = (const uint4*)(sma + off + 8192);
        const float4* bb_s = (const float4*)(sma + off + 16384);

        // ---- S = Q K^T (single-pass fp16, log2 domain) ----
        float4 sacc[8];
#pragma unroll
        for (int nt = 0; nt < 8; ++nt) sacc[nt] = make_float4(0.f, 0.f, 0.f, 0.f);

#pragma unroll
        for (int nt = 0; nt < 8; ++nt) {
#pragma unroll
            for (int dhc2 = 0; dhc2 < 2; ++dhc2) {
                uint4 kf = kf_s[(nt*2 + dhc2)*32 + lane];
                mma_f16(sacc[nt], qh[2*dhc2],     kf.x, kf.y);
                mma_f16(sacc[nt], qh[2*dhc2 + 1], kf.z, kf.w);
            }
        }

        // ---- mask via additive bias ----
#pragma unroll
        for (int nt = 0; nt < 8; ++nt) {
            float4 bi = bb_s[(w*8 + nt)*32 + lane];
            sacc[nt].x += bi.x; sacc[nt].y += bi.y;
            sacc[nt].z += bi.z; sacc[nt].w += bi.w;
        }

        // ---- online softmax (base-2) ----
        float tmA = MASKVAL, tmB = MASKVAL;
#pragma unroll
        for (int nt = 0; nt < 8; ++nt) {
            tmA = fmaxf(tmA, fmaxf(sacc[nt].x, sacc[nt].y));
            tmB = fmaxf(tmB, fmaxf(sacc[nt].z, sacc[nt].w));
        }
        tmA = fmaxf(tmA, __shfl_xor_sync(0xffffffffu, tmA, 1));
        tmA = fmaxf(tmA, __shfl_xor_sync(0xffffffffu, tmA, 2));
        tmB = fmaxf(tmB, __shfl_xor_sync(0xffffffffu, tmB, 1));
        tmB = fmaxf(tmB, __shfl_xor_sync(0xffffffffu, tmB, 2));

        float mnA = fmaxf(mA, tmA), mnB = fmaxf(mB, tmB);
        float aA = exp2f(mA - mnA), aB = exp2f(mB - mnB);
        mA = mnA; mB = mnB;

        float sumA = 0.f, sumB = 0.f;
#pragma unroll
        for (int nt = 0; nt < 8; ++nt) {
            float px = exp2f(sacc[nt].x - mnA);
            float py = exp2f(sacc[nt].y - mnA);
            float pz = exp2f(sacc[nt].z - mnB);
            float pw = exp2f(sacc[nt].w - mnB);
            sumA += px + py; sumB += pz + pw;
            sacc[nt] = make_float4(px, py, pz, pw);
        }
        lA = lA*aA + sumA;
        lB = lB*aB + sumB;
#pragma unroll
        for (int nt = 0; nt < 8; ++nt) {
            oacc[nt].x *= aA; oacc[nt].y *= aA;
            oacc[nt].z *= aB; oacc[nt].w *= aB;
        }

        // ---- O += P V  (uint4 frags feed two MMAs each) ----
        uint32_t af[4][4];
#pragma unroll
        for (int kc = 0; kc < 4; ++kc) {
            af[kc][0] = pack_f16x2(sacc[2*kc].x,   sacc[2*kc].y);
            af[kc][1] = pack_f16x2(sacc[2*kc].z,   sacc[2*kc].w);
            af[kc][2] = pack_f16x2(sacc[2*kc+1].x, sacc[2*kc+1].y);
            af[kc][3] = pack_f16x2(sacc[2*kc+1].z, sacc[2*kc+1].w);
        }
#pragma unroll
        for (int kc2 = 0; kc2 < 2; ++kc2) {
#pragma unroll
            for (int nvt = 0; nvt < 8; ++nvt) {
                uint4 v4 = vf_s[(kc2*8 + nvt)*32 + lane];
                mma_f16(oacc[nvt], af[2*kc2],     v4.x, v4.y);
                mma_f16(oacc[nvt], af[2*kc2 + 1], v4.z, v4.w);
            }
        }
        if (kt + 1 < 32) { CP_WAIT0(); __syncthreads(); }
    }

    // ---- epilogue: reduce l across 4 lanes, normalize, write fp16 ctx ----
    lA += __shfl_xor_sync(0xffffffffu, lA, 1);
    lA += __shfl_xor_sync(0xffffffffu, lA, 2);
    lB += __shfl_xor_sync(0xffffffffu, lB, 1);
    lB += __shfl_xor_sync(0xffffffffu, lB, 2);
    const float invA = 1.f / lA, invB = 1.f / lB;
#pragma unroll
    for (int nt = 0; nt < 8; ++nt) {
        int col = h*DHH + nt*8 + 2*tg;
        *reinterpret_cast<uint32_t*>(g_ctxh + (size_t)(b*SS + rowA)*DD + col) =
            pack_f16x2(oacc[nt].x * invA, oacc[nt].y * invA);
        *reinterpret_cast<uint32_t*>(g_ctxh + (size_t)(b*SS + rowB)*DD + col) =
            pack_f16x2(oacc[nt].z * invB, oacc[nt].w * invB);
    }
}

// ---------------- launch -----------------------------------------------------
extern "C" void kernel_launch(void* const* d_in, const int* in_sizes, int n_in,
                              void* d_out, int out_size) {
    const float* hs = (const float*)d_in[0];
    const void*  mk = d_in[1];
    const float* Wq = (const float*)d_in[2]; const float* bq = (const float*)d_in[3];
    const float* Wk = (const float*)d_in[4]; const float* bk = (const float*)d_in[5];
    const float* Wv = (const float*)d_in[6]; const float* bv = (const float*)d_in[7];
    const float* Wo = (const float*)d_in[8]; const float* bo = (const float*)d_in[9];
    float* out = (float*)d_out;

    static bool attr_set = false;
    if (!attr_set) {
        cudaFuncSetAttribute(gemm_qkv_mma,
                             cudaFuncAttributeMaxDynamicSharedMemorySize, GEMM_SMEM);
        cudaFuncSetAttribute(gemm_o_mma,
                             cudaFuncAttributeMaxDynamicSharedMemorySize, GEMM_SMEM);
        cudaFuncSetAttribute(attn_mma,
                             cudaFuncAttributeMaxDynamicSharedMemorySize, ATT_SMEM);
        attr_set = true;
    }

    build_bias<<<4096, 256>>>(mk);                                        // #1
    prep_kernel<<<512 + MTOT*DD/1024, 256>>>(hs, Wq, Wk, Wv, Wo);         // #2
    gemm_qkv_mma<<<dim3(8, 64, 3), 256, GEMM_SMEM>>>(bq, bk, bv);         // #3
    attn_mma<<<dim3(SS/128, BB*HH), 256, ATT_SMEM>>>();                   // #4 (profiled)
    gemm_o_mma<<<dim3(8, 64), 256, GEMM_SMEM>>>(bo, out);                 // #5
}